// round 2
// baseline (speedup 1.0000x reference)
#include <cuda_runtime.h>
#include <cstdint>

// Problem dimensions (fixed by the dataset)
#define NN   16000          // nodes
#define F1   256            // layer-1 input features
#define HID  512            // HEADS*OUT
#define NH   8              // heads
#define OC   64             // per-head out channels
#define RR   8              // relations

// ---------------- scratch (device globals; no allocation allowed) ----------
__device__ float    g_t[(size_t)RR * NN * HID];   // relation-transformed nodes [R,N,512]
__device__ float    g_h[(size_t)NN * HID];        // layer-1 output
__device__ float    g_agg[(size_t)NN * HID];      // aggregation buffer
__device__ float    g_qn[(size_t)RR * NN * NH];
__device__ float    g_kn[(size_t)RR * NN * NH];
__device__ float    g_logit[(size_t)(300000) * NH];
__device__ float    g_ex[(size_t)(300000) * NH];
__device__ unsigned g_max[NN * NH];               // ordered-uint per-(dst,head) max
__device__ float    g_sum[NN * NH];
__device__ float    g_ce[NH];                     // (We @ e)[h]
__device__ int      g_etmax;

// ---------------- helpers ---------------------------------------------------
__device__ __forceinline__ unsigned ford(float f) {
    unsigned u = __float_as_uint(f);
    return (u & 0x80000000u) ? ~u : (u | 0x80000000u);
}
__device__ __forceinline__ float finv(unsigned u) {
    return (u & 0x80000000u) ? __uint_as_float(u ^ 0x80000000u)
                             : __uint_as_float(~u);
}

// ---------------- init kernels ----------------------------------------------
__global__ void init_scalar_kernel() { g_etmax = 0; }

__global__ void etmax_kernel(const int* __restrict__ et, int E0) {
    int i = blockIdx.x * blockDim.x + threadIdx.x;
    int loc = -1;
    for (; i < E0; i += gridDim.x * blockDim.x) loc = max(loc, et[i]);
    if (loc >= 0) atomicMax(&g_etmax, loc);
}

// zero g_agg [NN*HID], g_sum [NN*NH], init g_max to ford(-inf)
__global__ void clear_kernel() {
    int i = blockIdx.x * blockDim.x + threadIdx.x;
    if (i < NN * HID) g_agg[i] = 0.f;
    if (i < NN * NH) {
        g_sum[i] = 0.f;
        g_max[i] = 0x007FFFFFu;   // ford(-FLT_MAX-ish): smaller than any finite ord
    }
}

// ---------------- SGEMM: C[r] = A @ B[r]  (A:[M,K], B:[K,Nn], C:[M,Nn]) -----
__global__ __launch_bounds__(256)
void sgemm_kernel(const float* __restrict__ A, const float* __restrict__ B0,
                  float* __restrict__ C0, int M, int Nn, int K) {
    const int r = blockIdx.z;
    const float* B = B0 + (size_t)r * K * Nn;
    float*       C = C0 + (size_t)r * M * Nn;

    __shared__ float As[8][128];
    __shared__ float Bs[8][128];

    const int tid  = threadIdx.x;
    const int m0   = blockIdx.y * 128;
    const int n0   = blockIdx.x * 128;
    const int arow = tid >> 1, acol = (tid & 1) * 4;
    const int brow = tid >> 5, bcol = (tid & 31) * 4;
    const int ty   = tid >> 4, tx   = tid & 15;

    const float* Ap = A + (size_t)(m0 + arow) * K + acol;
    const float* Bp = B + (size_t)brow * Nn + n0 + bcol;

    float acc[8][8];
#pragma unroll
    for (int i = 0; i < 8; i++)
#pragma unroll
        for (int j = 0; j < 8; j++) acc[i][j] = 0.f;

    for (int k0 = 0; k0 < K; k0 += 8) {
        float4 av = *(const float4*)(Ap + k0);
        As[acol + 0][arow] = av.x;
        As[acol + 1][arow] = av.y;
        As[acol + 2][arow] = av.z;
        As[acol + 3][arow] = av.w;
        float4 bv = *(const float4*)(Bp + (size_t)k0 * Nn);
        *(float4*)&Bs[brow][bcol] = bv;
        __syncthreads();
#pragma unroll
        for (int kk = 0; kk < 8; kk++) {
            float4 a0 = *(const float4*)&As[kk][ty * 8];
            float4 a1 = *(const float4*)&As[kk][ty * 8 + 4];
            float4 b0 = *(const float4*)&Bs[kk][tx * 8];
            float4 b1 = *(const float4*)&Bs[kk][tx * 8 + 4];
            float a[8] = {a0.x, a0.y, a0.z, a0.w, a1.x, a1.y, a1.z, a1.w};
            float b[8] = {b0.x, b0.y, b0.z, b0.w, b1.x, b1.y, b1.z, b1.w};
#pragma unroll
            for (int i = 0; i < 8; i++)
#pragma unroll
                for (int j = 0; j < 8; j++) acc[i][j] += a[i] * b[j];
        }
        __syncthreads();
    }
#pragma unroll
    for (int i = 0; i < 8; i++) {
        float* Cp = C + (size_t)(m0 + ty * 8 + i) * Nn + n0 + tx * 8;
        *(float4*)(Cp)     = make_float4(acc[i][0], acc[i][1], acc[i][2], acc[i][3]);
        *(float4*)(Cp + 4) = make_float4(acc[i][4], acc[i][5], acc[i][6], acc[i][7]);
    }
}

// ---------------- ce[h] = sum_j We[j] * e[j][h] ------------------------------
__global__ void ce_kernel(const float* __restrict__ We, const float* __restrict__ e) {
    int h = threadIdx.x;
    if (h >= NH) return;
    float s = 0.f;
    for (int j = 0; j < HID; j++) s += We[j] * e[j * NH + h];
    g_ce[h] = s;
}

// ---------------- qn/kn: warp per (r,n) row of g_t ---------------------------
__global__ __launch_bounds__(256)
void qk_kernel(const float* __restrict__ q, const float* __restrict__ k) {
    int warp = (blockIdx.x * blockDim.x + threadIdx.x) >> 5;
    if (warp >= RR * NN) return;
    int lane = threadIdx.x & 31;
    const float* trow = g_t + (size_t)warp * HID;
    float aq[NH], ak[NH];
#pragma unroll
    for (int h = 0; h < NH; h++) { aq[h] = 0.f; ak[h] = 0.f; }
    for (int j = lane; j < HID; j += 32) {
        float tv = trow[j];
        const float* qr = q + j * NH;
        const float* kr = k + j * NH;
#pragma unroll
        for (int h = 0; h < NH; h++) {
            aq[h] += tv * __ldg(qr + h);
            ak[h] += tv * __ldg(kr + h);
        }
    }
#pragma unroll
    for (int h = 0; h < NH; h++) {
#pragma unroll
        for (int o = 16; o; o >>= 1) {
            aq[h] += __shfl_xor_sync(0xffffffffu, aq[h], o);
            ak[h] += __shfl_xor_sync(0xffffffffu, ak[h], o);
        }
    }
    if (lane == 0) {
#pragma unroll
        for (int h = 0; h < NH; h++) {
            g_qn[(size_t)warp * NH + h] = aq[h];
            g_kn[(size_t)warp * NH + h] = ak[h];
        }
    }
}

// ---------------- per-edge logits + segment max ------------------------------
__global__ void logit_kernel(const int* __restrict__ ei, const int* __restrict__ etyp,
                             const float* __restrict__ ea, int E0, int Etot) {
    int e = blockIdx.x * blockDim.x + threadIdx.x;
    if (e >= Etot) return;
    int s, d, r;  float av;
    if (e < E0) { s = ei[e]; d = ei[E0 + e]; r = etyp[e]; av = ea[e]; }
    else        { s = d = e - E0; r = (g_etmax + 1) & (RR - 1); av = 0.5f; }
    const float* qrow = g_qn + ((size_t)r * NN + d) * NH;
    const float* krow = g_kn + ((size_t)r * NN + s) * NH;
#pragma unroll
    for (int h = 0; h < NH; h++) {
        float l = qrow[h] + krow[h] + av * g_ce[h];
        l = (l >= 0.f) ? l : 0.2f * l;
        g_logit[(size_t)e * NH + h] = l;
        atomicMax(&g_max[d * NH + h], ford(l));
    }
}

// ---------------- exp + segment sum -----------------------------------------
__global__ void exp_kernel(const int* __restrict__ ei, int E0, int Etot) {
    int e = blockIdx.x * blockDim.x + threadIdx.x;
    if (e >= Etot) return;
    int d = (e < E0) ? ei[E0 + e] : (e - E0);
#pragma unroll
    for (int h = 0; h < NH; h++) {
        float m  = finv(g_max[d * NH + h]);
        float ex = expf(g_logit[(size_t)e * NH + h] - m);
        g_ex[(size_t)e * NH + h] = ex;
        atomicAdd(&g_sum[d * NH + h], ex);
    }
}

// ---------------- weighted aggregation: warp per edge ------------------------
__global__ __launch_bounds__(256)
void agg_kernel(const int* __restrict__ ei, const int* __restrict__ etyp,
                int E0, int Etot) {
    int e = (blockIdx.x * blockDim.x + threadIdx.x) >> 5;
    if (e >= Etot) return;
    int lane = threadIdx.x & 31;
    int s, d, r;
    if (e < E0) { s = ei[e]; d = ei[E0 + e]; r = etyp[e]; }
    else        { s = d = e - E0; r = (g_etmax + 1) & (RR - 1); }
    float wloc = 0.f;
    if (lane < NH)
        wloc = g_ex[(size_t)e * NH + lane] / (g_sum[d * NH + lane] + 1e-16f);
    const float* trow = g_t + ((size_t)r * NN + s) * HID;
    float*       arow = g_agg + (size_t)d * HID;
#pragma unroll
    for (int i = 0; i < HID / 32; i++) {
        int c = lane + 32 * i;
        float w = __shfl_sync(0xffffffffu, wloc, c >> 6);
        atomicAdd(arow + c, w * trow[c]);
    }
}

// ---------------- epilogues --------------------------------------------------
__global__ void epi_concat_kernel(const float* __restrict__ b) {
    int i = blockIdx.x * blockDim.x + threadIdx.x;
    if (i < NN * HID) g_h[i] = g_agg[i] + b[i & (HID - 1)];
}

__global__ void epi_mean_kernel(const float* __restrict__ b, float* __restrict__ out) {
    int i = blockIdx.x * blockDim.x + threadIdx.x;
    if (i >= NN * OC) return;
    int n = i / OC, o = i % OC;
    float s = 0.f;
#pragma unroll
    for (int h = 0; h < NH; h++) s += g_agg[(size_t)n * HID + h * OC + o];
    out[i] = s * (1.0f / NH) + b[o];
}

// layer-2 input lives in the device global g_h; give the SGEMM a launch path
// that reads it without needing cudaGetSymbolAddress on the host.
__global__ __launch_bounds__(256)
void sgemm_l2_kernel(const float* __restrict__ B0, int Nn, int K) {
    // thin wrapper body duplicated from sgemm_kernel with A = g_h, C = g_t
    const int r = blockIdx.z;
    const float* A = g_h;
    const float* B = B0 + (size_t)r * K * Nn;
    float*       C = g_t + (size_t)r * NN * Nn;

    __shared__ float As[8][128];
    __shared__ float Bs[8][128];

    const int tid  = threadIdx.x;
    const int m0   = blockIdx.y * 128;
    const int n0   = blockIdx.x * 128;
    const int arow = tid >> 1, acol = (tid & 1) * 4;
    const int brow = tid >> 5, bcol = (tid & 31) * 4;
    const int ty   = tid >> 4, tx   = tid & 15;

    const float* Ap = A + (size_t)(m0 + arow) * K + acol;
    const float* Bp = B + (size_t)brow * Nn + n0 + bcol;

    float acc[8][8];
#pragma unroll
    for (int i = 0; i < 8; i++)
#pragma unroll
        for (int j = 0; j < 8; j++) acc[i][j] = 0.f;

    for (int k0 = 0; k0 < K; k0 += 8) {
        float4 av = *(const float4*)(Ap + k0);
        As[acol + 0][arow] = av.x;
        As[acol + 1][arow] = av.y;
        As[acol + 2][arow] = av.z;
        As[acol + 3][arow] = av.w;
        float4 bv = *(const float4*)(Bp + (size_t)k0 * Nn);
        *(float4*)&Bs[brow][bcol] = bv;
        __syncthreads();
#pragma unroll
        for (int kk = 0; kk < 8; kk++) {
            float4 a0 = *(const float4*)&As[kk][ty * 8];
            float4 a1 = *(const float4*)&As[kk][ty * 8 + 4];
            float4 b0 = *(const float4*)&Bs[kk][tx * 8];
            float4 b1 = *(const float4*)&Bs[kk][tx * 8 + 4];
            float a[8] = {a0.x, a0.y, a0.z, a0.w, a1.x, a1.y, a1.z, a1.w};
            float b[8] = {b0.x, b0.y, b0.z, b0.w, b1.x, b1.y, b1.z, b1.w};
#pragma unroll
            for (int i = 0; i < 8; i++)
#pragma unroll
                for (int j = 0; j < 8; j++) acc[i][j] += a[i] * b[j];
        }
        __syncthreads();
    }
#pragma unroll
    for (int i = 0; i < 8; i++) {
        float* Cp = C + (size_t)(m0 + ty * 8 + i) * Nn + n0 + tx * 8;
        *(float4*)(Cp)     = make_float4(acc[i][0], acc[i][1], acc[i][2], acc[i][3]);
        *(float4*)(Cp + 4) = make_float4(acc[i][4], acc[i][5], acc[i][6], acc[i][7]);
    }
}

// ---------------- layer-1 SGEMM wrapper: A = x (input), C = g_t ---------------
__global__ __launch_bounds__(256)
void sgemm_l1_kernel(const float* __restrict__ A, const float* __restrict__ B0,
                     int Nn, int K) {
    const int r = blockIdx.z;
    const float* B = B0 + (size_t)r * K * Nn;
    float*       C = g_t + (size_t)r * NN * Nn;

    __shared__ float As[8][128];
    __shared__ float Bs[8][128];

    const int tid  = threadIdx.x;
    const int m0   = blockIdx.y * 128;
    const int n0   = blockIdx.x * 128;
    const int arow = tid >> 1, acol = (tid & 1) * 4;
    const int brow = tid >> 5, bcol = (tid & 31) * 4;
    const int ty   = tid >> 4, tx   = tid & 15;

    const float* Ap = A + (size_t)(m0 + arow) * K + acol;
    const float* Bp = B + (size_t)brow * Nn + n0 + bcol;

    float acc[8][8];
#pragma unroll
    for (int i = 0; i < 8; i++)
#pragma unroll
        for (int j = 0; j < 8; j++) acc[i][j] = 0.f;

    for (int k0 = 0; k0 < K; k0 += 8) {
        float4 av = *(const float4*)(Ap + k0);
        As[acol + 0][arow] = av.x;
        As[acol + 1][arow] = av.y;
        As[acol + 2][arow] = av.z;
        As[acol + 3][arow] = av.w;
        float4 bv = *(const float4*)(Bp + (size_t)k0 * Nn);
        *(float4*)&Bs[brow][bcol] = bv;
        __syncthreads();
#pragma unroll
        for (int kk = 0; kk < 8; kk++) {
            float4 a0 = *(const float4*)&As[kk][ty * 8];
            float4 a1 = *(const float4*)&As[kk][ty * 8 + 4];
            float4 b0 = *(const float4*)&Bs[kk][tx * 8];
            float4 b1 = *(const float4*)&Bs[kk][tx * 8 + 4];
            float a[8] = {a0.x, a0.y, a0.z, a0.w, a1.x, a1.y, a1.z, a1.w};
            float b[8] = {b0.x, b0.y, b0.z, b0.w, b1.x, b1.y, b1.z, b1.w};
#pragma unroll
            for (int i = 0; i < 8; i++)
#pragma unroll
                for (int j = 0; j < 8; j++) acc[i][j] += a[i] * b[j];
        }
        __syncthreads();
    }
#pragma unroll
    for (int i = 0; i < 8; i++) {
        float* Cp = C + (size_t)(m0 + ty * 8 + i) * Nn + n0 + tx * 8;
        *(float4*)(Cp)     = make_float4(acc[i][0], acc[i][1], acc[i][2], acc[i][3]);
        *(float4*)(Cp + 4) = make_float4(acc[i][4], acc[i][5], acc[i][6], acc[i][7]);
    }
}

// ---------------- host driver ------------------------------------------------
extern "C" void kernel_launch(void* const* d_in, const int* in_sizes, int n_in,
                              void* d_out, int out_size) {
    const float* x   = (const float*)d_in[0];
    const int*   ei  = (const int*)  d_in[1];
    const int*   ety = (const int*)  d_in[2];
    const float* ea  = (const float*)d_in[3];
    const float* W1  = (const float*)d_in[4];
    const float* q1  = (const float*)d_in[5];
    const float* k1  = (const float*)d_in[6];
    const float* We1 = (const float*)d_in[7];
    const float* e1  = (const float*)d_in[8];
    const float* b1  = (const float*)d_in[9];
    const float* W2  = (const float*)d_in[10];
    const float* q2  = (const float*)d_in[11];
    const float* k2  = (const float*)d_in[12];
    const float* We2 = (const float*)d_in[13];
    const float* e2  = (const float*)d_in[14];
    const float* b2  = (const float*)d_in[15];

    const int E0   = in_sizes[2];
    const int Etot = E0 + NN;

    const dim3 gg(HID / 128, NN / 128, RR);
    const int  clearB = (NN * HID + 255) / 256;

    init_scalar_kernel<<<1, 1>>>();
    etmax_kernel<<<256, 256>>>(ety, E0);

    // ---------------- layer 1 (concat) ----------------
    sgemm_l1_kernel<<<gg, 256>>>(x, W1, HID, F1);
    ce_kernel<<<1, NH>>>(We1, e1);
    qk_kernel<<<(RR * NN) / 8, 256>>>(q1, k1);
    clear_kernel<<<clearB, 256>>>();
    logit_kernel<<<(Etot + 255) / 256, 256>>>(ei, ety, ea, E0, Etot);
    exp_kernel<<<(Etot + 255) / 256, 256>>>(ei, E0, Etot);
    agg_kernel<<<(Etot * 32 + 255) / 256, 256>>>(ei, ety, E0, Etot);
    epi_concat_kernel<<<clearB, 256>>>(b1);

    // ---------------- layer 2 (mean) ------------------
    sgemm_l2_kernel<<<gg, 256>>>(W2, HID, HID);
    ce_kernel<<<1, NH>>>(We2, e2);
    qk_kernel<<<(RR * NN) / 8, 256>>>(q2, k2);
    clear_kernel<<<clearB, 256>>>();
    logit_kernel<<<(Etot + 255) / 256, 256>>>(ei, ety, ea, E0, Etot);
    exp_kernel<<<(Etot + 255) / 256, 256>>>(ei, E0, Etot);
    agg_kernel<<<(Etot * 32 + 255) / 256, 256>>>(ei, ety, E0, Etot);
    epi_mean_kernel<<<(NN * OC + 255) / 256, 256>>>(b2, (float*)d_out);
}

// round 3
// speedup vs baseline: 1.3356x; 1.3356x over previous
#include <cuda_runtime.h>
#include <cstdint>

// Problem dimensions (fixed by the dataset)
#define NN   16000          // nodes
#define F1   256            // layer-1 input features
#define HID  512            // HEADS*OUT
#define NH   8              // heads
#define OC   64             // per-head out channels
#define RR   8              // relations

// ---------------- scratch (device globals; no allocation allowed) ----------
__device__ float    g_t[(size_t)RR * NN * HID];   // relation-transformed nodes [R,N,512]
__device__ float    g_h[(size_t)NN * HID];        // layer-1 output
__device__ float    g_agg[(size_t)NN * HID];      // aggregation buffer
__device__ float    g_qn[(size_t)RR * NN * NH];
__device__ float    g_kn[(size_t)RR * NN * NH];
__device__ float    g_logit[(size_t)(300000) * NH];
__device__ float    g_ex[(size_t)(300000) * NH];
__device__ unsigned g_max[NN * NH];               // ordered-uint per-(dst,head) max
__device__ float    g_sum[NN * NH];
__device__ float    g_ce[NH];                     // (We @ e)[h]
__device__ int      g_etmax;

// ---------------- helpers ---------------------------------------------------
__device__ __forceinline__ unsigned ford(float f) {
    unsigned u = __float_as_uint(f);
    return (u & 0x80000000u) ? ~u : (u | 0x80000000u);
}
__device__ __forceinline__ float finv(unsigned u) {
    return (u & 0x80000000u) ? __uint_as_float(u ^ 0x80000000u)
                             : __uint_as_float(~u);
}
__device__ __forceinline__ uint32_t f2tf(float f) {
    uint32_t u;
    asm("cvt.rna.tf32.f32 %0, %1;" : "=r"(u) : "f"(f));
    return u;
}
__device__ __forceinline__ void mma_tf32(float c[4], const uint32_t a[4], const uint32_t b[2]) {
    asm volatile("mma.sync.aligned.m16n8k8.row.col.f32.tf32.tf32.f32 "
                 "{%0,%1,%2,%3}, {%4,%5,%6,%7}, {%8,%9}, {%0,%1,%2,%3};"
                 : "+f"(c[0]), "+f"(c[1]), "+f"(c[2]), "+f"(c[3])
                 : "r"(a[0]), "r"(a[1]), "r"(a[2]), "r"(a[3]), "r"(b[0]), "r"(b[1]));
}

// ---------------- init kernels ----------------------------------------------
__global__ void init_scalar_kernel() { g_etmax = 0; }

__global__ void etmax_kernel(const int* __restrict__ et, int E0) {
    int i = blockIdx.x * blockDim.x + threadIdx.x;
    int loc = -1;
    for (; i < E0; i += gridDim.x * blockDim.x) loc = max(loc, et[i]);
    if (loc >= 0) atomicMax(&g_etmax, loc);
}

// zero g_agg [NN*HID], g_sum [NN*NH], init g_max to ford(-inf)
__global__ void clear_kernel() {
    int i = blockIdx.x * blockDim.x + threadIdx.x;
    if (i < NN * HID) g_agg[i] = 0.f;
    if (i < NN * NH) {
        g_sum[i] = 0.f;
        g_max[i] = 0x007FFFFFu;
    }
}

// ---------------- tf32 tensor-core GEMM -------------------------------------
// C[128x128 tile] = A[M x K] @ B[K x 512], row-major everywhere.
// Block: 256 threads = 8 warps, warp tile 32(m) x 64(n), BK=16, double-buffered.
// As stored transposed [k][m] (+4 pad); Bs [k][n] (+4 pad). Both fragment LDS
// and staging STS are bank-conflict-free. tf32 conversion happens at staging.
__device__ __forceinline__ void gemm_tf32_body(
    const float* __restrict__ A, const float* __restrict__ B,
    float* __restrict__ C, int K, int m0, int n0)
{
    __shared__ uint32_t As[2][16][132];
    __shared__ uint32_t Bs[2][16][132];

    const int tid  = threadIdx.x;
    const int lane = tid & 31, warp = tid >> 5;
    const int grp  = lane >> 2, tig = lane & 3;
    const int wm   = (warp & 3) * 32;
    const int wn   = (warp >> 2) * 64;

    // loader mapping (two 256-element chunks)
    const int am  = tid & 127;         // A: m within tile (consecutive per warp)
    const int akq0 = tid >> 7;         // A: k-quad 0..1 (chunk0), +2 for chunk1
    const int akq1 = akq0 + 2;
    const int bn4 = tid & 31;          // B: n-quad (consecutive per warp)
    const int bk0 = tid >> 5;          // B: k row 0..7 (chunk0), +8 chunk1
    const int bk1 = bk0 + 8;

    const float* Ag0 = A + (size_t)(m0 + am) * K + 4 * akq0;
    const float* Ag1 = A + (size_t)(m0 + am) * K + 4 * akq1;
    const float* Bg0 = B + (size_t)bk0 * 512 + n0 + 4 * bn4;
    const float* Bg1 = B + (size_t)bk1 * 512 + n0 + 4 * bn4;

    float c[2][8][4];
#pragma unroll
    for (int mt = 0; mt < 2; mt++)
#pragma unroll
        for (int nt = 0; nt < 8; nt++)
#pragma unroll
            for (int i = 0; i < 4; i++) c[mt][nt][i] = 0.f;

    // prologue: stage tile 0
    float4 a0v = *(const float4*)Ag0;
    float4 a1v = *(const float4*)Ag1;
    float4 b0v = *(const float4*)Bg0;
    float4 b1v = *(const float4*)Bg1;
    As[0][4 * akq0 + 0][am] = f2tf(a0v.x); As[0][4 * akq0 + 1][am] = f2tf(a0v.y);
    As[0][4 * akq0 + 2][am] = f2tf(a0v.z); As[0][4 * akq0 + 3][am] = f2tf(a0v.w);
    As[0][4 * akq1 + 0][am] = f2tf(a1v.x); As[0][4 * akq1 + 1][am] = f2tf(a1v.y);
    As[0][4 * akq1 + 2][am] = f2tf(a1v.z); As[0][4 * akq1 + 3][am] = f2tf(a1v.w);
    *(uint4*)&Bs[0][bk0][4 * bn4] = make_uint4(f2tf(b0v.x), f2tf(b0v.y), f2tf(b0v.z), f2tf(b0v.w));
    *(uint4*)&Bs[0][bk1][4 * bn4] = make_uint4(f2tf(b1v.x), f2tf(b1v.y), f2tf(b1v.z), f2tf(b1v.w));
    __syncthreads();

    int buf = 0;
    const int NSTEP = K >> 4;
    for (int s = 0; s < NSTEP; s++) {
        const bool nxt = (s + 1) < NSTEP;
        if (nxt) {
            const int ko = (s + 1) << 4;
            a0v = *(const float4*)(Ag0 + ko);
            a1v = *(const float4*)(Ag1 + ko);
            b0v = *(const float4*)(Bg0 + (size_t)ko * 512);
            b1v = *(const float4*)(Bg1 + (size_t)ko * 512);
        }
#pragma unroll
        for (int kb = 0; kb < 16; kb += 8) {
            uint32_t af[2][4], bf[8][2];
#pragma unroll
            for (int mt = 0; mt < 2; mt++) {
                const int mc = wm + mt * 16 + grp;
                af[mt][0] = As[buf][kb + tig][mc];
                af[mt][1] = As[buf][kb + tig][mc + 8];
                af[mt][2] = As[buf][kb + tig + 4][mc];
                af[mt][3] = As[buf][kb + tig + 4][mc + 8];
            }
#pragma unroll
            for (int nt = 0; nt < 8; nt++) {
                const int nc = wn + nt * 8 + grp;
                bf[nt][0] = Bs[buf][kb + tig][nc];
                bf[nt][1] = Bs[buf][kb + tig + 4][nc];
            }
#pragma unroll
            for (int mt = 0; mt < 2; mt++)
#pragma unroll
                for (int nt = 0; nt < 8; nt++)
                    mma_tf32(c[mt][nt], af[mt], bf[nt]);
        }
        if (nxt) {
            const int nb = buf ^ 1;
            As[nb][4 * akq0 + 0][am] = f2tf(a0v.x); As[nb][4 * akq0 + 1][am] = f2tf(a0v.y);
            As[nb][4 * akq0 + 2][am] = f2tf(a0v.z); As[nb][4 * akq0 + 3][am] = f2tf(a0v.w);
            As[nb][4 * akq1 + 0][am] = f2tf(a1v.x); As[nb][4 * akq1 + 1][am] = f2tf(a1v.y);
            As[nb][4 * akq1 + 2][am] = f2tf(a1v.z); As[nb][4 * akq1 + 3][am] = f2tf(a1v.w);
            *(uint4*)&Bs[nb][bk0][4 * bn4] = make_uint4(f2tf(b0v.x), f2tf(b0v.y), f2tf(b0v.z), f2tf(b0v.w));
            *(uint4*)&Bs[nb][bk1][4 * bn4] = make_uint4(f2tf(b1v.x), f2tf(b1v.y), f2tf(b1v.z), f2tf(b1v.w));
            __syncthreads();
            buf = nb;
        }
    }

    // epilogue
#pragma unroll
    for (int mt = 0; mt < 2; mt++) {
        const int row = m0 + wm + mt * 16 + grp;
#pragma unroll
        for (int nt = 0; nt < 8; nt++) {
            const int col = n0 + wn + nt * 8 + tig * 2;
            *(float2*)(C + (size_t)row * 512 + col)       = make_float2(c[mt][nt][0], c[mt][nt][1]);
            *(float2*)(C + (size_t)(row + 8) * 512 + col) = make_float2(c[mt][nt][2], c[mt][nt][3]);
        }
    }
}

// grid: x = (n_tile | r<<2)  [adjacent blocks share the A tile -> L2 reuse], y = m_tile
__global__ __launch_bounds__(256, 2)
void gemm_l1_kernel(const float* __restrict__ A, const float* __restrict__ B0) {
    const int nb = blockIdx.x & 3, r = blockIdx.x >> 2;
    gemm_tf32_body(A, B0 + (size_t)r * F1 * HID,
                   g_t + (size_t)r * NN * HID, F1,
                   blockIdx.y * 128, nb * 128);
}
__global__ __launch_bounds__(256, 2)
void gemm_l2_kernel(const float* __restrict__ B0) {
    const int nb = blockIdx.x & 3, r = blockIdx.x >> 2;
    gemm_tf32_body(g_h, B0 + (size_t)r * HID * HID,
                   g_t + (size_t)r * NN * HID, HID,
                   blockIdx.y * 128, nb * 128);
}

// ---------------- ce[h] = sum_j We[j] * e[j][h] (warp per head) --------------
__global__ void ce_kernel(const float* __restrict__ We, const float* __restrict__ e) {
    const int warp = threadIdx.x >> 5, lane = threadIdx.x & 31;
    float s = 0.f;
    for (int j = lane; j < HID; j += 32) s += We[j] * e[j * NH + warp];
#pragma unroll
    for (int o = 16; o; o >>= 1) s += __shfl_xor_sync(0xffffffffu, s, o);
    if (lane == 0) g_ce[warp] = s;
}

// ---------------- qn/kn: warp per (r,n) row of g_t ---------------------------
__global__ __launch_bounds__(256)
void qk_kernel(const float* __restrict__ q, const float* __restrict__ k) {
    int warp = (blockIdx.x * blockDim.x + threadIdx.x) >> 5;
    if (warp >= RR * NN) return;
    int lane = threadIdx.x & 31;
    const float* trow = g_t + (size_t)warp * HID;
    float aq[NH], ak[NH];
#pragma unroll
    for (int h = 0; h < NH; h++) { aq[h] = 0.f; ak[h] = 0.f; }
    for (int j = lane; j < HID; j += 32) {
        float tv = trow[j];
        const float* qr = q + j * NH;
        const float* kr = k + j * NH;
#pragma unroll
        for (int h = 0; h < NH; h++) {
            aq[h] += tv * __ldg(qr + h);
            ak[h] += tv * __ldg(kr + h);
        }
    }
#pragma unroll
    for (int h = 0; h < NH; h++) {
#pragma unroll
        for (int o = 16; o; o >>= 1) {
            aq[h] += __shfl_xor_sync(0xffffffffu, aq[h], o);
            ak[h] += __shfl_xor_sync(0xffffffffu, ak[h], o);
        }
    }
    if (lane == 0) {
#pragma unroll
        for (int h = 0; h < NH; h++) {
            g_qn[(size_t)warp * NH + h] = aq[h];
            g_kn[(size_t)warp * NH + h] = ak[h];
        }
    }
}

// ---------------- per-edge logits + segment max ------------------------------
__global__ void logit_kernel(const int* __restrict__ ei, const int* __restrict__ etyp,
                             const float* __restrict__ ea, int E0, int Etot) {
    int e = blockIdx.x * blockDim.x + threadIdx.x;
    if (e >= Etot) return;
    int s, d, r;  float av;
    if (e < E0) { s = ei[e]; d = ei[E0 + e]; r = etyp[e]; av = ea[e]; }
    else        { s = d = e - E0; r = (g_etmax + 1) & (RR - 1); av = 0.5f; }
    const float* qrow = g_qn + ((size_t)r * NN + d) * NH;
    const float* krow = g_kn + ((size_t)r * NN + s) * NH;
#pragma unroll
    for (int h = 0; h < NH; h++) {
        float l = qrow[h] + krow[h] + av * g_ce[h];
        l = (l >= 0.f) ? l : 0.2f * l;
        g_logit[(size_t)e * NH + h] = l;
        atomicMax(&g_max[d * NH + h], ford(l));
    }
}

// ---------------- exp + segment sum -----------------------------------------
__global__ void exp_kernel(const int* __restrict__ ei, int E0, int Etot) {
    int e = blockIdx.x * blockDim.x + threadIdx.x;
    if (e >= Etot) return;
    int d = (e < E0) ? ei[E0 + e] : (e - E0);
#pragma unroll
    for (int h = 0; h < NH; h++) {
        float m  = finv(g_max[d * NH + h]);
        float ex = expf(g_logit[(size_t)e * NH + h] - m);
        g_ex[(size_t)e * NH + h] = ex;
        atomicAdd(&g_sum[d * NH + h], ex);
    }
}

// ---------------- weighted aggregation: warp per edge ------------------------
__global__ __launch_bounds__(256)
void agg_kernel(const int* __restrict__ ei, const int* __restrict__ etyp,
                int E0, int Etot) {
    int e = (blockIdx.x * blockDim.x + threadIdx.x) >> 5;
    if (e >= Etot) return;
    int lane = threadIdx.x & 31;
    int s, d, r;
    if (e < E0) { s = ei[e]; d = ei[E0 + e]; r = etyp[e]; }
    else        { s = d = e - E0; r = (g_etmax + 1) & (RR - 1); }
    float wloc = 0.f;
    if (lane < NH)
        wloc = g_ex[(size_t)e * NH + lane] / (g_sum[d * NH + lane] + 1e-16f);
    const float* trow = g_t + ((size_t)r * NN + s) * HID;
    float*       arow = g_agg + (size_t)d * HID;
#pragma unroll
    for (int i = 0; i < HID / 32; i++) {
        int c = lane + 32 * i;
        float w = __shfl_sync(0xffffffffu, wloc, c >> 6);
        atomicAdd(arow + c, w * trow[c]);
    }
}

// ---------------- epilogues --------------------------------------------------
__global__ void epi_concat_kernel(const float* __restrict__ b) {
    int i = blockIdx.x * blockDim.x + threadIdx.x;
    if (i < NN * HID) g_h[i] = g_agg[i] + b[i & (HID - 1)];
}

__global__ void epi_mean_kernel(const float* __restrict__ b, float* __restrict__ out) {
    int i = blockIdx.x * blockDim.x + threadIdx.x;
    if (i >= NN * OC) return;
    int n = i / OC, o = i % OC;
    float s = 0.f;
#pragma unroll
    for (int h = 0; h < NH; h++) s += g_agg[(size_t)n * HID + h * OC + o];
    out[i] = s * (1.0f / NH) + b[o];
}

// ---------------- host driver ------------------------------------------------
extern "C" void kernel_launch(void* const* d_in, const int* in_sizes, int n_in,
                              void* d_out, int out_size) {
    const float* x   = (const float*)d_in[0];
    const int*   ei  = (const int*)  d_in[1];
    const int*   ety = (const int*)  d_in[2];
    const float* ea  = (const float*)d_in[3];
    const float* W1  = (const float*)d_in[4];
    const float* q1  = (const float*)d_in[5];
    const float* k1  = (const float*)d_in[6];
    const float* We1 = (const float*)d_in[7];
    const float* e1  = (const float*)d_in[8];
    const float* b1  = (const float*)d_in[9];
    const float* W2  = (const float*)d_in[10];
    const float* q2  = (const float*)d_in[11];
    const float* k2  = (const float*)d_in[12];
    const float* We2 = (const float*)d_in[13];
    const float* e2  = (const float*)d_in[14];
    const float* b2  = (const float*)d_in[15];

    const int E0   = in_sizes[2];
    const int Etot = E0 + NN;

    const dim3 gg(4 * RR, NN / 128);      // (n_tile | r<<2, m_tile)
    const int  clearB = (NN * HID + 255) / 256;

    init_scalar_kernel<<<1, 1>>>();
    etmax_kernel<<<256, 256>>>(ety, E0);

    // ---------------- layer 1 (concat) ----------------
    gemm_l1_kernel<<<gg, 256>>>(x, W1);
    ce_kernel<<<1, 256>>>(We1, e1);
    qk_kernel<<<(RR * NN) / 8, 256>>>(q1, k1);
    clear_kernel<<<clearB, 256>>>();
    logit_kernel<<<(Etot + 255) / 256, 256>>>(ei, ety, ea, E0, Etot);
    exp_kernel<<<(Etot + 255) / 256, 256>>>(ei, E0, Etot);
    agg_kernel<<<(Etot * 32 + 255) / 256, 256>>>(ei, ety, E0, Etot);
    epi_concat_kernel<<<clearB, 256>>>(b1);

    // ---------------- layer 2 (mean) ------------------
    gemm_l2_kernel<<<gg, 256>>>(W2);
    ce_kernel<<<1, 256>>>(We2, e2);
    qk_kernel<<<(RR * NN) / 8, 256>>>(q2, k2);
    clear_kernel<<<clearB, 256>>>();
    logit_kernel<<<(Etot + 255) / 256, 256>>>(ei, ety, ea, E0, Etot);
    exp_kernel<<<(Etot + 255) / 256, 256>>>(ei, E0, Etot);
    agg_kernel<<<(Etot * 32 + 255) / 256, 256>>>(ei, ety, E0, Etot);
    epi_mean_kernel<<<(NN * OC + 255) / 256, 256>>>(b2, (float*)d_out);
}

// round 4
// speedup vs baseline: 2.0377x; 1.5257x over previous
#include <cuda_runtime.h>
#include <cstdint>

// Problem dimensions (fixed by the dataset)
#define NN   16000          // nodes
#define F1   256            // layer-1 input features
#define HID  512            // HEADS*OUT
#define NH   8              // heads
#define OC   64             // per-head out channels
#define RR   8              // relations
#define ECAP 300000         // capacity for edges + self loops

// ---------------- scratch (device globals; no allocation allowed) ----------
__device__ float    g_t[(size_t)RR * NN * HID];   // relation-transformed nodes [R,N,512]
__device__ float    g_h[(size_t)NN * HID];        // layer-1 output
__device__ float    g_qn[(size_t)RR * NN * NH];
__device__ float    g_kn[(size_t)RR * NN * NH];
__device__ float    g_ce[NH];                     // (We @ e)[h]
__device__ int      g_etmax;
__device__ int      g_hist[NN];
__device__ int      g_rowptr[NN + 1];
__device__ int      g_cursor[NN];
__device__ int      g_csr_sr[ECAP];               // src | (rel << 20)
__device__ float    g_csr_attr[ECAP];

// ---------------- helpers ---------------------------------------------------
__device__ __forceinline__ uint32_t f2tf(float f) {
    uint32_t u;
    asm("cvt.rna.tf32.f32 %0, %1;" : "=r"(u) : "f"(f));
    return u;
}
__device__ __forceinline__ void mma_tf32(float c[4], const uint32_t a[4], const uint32_t b[2]) {
    asm volatile("mma.sync.aligned.m16n8k8.row.col.f32.tf32.tf32.f32 "
                 "{%0,%1,%2,%3}, {%4,%5,%6,%7}, {%8,%9}, {%0,%1,%2,%3};"
                 : "+f"(c[0]), "+f"(c[1]), "+f"(c[2]), "+f"(c[3])
                 : "r"(a[0]), "r"(a[1]), "r"(a[2]), "r"(a[3]), "r"(b[0]), "r"(b[1]));
}

// ---------------- CSR build --------------------------------------------------
__global__ void init_kernel() {
    int i = blockIdx.x * blockDim.x + threadIdx.x;
    if (i < NN) g_hist[i] = 0;
    if (i == 0) g_etmax = 0;
}

__global__ void etmax_kernel(const int* __restrict__ et, int E0) {
    int i = blockIdx.x * blockDim.x + threadIdx.x;
    int loc = -1;
    for (; i < E0; i += gridDim.x * blockDim.x) loc = max(loc, et[i]);
    if (loc >= 0) atomicMax(&g_etmax, loc);
}

__global__ void hist_kernel(const int* __restrict__ ei, int E0, int Etot) {
    int e = blockIdx.x * blockDim.x + threadIdx.x;
    if (e >= Etot) return;
    int d = (e < E0) ? ei[E0 + e] : (e - E0);
    atomicAdd(&g_hist[d], 1);
}

__global__ __launch_bounds__(1024)
void scan_kernel() {
    __shared__ int sm[1024];
    const int t = threadIdx.x;
    const int base = t * 16;
    int loc[16];
    int sum = 0;
#pragma unroll
    for (int i = 0; i < 16; i++) {
        int idx = base + i;
        int v = (idx < NN) ? g_hist[idx] : 0;
        loc[i] = sum;
        sum += v;
    }
    sm[t] = sum;
    __syncthreads();
    for (int off = 1; off < 1024; off <<= 1) {
        int v = (t >= off) ? sm[t - off] : 0;
        __syncthreads();
        sm[t] += v;
        __syncthreads();
    }
    int pre = (t > 0) ? sm[t - 1] : 0;
#pragma unroll
    for (int i = 0; i < 16; i++) {
        int idx = base + i;
        if (idx < NN) {
            g_rowptr[idx] = pre + loc[i];
            g_cursor[idx] = pre + loc[i];
        }
    }
    if (t == 1023) g_rowptr[NN] = sm[1023];
}

__global__ void scatter_kernel(const int* __restrict__ ei, const int* __restrict__ etyp,
                               const float* __restrict__ ea, int E0, int Etot) {
    int e = blockIdx.x * blockDim.x + threadIdx.x;
    if (e >= Etot) return;
    int s, d, r;  float at;
    if (e < E0) { s = ei[e]; d = ei[E0 + e]; r = etyp[e]; at = ea[e]; }
    else        { s = d = e - E0; r = (g_etmax + 1) & (RR - 1); at = 0.5f; }
    int p = atomicAdd(&g_cursor[d], 1);
    g_csr_sr[p]   = s | (r << 20);
    g_csr_attr[p] = at;
}

// ---------------- tf32 tensor-core GEMM -------------------------------------
__device__ __forceinline__ void gemm_tf32_body(
    const float* __restrict__ A, const float* __restrict__ B,
    float* __restrict__ C, int K, int m0, int n0)
{
    __shared__ uint32_t As[2][16][132];
    __shared__ uint32_t Bs[2][16][132];

    const int tid  = threadIdx.x;
    const int lane = tid & 31, warp = tid >> 5;
    const int grp  = lane >> 2, tig = lane & 3;
    const int wm   = (warp & 3) * 32;
    const int wn   = (warp >> 2) * 64;

    const int am  = tid & 127;
    const int akq0 = tid >> 7;
    const int akq1 = akq0 + 2;
    const int bn4 = tid & 31;
    const int bk0 = tid >> 5;
    const int bk1 = bk0 + 8;

    const float* Ag0 = A + (size_t)(m0 + am) * K + 4 * akq0;
    const float* Ag1 = A + (size_t)(m0 + am) * K + 4 * akq1;
    const float* Bg0 = B + (size_t)bk0 * 512 + n0 + 4 * bn4;
    const float* Bg1 = B + (size_t)bk1 * 512 + n0 + 4 * bn4;

    float c[2][8][4];
#pragma unroll
    for (int mt = 0; mt < 2; mt++)
#pragma unroll
        for (int nt = 0; nt < 8; nt++)
#pragma unroll
            for (int i = 0; i < 4; i++) c[mt][nt][i] = 0.f;

    float4 a0v = *(const float4*)Ag0;
    float4 a1v = *(const float4*)Ag1;
    float4 b0v = *(const float4*)Bg0;
    float4 b1v = *(const float4*)Bg1;
    As[0][4 * akq0 + 0][am] = f2tf(a0v.x); As[0][4 * akq0 + 1][am] = f2tf(a0v.y);
    As[0][4 * akq0 + 2][am] = f2tf(a0v.z); As[0][4 * akq0 + 3][am] = f2tf(a0v.w);
    As[0][4 * akq1 + 0][am] = f2tf(a1v.x); As[0][4 * akq1 + 1][am] = f2tf(a1v.y);
    As[0][4 * akq1 + 2][am] = f2tf(a1v.z); As[0][4 * akq1 + 3][am] = f2tf(a1v.w);
    *(uint4*)&Bs[0][bk0][4 * bn4] = make_uint4(f2tf(b0v.x), f2tf(b0v.y), f2tf(b0v.z), f2tf(b0v.w));
    *(uint4*)&Bs[0][bk1][4 * bn4] = make_uint4(f2tf(b1v.x), f2tf(b1v.y), f2tf(b1v.z), f2tf(b1v.w));
    __syncthreads();

    int buf = 0;
    const int NSTEP = K >> 4;
    for (int s = 0; s < NSTEP; s++) {
        const bool nxt = (s + 1) < NSTEP;
        if (nxt) {
            const int ko = (s + 1) << 4;
            a0v = *(const float4*)(Ag0 + ko);
            a1v = *(const float4*)(Ag1 + ko);
            b0v = *(const float4*)(Bg0 + (size_t)ko * 512);
            b1v = *(const float4*)(Bg1 + (size_t)ko * 512);
        }
#pragma unroll
        for (int kb = 0; kb < 16; kb += 8) {
            uint32_t af[2][4], bf[8][2];
#pragma unroll
            for (int mt = 0; mt < 2; mt++) {
                const int mc = wm + mt * 16 + grp;
                af[mt][0] = As[buf][kb + tig][mc];
                af[mt][1] = As[buf][kb + tig][mc + 8];
                af[mt][2] = As[buf][kb + tig + 4][mc];
                af[mt][3] = As[buf][kb + tig + 4][mc + 8];
            }
#pragma unroll
            for (int nt = 0; nt < 8; nt++) {
                const int nc = wn + nt * 8 + grp;
                bf[nt][0] = Bs[buf][kb + tig][nc];
                bf[nt][1] = Bs[buf][kb + tig + 4][nc];
            }
#pragma unroll
            for (int mt = 0; mt < 2; mt++)
#pragma unroll
                for (int nt = 0; nt < 8; nt++)
                    mma_tf32(c[mt][nt], af[mt], bf[nt]);
        }
        if (nxt) {
            const int nb = buf ^ 1;
            As[nb][4 * akq0 + 0][am] = f2tf(a0v.x); As[nb][4 * akq0 + 1][am] = f2tf(a0v.y);
            As[nb][4 * akq0 + 2][am] = f2tf(a0v.z); As[nb][4 * akq0 + 3][am] = f2tf(a0v.w);
            As[nb][4 * akq1 + 0][am] = f2tf(a1v.x); As[nb][4 * akq1 + 1][am] = f2tf(a1v.y);
            As[nb][4 * akq1 + 2][am] = f2tf(a1v.z); As[nb][4 * akq1 + 3][am] = f2tf(a1v.w);
            *(uint4*)&Bs[nb][bk0][4 * bn4] = make_uint4(f2tf(b0v.x), f2tf(b0v.y), f2tf(b0v.z), f2tf(b0v.w));
            *(uint4*)&Bs[nb][bk1][4 * bn4] = make_uint4(f2tf(b1v.x), f2tf(b1v.y), f2tf(b1v.z), f2tf(b1v.w));
            __syncthreads();
            buf = nb;
        }
    }

#pragma unroll
    for (int mt = 0; mt < 2; mt++) {
        const int row = m0 + wm + mt * 16 + grp;
#pragma unroll
        for (int nt = 0; nt < 8; nt++) {
            const int col = n0 + wn + nt * 8 + tig * 2;
            *(float2*)(C + (size_t)row * 512 + col)       = make_float2(c[mt][nt][0], c[mt][nt][1]);
            *(float2*)(C + (size_t)(row + 8) * 512 + col) = make_float2(c[mt][nt][2], c[mt][nt][3]);
        }
    }
}

__global__ __launch_bounds__(256, 2)
void gemm_l1_kernel(const float* __restrict__ A, const float* __restrict__ B0) {
    const int nb = blockIdx.x & 3, r = blockIdx.x >> 2;
    gemm_tf32_body(A, B0 + (size_t)r * F1 * HID,
                   g_t + (size_t)r * NN * HID, F1,
                   blockIdx.y * 128, nb * 128);
}
__global__ __launch_bounds__(256, 2)
void gemm_l2_kernel(const float* __restrict__ B0) {
    const int nb = blockIdx.x & 3, r = blockIdx.x >> 2;
    gemm_tf32_body(g_h, B0 + (size_t)r * HID * HID,
                   g_t + (size_t)r * NN * HID, HID,
                   blockIdx.y * 128, nb * 128);
}

// ---------------- ce[h] = sum_j We[j] * e[j][h] (warp per head) --------------
__global__ void ce_kernel(const float* __restrict__ We, const float* __restrict__ e) {
    const int warp = threadIdx.x >> 5, lane = threadIdx.x & 31;
    float s = 0.f;
    for (int j = lane; j < HID; j += 32) s += We[j] * e[j * NH + warp];
#pragma unroll
    for (int o = 16; o; o >>= 1) s += __shfl_xor_sync(0xffffffffu, s, o);
    if (lane == 0) g_ce[warp] = s;
}

// ---------------- qn/kn: warp per 2 rows of g_t, float4 loads ----------------
__global__ __launch_bounds__(256)
void qk_kernel(const float* __restrict__ q, const float* __restrict__ k) {
    int wp = (blockIdx.x * blockDim.x + threadIdx.x) >> 5;   // row pair
    if (wp >= RR * NN / 2) return;
    const int lane = threadIdx.x & 31;
    const float4* t4a = (const float4*)(g_t + (size_t)(2 * wp) * HID);
    const float4* t4b = t4a + 128;
    const float4* q4  = (const float4*)q;
    const float4* k4  = (const float4*)k;
    float aq0[NH], aq1[NH], ak0[NH], ak1[NH];
#pragma unroll
    for (int h = 0; h < NH; h++) { aq0[h] = aq1[h] = ak0[h] = ak1[h] = 0.f; }
#pragma unroll
    for (int i = 0; i < 4; i++) {
        const int j4 = lane + 32 * i;
        float4 ta = t4a[j4];
        float4 tb = t4b[j4];
        const float tav[4] = {ta.x, ta.y, ta.z, ta.w};
        const float tbv[4] = {tb.x, tb.y, tb.z, tb.w};
#pragma unroll
        for (int f = 0; f < 4; f++) {
            float4 qa = q4[(4 * j4 + f) * 2], qb = q4[(4 * j4 + f) * 2 + 1];
            float4 ka = k4[(4 * j4 + f) * 2], kb = k4[(4 * j4 + f) * 2 + 1];
            const float fa = tav[f], fb = tbv[f];
            aq0[0] += fa * qa.x; aq0[1] += fa * qa.y; aq0[2] += fa * qa.z; aq0[3] += fa * qa.w;
            aq0[4] += fa * qb.x; aq0[5] += fa * qb.y; aq0[6] += fa * qb.z; aq0[7] += fa * qb.w;
            aq1[0] += fb * qa.x; aq1[1] += fb * qa.y; aq1[2] += fb * qa.z; aq1[3] += fb * qa.w;
            aq1[4] += fb * qb.x; aq1[5] += fb * qb.y; aq1[6] += fb * qb.z; aq1[7] += fb * qb.w;
            ak0[0] += fa * ka.x; ak0[1] += fa * ka.y; ak0[2] += fa * ka.z; ak0[3] += fa * ka.w;
            ak0[4] += fa * kb.x; ak0[5] += fa * kb.y; ak0[6] += fa * kb.z; ak0[7] += fa * kb.w;
            ak1[0] += fb * ka.x; ak1[1] += fb * ka.y; ak1[2] += fb * ka.z; ak1[3] += fb * ka.w;
            ak1[4] += fb * kb.x; ak1[5] += fb * kb.y; ak1[6] += fb * kb.z; ak1[7] += fb * kb.w;
        }
    }
#pragma unroll
    for (int h = 0; h < NH; h++) {
#pragma unroll
        for (int o = 16; o; o >>= 1) {
            aq0[h] += __shfl_xor_sync(0xffffffffu, aq0[h], o);
            aq1[h] += __shfl_xor_sync(0xffffffffu, aq1[h], o);
            ak0[h] += __shfl_xor_sync(0xffffffffu, ak0[h], o);
            ak1[h] += __shfl_xor_sync(0xffffffffu, ak1[h], o);
        }
    }
    if (lane == 0) {
        float* q0 = g_qn + (size_t)(2 * wp) * NH;
        float* k0 = g_kn + (size_t)(2 * wp) * NH;
#pragma unroll
        for (int h = 0; h < NH; h++) {
            q0[h]      = aq0[h];
            q0[NH + h] = aq1[h];
            k0[h]      = ak0[h];
            k0[NH + h] = ak1[h];
        }
    }
}

// ---------------- fused softmax + aggregation: warp per destination ----------
// Phase A: online (m,s) per head, lanes = (edge chunk 0..3) x (head 0..7).
// Phase B: sequential edges; lanes cover 512 features via 4 x float4; acc in regs.
__global__ __launch_bounds__(256)
void fagg_kernel(const float* __restrict__ b, float* __restrict__ out, int concat) {
    const int d = (blockIdx.x * blockDim.x + threadIdx.x) >> 5;
    if (d >= NN) return;
    const int lane = threadIdx.x & 31;
    const int h = lane & 7;
    const int roff = g_rowptr[d];
    const int deg  = g_rowptr[d + 1] - roff;
    const float ceh = g_ce[h];

    // ---- phase A: per-head online softmax stats ----
    float m = -1e30f, s = 0.f;
    for (int base = 0; base < deg; base += 4) {
        const int e = base + (lane >> 3);
        if (e < deg) {
            const int   sr = g_csr_sr[roff + e];
            const float at = g_csr_attr[roff + e];
            const int src = sr & 0xFFFFF, r = sr >> 20;
            float l = g_qn[((size_t)r * NN + d) * NH + h]
                    + g_kn[((size_t)r * NN + src) * NH + h] + at * ceh;
            l = (l >= 0.f) ? l : 0.2f * l;
            const float mn = fmaxf(m, l);
            s = s * __expf(m - mn) + __expf(l - mn);
            m = mn;
        }
    }
#pragma unroll
    for (int off = 8; off < 32; off <<= 1) {
        const float om = __shfl_xor_sync(0xffffffffu, m, off);
        const float os = __shfl_xor_sync(0xffffffffu, s, off);
        const float mn = fmaxf(m, om);
        s = s * __expf(m - mn) + os * __expf(om - mn);
        m = mn;
    }
    const float sinv = 1.f / (s + 1e-16f);

    // ---- phase B: weighted aggregation ----
    float4 a0 = make_float4(0, 0, 0, 0), a1 = a0, a2 = a0, a3 = a0;
    const int hw0 = lane >> 4;   // head of j=0 elements; j adds 2
    const float qv_d = 0.f; (void)qv_d;
    for (int e = 0; e < deg; e++) {
        const int   sr = g_csr_sr[roff + e];
        const float at = g_csr_attr[roff + e];
        const int src = sr & 0xFFFFF, r = sr >> 20;
        float l = g_qn[((size_t)r * NN + d) * NH + h]
                + g_kn[((size_t)r * NN + src) * NH + h] + at * ceh;
        l = (l >= 0.f) ? l : 0.2f * l;
        const float w = __expf(l - m) * sinv;
        const float w0 = __shfl_sync(0xffffffffu, w, hw0);
        const float w1 = __shfl_sync(0xffffffffu, w, hw0 + 2);
        const float w2 = __shfl_sync(0xffffffffu, w, hw0 + 4);
        const float w3 = __shfl_sync(0xffffffffu, w, hw0 + 6);
        const float4* t4 = (const float4*)(g_t + ((size_t)r * NN + src) * HID);
        const float4 t0 = t4[lane], t1 = t4[lane + 32], t2 = t4[lane + 64], t3 = t4[lane + 96];
        a0.x += w0 * t0.x; a0.y += w0 * t0.y; a0.z += w0 * t0.z; a0.w += w0 * t0.w;
        a1.x += w1 * t1.x; a1.y += w1 * t1.y; a1.z += w1 * t1.z; a1.w += w1 * t1.w;
        a2.x += w2 * t2.x; a2.y += w2 * t2.y; a2.z += w2 * t2.z; a2.w += w2 * t2.w;
        a3.x += w3 * t3.x; a3.y += w3 * t3.y; a3.z += w3 * t3.z; a3.w += w3 * t3.w;
    }

    if (concat) {
        const float4* b4 = (const float4*)b;
        float4* o4 = (float4*)(g_h + (size_t)d * HID);
        float4 v;
        v = b4[lane];      o4[lane]      = make_float4(a0.x + v.x, a0.y + v.y, a0.z + v.z, a0.w + v.w);
        v = b4[lane + 32]; o4[lane + 32] = make_float4(a1.x + v.x, a1.y + v.y, a1.z + v.z, a1.w + v.w);
        v = b4[lane + 64]; o4[lane + 64] = make_float4(a2.x + v.x, a2.y + v.y, a2.z + v.z, a2.w + v.w);
        v = b4[lane + 96]; o4[lane + 96] = make_float4(a3.x + v.x, a3.y + v.y, a3.z + v.z, a3.w + v.w);
    } else {
        // mean over heads: sum j (heads hw0, hw0+2, hw0+4, hw0+6), then add lane^16
        float4 s1 = make_float4(a0.x + a1.x + a2.x + a3.x,
                                a0.y + a1.y + a2.y + a3.y,
                                a0.z + a1.z + a2.z + a3.z,
                                a0.w + a1.w + a2.w + a3.w);
        s1.x += __shfl_xor_sync(0xffffffffu, s1.x, 16);
        s1.y += __shfl_xor_sync(0xffffffffu, s1.y, 16);
        s1.z += __shfl_xor_sync(0xffffffffu, s1.z, 16);
        s1.w += __shfl_xor_sync(0xffffffffu, s1.w, 16);
        if (lane < 16) {
            const float4 bv = ((const float4*)b)[lane];
            ((float4*)(out + (size_t)d * OC))[lane] =
                make_float4(s1.x * 0.125f + bv.x, s1.y * 0.125f + bv.y,
                            s1.z * 0.125f + bv.z, s1.w * 0.125f + bv.w);
        }
    }
}

// ---------------- host driver ------------------------------------------------
extern "C" void kernel_launch(void* const* d_in, const int* in_sizes, int n_in,
                              void* d_out, int out_size) {
    const float* x   = (const float*)d_in[0];
    const int*   ei  = (const int*)  d_in[1];
    const int*   ety = (const int*)  d_in[2];
    const float* ea  = (const float*)d_in[3];
    const float* W1  = (const float*)d_in[4];
    const float* q1  = (const float*)d_in[5];
    const float* k1  = (const float*)d_in[6];
    const float* We1 = (const float*)d_in[7];
    const float* e1  = (const float*)d_in[8];
    const float* b1  = (const float*)d_in[9];
    const float* W2  = (const float*)d_in[10];
    const float* q2  = (const float*)d_in[11];
    const float* k2  = (const float*)d_in[12];
    const float* We2 = (const float*)d_in[13];
    const float* e2  = (const float*)d_in[14];
    const float* b2  = (const float*)d_in[15];

    const int E0   = in_sizes[2];
    const int Etot = E0 + NN;

    const dim3 gg(4 * RR, NN / 128);
    const int  eB   = (Etot + 255) / 256;
    const int  fagB = (NN * 32) / 256;

    // CSR build (launches 1-5; GEMM is launch 6 for the ncu -s 5 window)
    init_kernel<<<(NN + 255) / 256, 256>>>();
    etmax_kernel<<<256, 256>>>(ety, E0);
    hist_kernel<<<eB, 256>>>(ei, E0, Etot);
    scan_kernel<<<1, 1024>>>();
    scatter_kernel<<<eB, 256>>>(ei, ety, ea, E0, Etot);

    // ---------------- layer 1 (concat) ----------------
    gemm_l1_kernel<<<gg, 256>>>(x, W1);
    ce_kernel<<<1, 256>>>(We1, e1);
    qk_kernel<<<(RR * NN / 2 + 7) / 8, 256>>>(q1, k1);
    fagg_kernel<<<fagB, 256>>>(b1, nullptr, 1);

    // ---------------- layer 2 (mean) ------------------
    gemm_l2_kernel<<<gg, 256>>>(W2);
    ce_kernel<<<1, 256>>>(We2, e2);
    qk_kernel<<<(RR * NN / 2 + 7) / 8, 256>>>(q2, k2);
    fagg_kernel<<<fagB, 256>>>(b2, (float*)d_out, 0);
}

// round 5
// speedup vs baseline: 3.0315x; 1.4877x over previous
#include <cuda_runtime.h>
#include <cstdint>

// Problem dimensions (fixed by the dataset)
#define NN   16000          // nodes
#define F1   256            // layer-1 input features
#define HID  512            // HEADS*OUT
#define NH   8              // heads
#define OC   64             // per-head out channels
#define RR   8              // relations
#define ECAP 300000         // capacity for edges + self loops

// ---------------- scratch (device globals; no allocation allowed) ----------
__device__ float    g_t[(size_t)RR * NN * HID];   // relation-transformed nodes [R,N,512]
__device__ float    g_h[(size_t)NN * HID];        // layer-1 output
__device__ float    g_qk[(size_t)NN * 128];       // [node][r*16 + (q:0-7 | k:8-15)]
__device__ float    g_wqk[(size_t)HID * 128];     // folded W@q / W@k weights
__device__ float    g_ce[NH];                     // (We @ e)[h]
__device__ int      g_etmax;
__device__ int      g_hist[NN];
__device__ int      g_rowptr[NN + 1];
__device__ int      g_cursor[NN];
__device__ int      g_csr_sr[ECAP];               // src | (rel << 20)
__device__ float    g_csr_attr[ECAP];

// ---------------- helpers ---------------------------------------------------
__device__ __forceinline__ uint32_t f2tf(float f) {
    uint32_t u;
    asm("cvt.rna.tf32.f32 %0, %1;" : "=r"(u) : "f"(f));
    return u;
}
__device__ __forceinline__ void mma_tf32(float c[4], const uint32_t a[4], const uint32_t b[2]) {
    asm volatile("mma.sync.aligned.m16n8k8.row.col.f32.tf32.tf32.f32 "
                 "{%0,%1,%2,%3}, {%4,%5,%6,%7}, {%8,%9}, {%0,%1,%2,%3};"
                 : "+f"(c[0]), "+f"(c[1]), "+f"(c[2]), "+f"(c[3])
                 : "r"(a[0]), "r"(a[1]), "r"(a[2]), "r"(a[3]), "r"(b[0]), "r"(b[1]));
}

// ---------------- CSR build --------------------------------------------------
__global__ void init_kernel() {
    int i = blockIdx.x * blockDim.x + threadIdx.x;
    if (i < NN) g_hist[i] = 0;
    if (i == 0) g_etmax = 0;
}

__global__ void etmax_kernel(const int* __restrict__ et, int E0) {
    int i = blockIdx.x * blockDim.x + threadIdx.x;
    int loc = -1;
    for (; i < E0; i += gridDim.x * blockDim.x) loc = max(loc, et[i]);
    if (loc >= 0) atomicMax(&g_etmax, loc);
}

__global__ void hist_kernel(const int* __restrict__ ei, int E0, int Etot) {
    int e = blockIdx.x * blockDim.x + threadIdx.x;
    if (e >= Etot) return;
    int d = (e < E0) ? ei[E0 + e] : (e - E0);
    atomicAdd(&g_hist[d], 1);
}

__global__ __launch_bounds__(1024)
void scan_kernel() {
    __shared__ int sm[1024];
    const int t = threadIdx.x;
    const int base = t * 16;
    int loc[16];
    int sum = 0;
#pragma unroll
    for (int i = 0; i < 16; i++) {
        int idx = base + i;
        int v = (idx < NN) ? g_hist[idx] : 0;
        loc[i] = sum;
        sum += v;
    }
    sm[t] = sum;
    __syncthreads();
    for (int off = 1; off < 1024; off <<= 1) {
        int v = (t >= off) ? sm[t - off] : 0;
        __syncthreads();
        sm[t] += v;
        __syncthreads();
    }
    int pre = (t > 0) ? sm[t - 1] : 0;
#pragma unroll
    for (int i = 0; i < 16; i++) {
        int idx = base + i;
        if (idx < NN) {
            g_rowptr[idx] = pre + loc[i];
            g_cursor[idx] = pre + loc[i];
        }
    }
    if (t == 1023) g_rowptr[NN] = sm[1023];
}

__global__ void scatter_kernel(const int* __restrict__ ei, const int* __restrict__ etyp,
                               const float* __restrict__ ea, int E0, int Etot) {
    int e = blockIdx.x * blockDim.x + threadIdx.x;
    if (e >= Etot) return;
    int s, d, r;  float at;
    if (e < E0) { s = ei[e]; d = ei[E0 + e]; r = etyp[e]; at = ea[e]; }
    else        { s = d = e - E0; r = (g_etmax + 1) & (RR - 1); at = 0.5f; }
    int p = atomicAdd(&g_cursor[d], 1);
    g_csr_sr[p]   = s | (r << 20);
    g_csr_attr[p] = at;
}

// ---------------- tf32 tensor-core GEMM (ldb/ldc parameterized) --------------
__device__ __forceinline__ void gemm_tf32_body(
    const float* __restrict__ A, const float* __restrict__ B,
    float* __restrict__ C, int K, int m0, int n0, int ldb, int ldc)
{
    __shared__ uint32_t As[2][16][132];
    __shared__ uint32_t Bs[2][16][132];

    const int tid  = threadIdx.x;
    const int lane = tid & 31, warp = tid >> 5;
    const int grp  = lane >> 2, tig = lane & 3;
    const int wm   = (warp & 3) * 32;
    const int wn   = (warp >> 2) * 64;

    const int am  = tid & 127;
    const int akq0 = tid >> 7;
    const int akq1 = akq0 + 2;
    const int bn4 = tid & 31;
    const int bk0 = tid >> 5;
    const int bk1 = bk0 + 8;

    const float* Ag0 = A + (size_t)(m0 + am) * K + 4 * akq0;
    const float* Ag1 = A + (size_t)(m0 + am) * K + 4 * akq1;
    const float* Bg0 = B + (size_t)bk0 * ldb + n0 + 4 * bn4;
    const float* Bg1 = B + (size_t)bk1 * ldb + n0 + 4 * bn4;

    float c[2][8][4];
#pragma unroll
    for (int mt = 0; mt < 2; mt++)
#pragma unroll
        for (int nt = 0; nt < 8; nt++)
#pragma unroll
            for (int i = 0; i < 4; i++) c[mt][nt][i] = 0.f;

    float4 a0v = *(const float4*)Ag0;
    float4 a1v = *(const float4*)Ag1;
    float4 b0v = *(const float4*)Bg0;
    float4 b1v = *(const float4*)Bg1;
    As[0][4 * akq0 + 0][am] = f2tf(a0v.x); As[0][4 * akq0 + 1][am] = f2tf(a0v.y);
    As[0][4 * akq0 + 2][am] = f2tf(a0v.z); As[0][4 * akq0 + 3][am] = f2tf(a0v.w);
    As[0][4 * akq1 + 0][am] = f2tf(a1v.x); As[0][4 * akq1 + 1][am] = f2tf(a1v.y);
    As[0][4 * akq1 + 2][am] = f2tf(a1v.z); As[0][4 * akq1 + 3][am] = f2tf(a1v.w);
    *(uint4*)&Bs[0][bk0][4 * bn4] = make_uint4(f2tf(b0v.x), f2tf(b0v.y), f2tf(b0v.z), f2tf(b0v.w));
    *(uint4*)&Bs[0][bk1][4 * bn4] = make_uint4(f2tf(b1v.x), f2tf(b1v.y), f2tf(b1v.z), f2tf(b1v.w));
    __syncthreads();

    int buf = 0;
    const int NSTEP = K >> 4;
    for (int s = 0; s < NSTEP; s++) {
        const bool nxt = (s + 1) < NSTEP;
        if (nxt) {
            const int ko = (s + 1) << 4;
            a0v = *(const float4*)(Ag0 + ko);
            a1v = *(const float4*)(Ag1 + ko);
            b0v = *(const float4*)(Bg0 + (size_t)ko * ldb);
            b1v = *(const float4*)(Bg1 + (size_t)ko * ldb);
        }
#pragma unroll
        for (int kb = 0; kb < 16; kb += 8) {
            uint32_t af[2][4], bf[8][2];
#pragma unroll
            for (int mt = 0; mt < 2; mt++) {
                const int mc = wm + mt * 16 + grp;
                af[mt][0] = As[buf][kb + tig][mc];
                af[mt][1] = As[buf][kb + tig][mc + 8];
                af[mt][2] = As[buf][kb + tig + 4][mc];
                af[mt][3] = As[buf][kb + tig + 4][mc + 8];
            }
#pragma unroll
            for (int nt = 0; nt < 8; nt++) {
                const int nc = wn + nt * 8 + grp;
                bf[nt][0] = Bs[buf][kb + tig][nc];
                bf[nt][1] = Bs[buf][kb + tig + 4][nc];
            }
#pragma unroll
            for (int mt = 0; mt < 2; mt++)
#pragma unroll
                for (int nt = 0; nt < 8; nt++)
                    mma_tf32(c[mt][nt], af[mt], bf[nt]);
        }
        if (nxt) {
            const int nb = buf ^ 1;
            As[nb][4 * akq0 + 0][am] = f2tf(a0v.x); As[nb][4 * akq0 + 1][am] = f2tf(a0v.y);
            As[nb][4 * akq0 + 2][am] = f2tf(a0v.z); As[nb][4 * akq0 + 3][am] = f2tf(a0v.w);
            As[nb][4 * akq1 + 0][am] = f2tf(a1v.x); As[nb][4 * akq1 + 1][am] = f2tf(a1v.y);
            As[nb][4 * akq1 + 2][am] = f2tf(a1v.z); As[nb][4 * akq1 + 3][am] = f2tf(a1v.w);
            *(uint4*)&Bs[nb][bk0][4 * bn4] = make_uint4(f2tf(b0v.x), f2tf(b0v.y), f2tf(b0v.z), f2tf(b0v.w));
            *(uint4*)&Bs[nb][bk1][4 * bn4] = make_uint4(f2tf(b1v.x), f2tf(b1v.y), f2tf(b1v.z), f2tf(b1v.w));
            __syncthreads();
            buf = nb;
        }
    }

#pragma unroll
    for (int mt = 0; mt < 2; mt++) {
        const int row = m0 + wm + mt * 16 + grp;
#pragma unroll
        for (int nt = 0; nt < 8; nt++) {
            const int col = n0 + wn + nt * 8 + tig * 2;
            *(float2*)(C + (size_t)row * ldc + col)       = make_float2(c[mt][nt][0], c[mt][nt][1]);
            *(float2*)(C + (size_t)(row + 8) * ldc + col) = make_float2(c[mt][nt][2], c[mt][nt][3]);
        }
    }
}

__global__ __launch_bounds__(256, 2)
void gemm_l1_kernel(const float* __restrict__ A, const float* __restrict__ B0) {
    const int nb = blockIdx.x & 3, r = blockIdx.x >> 2;
    gemm_tf32_body(A, B0 + (size_t)r * F1 * HID,
                   g_t + (size_t)r * NN * HID, F1,
                   blockIdx.y * 128, nb * 128, 512, 512);
}
__global__ __launch_bounds__(256, 2)
void gemm_l2_kernel(const float* __restrict__ B0) {
    const int nb = blockIdx.x & 3, r = blockIdx.x >> 2;
    gemm_tf32_body(g_h, B0 + (size_t)r * HID * HID,
                   g_t + (size_t)r * NN * HID, HID,
                   blockIdx.y * 128, nb * 128, 512, 512);
}
// q/k projection GEMM: [NN x K] @ [K x 128] -> g_qk [NN x 128]
__global__ __launch_bounds__(256, 2)
void qkgemm_l1_kernel(const float* __restrict__ A, int K) {
    gemm_tf32_body(A, g_wqk, g_qk, K, blockIdx.y * 128, 0, 128, 128);
}
__global__ __launch_bounds__(256, 2)
void qkgemm_l2_kernel(int K) {
    gemm_tf32_body(g_h, g_wqk, g_qk, K, blockIdx.y * 128, 0, 128, 128);
}

// ---------------- fold weights: g_wqk[j][r*16+h]=W[r]@q, +8: W[r]@k ----------
__global__ __launch_bounds__(256)
void packqk_kernel(const float* __restrict__ W, const float* __restrict__ q,
                   const float* __restrict__ k, int K) {
    const int gw = (blockIdx.x * blockDim.x + threadIdx.x) >> 5;
    if (gw >= RR * K) return;
    const int r = gw / K, j = gw - r * K;
    const int lane = threadIdx.x & 31;
    const float4* w4 = (const float4*)(W + ((size_t)r * K + j) * HID);
    const float4* q4 = (const float4*)q;
    const float4* k4 = (const float4*)k;
    float aq[NH], ak[NH];
#pragma unroll
    for (int h = 0; h < NH; h++) { aq[h] = 0.f; ak[h] = 0.f; }
#pragma unroll
    for (int i = 0; i < 4; i++) {
        const int c4 = lane + 32 * i;
        const float4 wv = w4[c4];
        const float wa[4] = {wv.x, wv.y, wv.z, wv.w};
#pragma unroll
        for (int f = 0; f < 4; f++) {
            const int c = 4 * c4 + f;
            const float4 qa = q4[c * 2], qb = q4[c * 2 + 1];
            const float4 ka = k4[c * 2], kb = k4[c * 2 + 1];
            const float w = wa[f];
            aq[0] += w * qa.x; aq[1] += w * qa.y; aq[2] += w * qa.z; aq[3] += w * qa.w;
            aq[4] += w * qb.x; aq[5] += w * qb.y; aq[6] += w * qb.z; aq[7] += w * qb.w;
            ak[0] += w * ka.x; ak[1] += w * ka.y; ak[2] += w * ka.z; ak[3] += w * ka.w;
            ak[4] += w * kb.x; ak[5] += w * kb.y; ak[6] += w * kb.z; ak[7] += w * kb.w;
        }
    }
#pragma unroll
    for (int h = 0; h < NH; h++) {
#pragma unroll
        for (int o = 16; o; o >>= 1) {
            aq[h] += __shfl_xor_sync(0xffffffffu, aq[h], o);
            ak[h] += __shfl_xor_sync(0xffffffffu, ak[h], o);
        }
    }
    if (lane == 0) {
        float* dst = g_wqk + (size_t)j * 128 + r * 16;
#pragma unroll
        for (int h = 0; h < NH; h++) {
            dst[h]      = aq[h];
            dst[8 + h]  = ak[h];
        }
    }
}

// ---------------- ce[h] = sum_j We[j] * e[j][h] (warp per head) --------------
__global__ void ce_kernel(const float* __restrict__ We, const float* __restrict__ e) {
    const int warp = threadIdx.x >> 5, lane = threadIdx.x & 31;
    float s = 0.f;
    for (int j = lane; j < HID; j += 32) s += We[j] * e[j * NH + warp];
#pragma unroll
    for (int o = 16; o; o >>= 1) s += __shfl_xor_sync(0xffffffffu, s, o);
    if (lane == 0) g_ce[warp] = s;
}

// ---------------- fused softmax + aggregation: warp per destination ----------
__global__ __launch_bounds__(256)
void fagg_kernel(const float* __restrict__ b, float* __restrict__ out, int concat) {
    const int d = (blockIdx.x * blockDim.x + threadIdx.x) >> 5;
    if (d >= NN) return;
    const int lane = threadIdx.x & 31;
    const int h = lane & 7;
    const int roff = g_rowptr[d];
    const int deg  = g_rowptr[d + 1] - roff;
    const float ceh = g_ce[h];
    const float* qrow = g_qk + (size_t)d * 128;

    // ---- phase A: per-head online softmax stats ----
    float m = -1e30f, s = 0.f;
    for (int base = 0; base < deg; base += 4) {
        const int e = base + (lane >> 3);
        if (e < deg) {
            const int   sr = g_csr_sr[roff + e];
            const float at = g_csr_attr[roff + e];
            const int src = sr & 0xFFFFF, r = sr >> 20;
            float l = qrow[r * 16 + h]
                    + g_qk[(size_t)src * 128 + r * 16 + 8 + h] + at * ceh;
            l = (l >= 0.f) ? l : 0.2f * l;
            const float mn = fmaxf(m, l);
            s = s * __expf(m - mn) + __expf(l - mn);
            m = mn;
        }
    }
#pragma unroll
    for (int off = 8; off < 32; off <<= 1) {
        const float om = __shfl_xor_sync(0xffffffffu, m, off);
        const float os = __shfl_xor_sync(0xffffffffu, s, off);
        const float mn = fmaxf(m, om);
        s = s * __expf(m - mn) + os * __expf(om - mn);
        m = mn;
    }
    const float sinv = 1.f / (s + 1e-16f);

    // ---- phase B: weighted aggregation ----
    float4 a0 = make_float4(0, 0, 0, 0), a1 = a0, a2 = a0, a3 = a0;
    const int hw0 = lane >> 4;
    for (int e = 0; e < deg; e++) {
        const int   sr = g_csr_sr[roff + e];
        const float at = g_csr_attr[roff + e];
        const int src = sr & 0xFFFFF, r = sr >> 20;
        float l = qrow[r * 16 + h]
                + g_qk[(size_t)src * 128 + r * 16 + 8 + h] + at * ceh;
        l = (l >= 0.f) ? l : 0.2f * l;
        const float w = __expf(l - m) * sinv;
        const float w0 = __shfl_sync(0xffffffffu, w, hw0);
        const float w1 = __shfl_sync(0xffffffffu, w, hw0 + 2);
        const float w2 = __shfl_sync(0xffffffffu, w, hw0 + 4);
        const float w3 = __shfl_sync(0xffffffffu, w, hw0 + 6);
        const float4* t4 = (const float4*)(g_t + ((size_t)r * NN + src) * HID);
        const float4 t0 = t4[lane], t1 = t4[lane + 32], t2 = t4[lane + 64], t3 = t4[lane + 96];
        a0.x += w0 * t0.x; a0.y += w0 * t0.y; a0.z += w0 * t0.z; a0.w += w0 * t0.w;
        a1.x += w1 * t1.x; a1.y += w1 * t1.y; a1.z += w1 * t1.z; a1.w += w1 * t1.w;
        a2.x += w2 * t2.x; a2.y += w2 * t2.y; a2.z += w2 * t2.z; a2.w += w2 * t2.w;
        a3.x += w3 * t3.x; a3.y += w3 * t3.y; a3.z += w3 * t3.z; a3.w += w3 * t3.w;
    }

    if (concat) {
        const float4* b4 = (const float4*)b;
        float4* o4 = (float4*)(g_h + (size_t)d * HID);
        float4 v;
        v = b4[lane];      o4[lane]      = make_float4(a0.x + v.x, a0.y + v.y, a0.z + v.z, a0.w + v.w);
        v = b4[lane + 32]; o4[lane + 32] = make_float4(a1.x + v.x, a1.y + v.y, a1.z + v.z, a1.w + v.w);
        v = b4[lane + 64]; o4[lane + 64] = make_float4(a2.x + v.x, a2.y + v.y, a2.z + v.z, a2.w + v.w);
        v = b4[lane + 96]; o4[lane + 96] = make_float4(a3.x + v.x, a3.y + v.y, a3.z + v.z, a3.w + v.w);
    } else {
        float4 s1 = make_float4(a0.x + a1.x + a2.x + a3.x,
                                a0.y + a1.y + a2.y + a3.y,
                                a0.z + a1.z + a2.z + a3.z,
                                a0.w + a1.w + a2.w + a3.w);
        s1.x += __shfl_xor_sync(0xffffffffu, s1.x, 16);
        s1.y += __shfl_xor_sync(0xffffffffu, s1.y, 16);
        s1.z += __shfl_xor_sync(0xffffffffu, s1.z, 16);
        s1.w += __shfl_xor_sync(0xffffffffu, s1.w, 16);
        if (lane < 16) {
            const float4 bv = ((const float4*)b)[lane];
            ((float4*)(out + (size_t)d * OC))[lane] =
                make_float4(s1.x * 0.125f + bv.x, s1.y * 0.125f + bv.y,
                            s1.z * 0.125f + bv.z, s1.w * 0.125f + bv.w);
        }
    }
}

// ---------------- host driver ------------------------------------------------
extern "C" void kernel_launch(void* const* d_in, const int* in_sizes, int n_in,
                              void* d_out, int out_size) {
    const float* x   = (const float*)d_in[0];
    const int*   ei  = (const int*)  d_in[1];
    const int*   ety = (const int*)  d_in[2];
    const float* ea  = (const float*)d_in[3];
    const float* W1  = (const float*)d_in[4];
    const float* q1  = (const float*)d_in[5];
    const float* k1  = (const float*)d_in[6];
    const float* We1 = (const float*)d_in[7];
    const float* e1  = (const float*)d_in[8];
    const float* b1  = (const float*)d_in[9];
    const float* W2  = (const float*)d_in[10];
    const float* q2  = (const float*)d_in[11];
    const float* k2  = (const float*)d_in[12];
    const float* We2 = (const float*)d_in[13];
    const float* e2  = (const float*)d_in[14];
    const float* b2  = (const float*)d_in[15];

    const int E0   = in_sizes[2];
    const int Etot = E0 + NN;

    const dim3 gg(4 * RR, NN / 128);
    const dim3 gq(1, NN / 128);
    const int  eB   = (Etot + 255) / 256;
    const int  fagB = (NN * 32) / 256;

    init_kernel<<<(NN + 255) / 256, 256>>>();
    etmax_kernel<<<256, 256>>>(ety, E0);
    hist_kernel<<<eB, 256>>>(ei, E0, Etot);

    // ---------------- layer 1 (concat) ----------------
    gemm_l1_kernel<<<gg, 256>>>(x, W1);
    scan_kernel<<<1, 1024>>>();
    scatter_kernel<<<eB, 256>>>(ei, ety, ea, E0, Etot);
    packqk_kernel<<<RR * F1 / 8, 256>>>(W1, q1, k1, F1);
    ce_kernel<<<1, 256>>>(We1, e1);
    qkgemm_l1_kernel<<<gq, 256>>>(x, F1);
    fagg_kernel<<<fagB, 256>>>(b1, nullptr, 1);

    // ---------------- layer 2 (mean) ------------------
    gemm_l2_kernel<<<gg, 256>>>(W2);
    packqk_kernel<<<RR * HID / 8, 256>>>(W2, q2, k2, HID);
    ce_kernel<<<1, 256>>>(We2, e2);
    qkgemm_l2_kernel<<<gq, 256>>>(HID);
    fagg_kernel<<<fagB, 256>>>(b2, (float*)d_out, 0);
}

// round 6
// speedup vs baseline: 3.6746x; 1.2121x over previous
#include <cuda_runtime.h>
#include <cstdint>

// Problem dimensions (fixed by the dataset)
#define NN   16000          // nodes
#define F1   256            // layer-1 input features
#define HID  512            // HEADS*OUT
#define NH   8              // heads
#define OC   64             // per-head out channels
#define RR   8              // relations
#define ECAP 300000         // capacity for edges + self loops

// ---------------- scratch (device globals; no allocation allowed) ----------
__device__ float    g_t[(size_t)RR * NN * HID];   // relation-transformed nodes [R,N,512]
__device__ float    g_h[(size_t)NN * HID];        // layer-1 output
__device__ float    g_qk[(size_t)NN * 128];       // [node][r*16 + (q:0-7 | k:8-15)]
__device__ float    g_wqk[(size_t)HID * 128];     // folded W@q / W@k weights
__device__ float    g_ce[NH];                     // (We @ e)[h]
__device__ int      g_etmax;
__device__ int      g_hist[NN];
__device__ int      g_rowptr[NN + 1];
__device__ int      g_cursor[NN];
__device__ int      g_csr_sr[ECAP];               // src | (rel << 20)
__device__ float    g_csr_attr[ECAP];

// ---------------- helpers ---------------------------------------------------
__device__ __forceinline__ uint32_t f2tf(float f) {
    uint32_t u;
    asm("cvt.rna.tf32.f32 %0, %1;" : "=r"(u) : "f"(f));
    return u;
}
__device__ __forceinline__ void mma_tf32(float c[4], const uint32_t a[4], const uint32_t b[2]) {
    asm volatile("mma.sync.aligned.m16n8k8.row.col.f32.tf32.tf32.f32 "
                 "{%0,%1,%2,%3}, {%4,%5,%6,%7}, {%8,%9}, {%0,%1,%2,%3};"
                 : "+f"(c[0]), "+f"(c[1]), "+f"(c[2]), "+f"(c[3])
                 : "r"(a[0]), "r"(a[1]), "r"(a[2]), "r"(a[3]), "r"(b[0]), "r"(b[1]));
}

// ---------------- CSR build --------------------------------------------------
__global__ void init_kernel() {
    int i = blockIdx.x * blockDim.x + threadIdx.x;
    if (i < NN) g_hist[i] = 0;
    if (i == 0) g_etmax = 0;
}

__global__ void etmax_kernel(const int* __restrict__ et, int E0) {
    int i = blockIdx.x * blockDim.x + threadIdx.x;
    int loc = -1;
    for (; i < E0; i += gridDim.x * blockDim.x) loc = max(loc, et[i]);
    if (loc >= 0) atomicMax(&g_etmax, loc);
}

__global__ void hist_kernel(const int* __restrict__ ei, int E0, int Etot) {
    int e = blockIdx.x * blockDim.x + threadIdx.x;
    if (e >= Etot) return;
    int d = (e < E0) ? ei[E0 + e] : (e - E0);
    atomicAdd(&g_hist[d], 1);
}

__global__ __launch_bounds__(1024)
void scan_kernel() {
    __shared__ int sm[1024];
    const int t = threadIdx.x;
    const int base = t * 16;
    int loc[16];
    int sum = 0;
#pragma unroll
    for (int i = 0; i < 16; i++) {
        int idx = base + i;
        int v = (idx < NN) ? g_hist[idx] : 0;
        loc[i] = sum;
        sum += v;
    }
    sm[t] = sum;
    __syncthreads();
    for (int off = 1; off < 1024; off <<= 1) {
        int v = (t >= off) ? sm[t - off] : 0;
        __syncthreads();
        sm[t] += v;
        __syncthreads();
    }
    int pre = (t > 0) ? sm[t - 1] : 0;
#pragma unroll
    for (int i = 0; i < 16; i++) {
        int idx = base + i;
        if (idx < NN) {
            g_rowptr[idx] = pre + loc[i];
            g_cursor[idx] = pre + loc[i];
        }
    }
    if (t == 1023) g_rowptr[NN] = sm[1023];
}

__global__ void scatter_kernel(const int* __restrict__ ei, const int* __restrict__ etyp,
                               const float* __restrict__ ea, int E0, int Etot) {
    int e = blockIdx.x * blockDim.x + threadIdx.x;
    if (e >= Etot) return;
    int s, d, r;  float at;
    if (e < E0) { s = ei[e]; d = ei[E0 + e]; r = etyp[e]; at = ea[e]; }
    else        { s = d = e - E0; r = (g_etmax + 1) & (RR - 1); at = 0.5f; }
    int p = atomicAdd(&g_cursor[d], 1);
    g_csr_sr[p]   = s | (r << 20);
    g_csr_attr[p] = at;
}

// ---------------- tf32 tensor-core GEMM (conflict-free SMEM) -----------------
// As: [k][m-interleaved], stride 136 (== 8 mod 32). m mapped so the fragment
// pair (m, m+8) is adjacent -> one 64-bit LDS, both phases tile all 32 banks.
// Bs: [k][n], stride 136 -> scalar fragment loads hit banks 8*tig+grp (all 32).
__device__ __forceinline__ void gemm_tf32_body(
    const float* __restrict__ A, const float* __restrict__ B,
    float* __restrict__ C, int K, int m0, int n0, int ldb, int ldc)
{
    __shared__ __align__(16) uint32_t As[2][16][136];
    __shared__ __align__(16) uint32_t Bs[2][16][136];

    const int tid  = threadIdx.x;
    const int lane = tid & 31, warp = tid >> 5;
    const int grp  = lane >> 2, tig = lane & 3;
    const int wm   = (warp & 3) * 32;
    const int wn   = (warp >> 2) * 64;

    const int am   = tid & 127;
    const int amp  = (am & 0x70) | ((am & 7) << 1) | ((am >> 3) & 1);
    const int akq0 = tid >> 7;
    const int akq1 = akq0 + 2;
    const int bn4  = tid & 31;
    const int bk0  = tid >> 5;
    const int bk1  = bk0 + 8;

    const float* Ag0 = A + (size_t)(m0 + am) * K + 4 * akq0;
    const float* Ag1 = A + (size_t)(m0 + am) * K + 4 * akq1;
    const float* Bg0 = B + (size_t)bk0 * ldb + n0 + 4 * bn4;
    const float* Bg1 = B + (size_t)bk1 * ldb + n0 + 4 * bn4;

    float c[2][8][4];
#pragma unroll
    for (int mt = 0; mt < 2; mt++)
#pragma unroll
        for (int nt = 0; nt < 8; nt++)
#pragma unroll
            for (int i = 0; i < 4; i++) c[mt][nt][i] = 0.f;

    float4 a0v = *(const float4*)Ag0;
    float4 a1v = *(const float4*)Ag1;
    float4 b0v = *(const float4*)Bg0;
    float4 b1v = *(const float4*)Bg1;
    As[0][4 * akq0 + 0][amp] = f2tf(a0v.x); As[0][4 * akq0 + 1][amp] = f2tf(a0v.y);
    As[0][4 * akq0 + 2][amp] = f2tf(a0v.z); As[0][4 * akq0 + 3][amp] = f2tf(a0v.w);
    As[0][4 * akq1 + 0][amp] = f2tf(a1v.x); As[0][4 * akq1 + 1][amp] = f2tf(a1v.y);
    As[0][4 * akq1 + 2][amp] = f2tf(a1v.z); As[0][4 * akq1 + 3][amp] = f2tf(a1v.w);
    *(uint4*)&Bs[0][bk0][4 * bn4] = make_uint4(f2tf(b0v.x), f2tf(b0v.y), f2tf(b0v.z), f2tf(b0v.w));
    *(uint4*)&Bs[0][bk1][4 * bn4] = make_uint4(f2tf(b1v.x), f2tf(b1v.y), f2tf(b1v.z), f2tf(b1v.w));
    __syncthreads();

    int buf = 0;
    const int NSTEP = K >> 4;
    for (int s = 0; s < NSTEP; s++) {
        const bool nxt = (s + 1) < NSTEP;
        if (nxt) {
            const int ko = (s + 1) << 4;
            a0v = *(const float4*)(Ag0 + ko);
            a1v = *(const float4*)(Ag1 + ko);
            b0v = *(const float4*)(Bg0 + (size_t)ko * ldb);
            b1v = *(const float4*)(Bg1 + (size_t)ko * ldb);
        }
#pragma unroll
        for (int kb = 0; kb < 16; kb += 8) {
            uint32_t af[2][4], bf[8][2];
#pragma unroll
            for (int mt = 0; mt < 2; mt++) {
                const int mcol = wm + mt * 16 + 2 * grp;
                const uint2 p0 = *(const uint2*)&As[buf][kb + tig][mcol];
                const uint2 p1 = *(const uint2*)&As[buf][kb + tig + 4][mcol];
                af[mt][0] = p0.x; af[mt][1] = p0.y;
                af[mt][2] = p1.x; af[mt][3] = p1.y;
            }
#pragma unroll
            for (int nt = 0; nt < 8; nt++) {
                const int nc = wn + nt * 8 + grp;
                bf[nt][0] = Bs[buf][kb + tig][nc];
                bf[nt][1] = Bs[buf][kb + tig + 4][nc];
            }
#pragma unroll
            for (int mt = 0; mt < 2; mt++)
#pragma unroll
                for (int nt = 0; nt < 8; nt++)
                    mma_tf32(c[mt][nt], af[mt], bf[nt]);
        }
        if (nxt) {
            const int nb = buf ^ 1;
            As[nb][4 * akq0 + 0][amp] = f2tf(a0v.x); As[nb][4 * akq0 + 1][amp] = f2tf(a0v.y);
            As[nb][4 * akq0 + 2][amp] = f2tf(a0v.z); As[nb][4 * akq0 + 3][amp] = f2tf(a0v.w);
            As[nb][4 * akq1 + 0][amp] = f2tf(a1v.x); As[nb][4 * akq1 + 1][amp] = f2tf(a1v.y);
            As[nb][4 * akq1 + 2][amp] = f2tf(a1v.z); As[nb][4 * akq1 + 3][amp] = f2tf(a1v.w);
            *(uint4*)&Bs[nb][bk0][4 * bn4] = make_uint4(f2tf(b0v.x), f2tf(b0v.y), f2tf(b0v.z), f2tf(b0v.w));
            *(uint4*)&Bs[nb][bk1][4 * bn4] = make_uint4(f2tf(b1v.x), f2tf(b1v.y), f2tf(b1v.z), f2tf(b1v.w));
            __syncthreads();
            buf = nb;
        }
    }

#pragma unroll
    for (int mt = 0; mt < 2; mt++) {
        const int row = m0 + wm + mt * 16 + grp;
#pragma unroll
        for (int nt = 0; nt < 8; nt++) {
            const int col = n0 + wn + nt * 8 + tig * 2;
            *(float2*)(C + (size_t)row * ldc + col)       = make_float2(c[mt][nt][0], c[mt][nt][1]);
            *(float2*)(C + (size_t)(row + 8) * ldc + col) = make_float2(c[mt][nt][2], c[mt][nt][3]);
        }
    }
}

__global__ __launch_bounds__(256, 2)
void gemm_l1_kernel(const float* __restrict__ A, const float* __restrict__ B0) {
    const int nb = blockIdx.x & 3, r = blockIdx.x >> 2;
    gemm_tf32_body(A, B0 + (size_t)r * F1 * HID,
                   g_t + (size_t)r * NN * HID, F1,
                   blockIdx.y * 128, nb * 128, 512, 512);
}
__global__ __launch_bounds__(256, 2)
void gemm_l2_kernel(const float* __restrict__ B0) {
    const int nb = blockIdx.x & 3, r = blockIdx.x >> 2;
    gemm_tf32_body(g_h, B0 + (size_t)r * HID * HID,
                   g_t + (size_t)r * NN * HID, HID,
                   blockIdx.y * 128, nb * 128, 512, 512);
}
// q/k projection GEMM: [NN x K] @ [K x 128] -> g_qk [NN x 128]
__global__ __launch_bounds__(256, 2)
void qkgemm_l1_kernel(const float* __restrict__ A, int K) {
    gemm_tf32_body(A, g_wqk, g_qk, K, blockIdx.y * 128, 0, 128, 128);
}
__global__ __launch_bounds__(256, 2)
void qkgemm_l2_kernel(int K) {
    gemm_tf32_body(g_h, g_wqk, g_qk, K, blockIdx.y * 128, 0, 128, 128);
}

// ---------------- fold weights: g_wqk[j][r*16+h]=W[r]@q, +8: W[r]@k ----------
__global__ __launch_bounds__(256)
void packqk_kernel(const float* __restrict__ W, const float* __restrict__ q,
                   const float* __restrict__ k, int K) {
    const int gw = (blockIdx.x * blockDim.x + threadIdx.x) >> 5;
    if (gw >= RR * K) return;
    const int r = gw / K, j = gw - r * K;
    const int lane = threadIdx.x & 31;
    const float4* w4 = (const float4*)(W + ((size_t)r * K + j) * HID);
    const float4* q4 = (const float4*)q;
    const float4* k4 = (const float4*)k;
    float aq[NH], ak[NH];
#pragma unroll
    for (int h = 0; h < NH; h++) { aq[h] = 0.f; ak[h] = 0.f; }
#pragma unroll
    for (int i = 0; i < 4; i++) {
        const int c4 = lane + 32 * i;
        const float4 wv = w4[c4];
        const float wa[4] = {wv.x, wv.y, wv.z, wv.w};
#pragma unroll
        for (int f = 0; f < 4; f++) {
            const int c = 4 * c4 + f;
            const float4 qa = q4[c * 2], qb = q4[c * 2 + 1];
            const float4 ka = k4[c * 2], kb = k4[c * 2 + 1];
            const float w = wa[f];
            aq[0] += w * qa.x; aq[1] += w * qa.y; aq[2] += w * qa.z; aq[3] += w * qa.w;
            aq[4] += w * qb.x; aq[5] += w * qb.y; aq[6] += w * qb.z; aq[7] += w * qb.w;
            ak[0] += w * ka.x; ak[1] += w * ka.y; ak[2] += w * ka.z; ak[3] += w * ka.w;
            ak[4] += w * kb.x; ak[5] += w * kb.y; ak[6] += w * kb.z; ak[7] += w * kb.w;
        }
    }
#pragma unroll
    for (int h = 0; h < NH; h++) {
#pragma unroll
        for (int o = 16; o; o >>= 1) {
            aq[h] += __shfl_xor_sync(0xffffffffu, aq[h], o);
            ak[h] += __shfl_xor_sync(0xffffffffu, ak[h], o);
        }
    }
    if (lane == 0) {
        float* dst = g_wqk + (size_t)j * 128 + r * 16;
#pragma unroll
        for (int h = 0; h < NH; h++) {
            dst[h]      = aq[h];
            dst[8 + h]  = ak[h];
        }
    }
}

// ---------------- ce[h] = sum_j We[j] * e[j][h] (warp per head) --------------
__global__ void ce_kernel(const float* __restrict__ We, const float* __restrict__ e) {
    const int warp = threadIdx.x >> 5, lane = threadIdx.x & 31;
    float s = 0.f;
    for (int j = lane; j < HID; j += 32) s += We[j] * e[j * NH + warp];
#pragma unroll
    for (int o = 16; o; o >>= 1) s += __shfl_xor_sync(0xffffffffu, s, o);
    if (lane == 0) g_ce[warp] = s;
}

// ---------------- fused softmax + aggregation: warp per destination ----------
__global__ __launch_bounds__(256)
void fagg_kernel(const float* __restrict__ b, float* __restrict__ out, int concat) {
    const int d = (blockIdx.x * blockDim.x + threadIdx.x) >> 5;
    if (d >= NN) return;
    const int lane = threadIdx.x & 31;
    const int h = lane & 7;
    const int roff = g_rowptr[d];
    const int deg  = g_rowptr[d + 1] - roff;
    const float ceh = g_ce[h];
    const float* qrow = g_qk + (size_t)d * 128;

    // ---- phase A: per-head online softmax stats ----
    float m = -1e30f, s = 0.f;
    for (int base = 0; base < deg; base += 4) {
        const int e = base + (lane >> 3);
        if (e < deg) {
            const int   sr = g_csr_sr[roff + e];
            const float at = g_csr_attr[roff + e];
            const int src = sr & 0xFFFFF, r = sr >> 20;
            float l = qrow[r * 16 + h]
                    + g_qk[(size_t)src * 128 + r * 16 + 8 + h] + at * ceh;
            l = (l >= 0.f) ? l : 0.2f * l;
            const float mn = fmaxf(m, l);
            s = s * __expf(m - mn) + __expf(l - mn);
            m = mn;
        }
    }
#pragma unroll
    for (int off = 8; off < 32; off <<= 1) {
        const float om = __shfl_xor_sync(0xffffffffu, m, off);
        const float os = __shfl_xor_sync(0xffffffffu, s, off);
        const float mn = fmaxf(m, om);
        s = s * __expf(m - mn) + os * __expf(om - mn);
        m = mn;
    }
    const float sinv = 1.f / (s + 1e-16f);

    // ---- phase B: weighted aggregation ----
    float4 a0 = make_float4(0, 0, 0, 0), a1 = a0, a2 = a0, a3 = a0;
    const int hw0 = lane >> 4;
    for (int e = 0; e < deg; e++) {
        const int   sr = g_csr_sr[roff + e];
        const float at = g_csr_attr[roff + e];
        const int src = sr & 0xFFFFF, r = sr >> 20;
        float l = qrow[r * 16 + h]
                + g_qk[(size_t)src * 128 + r * 16 + 8 + h] + at * ceh;
        l = (l >= 0.f) ? l : 0.2f * l;
        const float w = __expf(l - m) * sinv;
        const float w0 = __shfl_sync(0xffffffffu, w, hw0);
        const float w1 = __shfl_sync(0xffffffffu, w, hw0 + 2);
        const float w2 = __shfl_sync(0xffffffffu, w, hw0 + 4);
        const float w3 = __shfl_sync(0xffffffffu, w, hw0 + 6);
        const float4* t4 = (const float4*)(g_t + ((size_t)r * NN + src) * HID);
        const float4 t0 = t4[lane], t1 = t4[lane + 32], t2 = t4[lane + 64], t3 = t4[lane + 96];
        a0.x += w0 * t0.x; a0.y += w0 * t0.y; a0.z += w0 * t0.z; a0.w += w0 * t0.w;
        a1.x += w1 * t1.x; a1.y += w1 * t1.y; a1.z += w1 * t1.z; a1.w += w1 * t1.w;
        a2.x += w2 * t2.x; a2.y += w2 * t2.y; a2.z += w2 * t2.z; a2.w += w2 * t2.w;
        a3.x += w3 * t3.x; a3.y += w3 * t3.y; a3.z += w3 * t3.z; a3.w += w3 * t3.w;
    }

    if (concat) {
        const float4* b4 = (const float4*)b;
        float4* o4 = (float4*)(g_h + (size_t)d * HID);
        float4 v;
        v = b4[lane];      o4[lane]      = make_float4(a0.x + v.x, a0.y + v.y, a0.z + v.z, a0.w + v.w);
        v = b4[lane + 32]; o4[lane + 32] = make_float4(a1.x + v.x, a1.y + v.y, a1.z + v.z, a1.w + v.w);
        v = b4[lane + 64]; o4[lane + 64] = make_float4(a2.x + v.x, a2.y + v.y, a2.z + v.z, a2.w + v.w);
        v = b4[lane + 96]; o4[lane + 96] = make_float4(a3.x + v.x, a3.y + v.y, a3.z + v.z, a3.w + v.w);
    } else {
        float4 s1 = make_float4(a0.x + a1.x + a2.x + a3.x,
                                a0.y + a1.y + a2.y + a3.y,
                                a0.z + a1.z + a2.z + a3.z,
                                a0.w + a1.w + a2.w + a3.w);
        s1.x += __shfl_xor_sync(0xffffffffu, s1.x, 16);
        s1.y += __shfl_xor_sync(0xffffffffu, s1.y, 16);
        s1.z += __shfl_xor_sync(0xffffffffu, s1.z, 16);
        s1.w += __shfl_xor_sync(0xffffffffu, s1.w, 16);
        if (lane < 16) {
            const float4 bv = ((const float4*)b)[lane];
            ((float4*)(out + (size_t)d * OC))[lane] =
                make_float4(s1.x * 0.125f + bv.x, s1.y * 0.125f + bv.y,
                            s1.z * 0.125f + bv.z, s1.w * 0.125f + bv.w);
        }
    }
}

// ---------------- host driver ------------------------------------------------
extern "C" void kernel_launch(void* const* d_in, const int* in_sizes, int n_in,
                              void* d_out, int out_size) {
    const float* x   = (const float*)d_in[0];
    const int*   ei  = (const int*)  d_in[1];
    const int*   ety = (const int*)  d_in[2];
    const float* ea  = (const float*)d_in[3];
    const float* W1  = (const float*)d_in[4];
    const float* q1  = (const float*)d_in[5];
    const float* k1  = (const float*)d_in[6];
    const float* We1 = (const float*)d_in[7];
    const float* e1  = (const float*)d_in[8];
    const float* b1  = (const float*)d_in[9];
    const float* W2  = (const float*)d_in[10];
    const float* q2  = (const float*)d_in[11];
    const float* k2  = (const float*)d_in[12];
    const float* We2 = (const float*)d_in[13];
    const float* e2  = (const float*)d_in[14];
    const float* b2  = (const float*)d_in[15];

    const int E0   = in_sizes[2];
    const int Etot = E0 + NN;

    const dim3 gg(4 * RR, NN / 128);
    const dim3 gq(1, NN / 128);
    const int  eB   = (Etot + 255) / 256;
    const int  fagB = (NN * 32) / 256;

    init_kernel<<<(NN + 255) / 256, 256>>>();
    etmax_kernel<<<256, 256>>>(ety, E0);
    hist_kernel<<<eB, 256>>>(ei, E0, Etot);

    // ---------------- layer 1 (concat) ----------------
    gemm_l1_kernel<<<gg, 256>>>(x, W1);
    scan_kernel<<<1, 1024>>>();
    scatter_kernel<<<eB, 256>>>(ei, ety, ea, E0, Etot);
    packqk_kernel<<<RR * F1 / 8, 256>>>(W1, q1, k1, F1);
    ce_kernel<<<1, 256>>>(We1, e1);
    qkgemm_l1_kernel<<<gq, 256>>>(x, F1);
    fagg_kernel<<<fagB, 256>>>(b1, nullptr, 1);

    // ---------------- layer 2 (mean) ------------------
    gemm_l2_kernel<<<gg, 256>>>(W2);
    packqk_kernel<<<RR * HID / 8, 256>>>(W2, q2, k2, HID);
    ce_kernel<<<1, 256>>>(We2, e2);
    qkgemm_l2_kernel<<<gq, 256>>>(HID);
    fagg_kernel<<<fagB, 256>>>(b2, (float*)d_out, 0);
}

// round 7
// speedup vs baseline: 4.0527x; 1.1029x over previous
#include <cuda_runtime.h>
#include <cstdint>

// Problem dimensions (fixed by the dataset)
#define NN   16000          // nodes
#define F1   256            // layer-1 input features
#define HID  512            // HEADS*OUT
#define NH   8              // heads
#define OC   64             // per-head out channels
#define RR   8              // relations
#define ECAP 300000         // capacity for edges + self loops

// ---------------- scratch (device globals; no allocation allowed) ----------
__device__ float    g_t[(size_t)RR * NN * HID];   // relation-transformed nodes [R,N,512]
__device__ float    g_h[(size_t)NN * HID];        // layer-1 output
__device__ float    g_qk[(size_t)NN * 128];       // [node][r*16 + (q:0-7 | k:8-15)]
__device__ float    g_wqk[(size_t)HID * 128];     // folded W@q / W@k weights
__device__ float    g_ce[NH];                     // (We @ e)[h]
__device__ int      g_etmax;
__device__ int      g_hist[NN];
__device__ int      g_rowptr[NN + 1];
__device__ int      g_cursor[NN];
__device__ int      g_csr_sr[ECAP];               // src | (rel << 20)
__device__ float    g_csr_attr[ECAP];

// ---------------- helpers ---------------------------------------------------
__device__ __forceinline__ uint32_t f2tf(float f) {
    uint32_t u;
    asm("cvt.rna.tf32.f32 %0, %1;" : "=r"(u) : "f"(f));
    return u;
}
__device__ __forceinline__ void mma_tf32(float c[4], const uint32_t a[4], const uint32_t b[2]) {
    asm volatile("mma.sync.aligned.m16n8k8.row.col.f32.tf32.tf32.f32 "
                 "{%0,%1,%2,%3}, {%4,%5,%6,%7}, {%8,%9}, {%0,%1,%2,%3};"
                 : "+f"(c[0]), "+f"(c[1]), "+f"(c[2]), "+f"(c[3])
                 : "r"(a[0]), "r"(a[1]), "r"(a[2]), "r"(a[3]), "r"(b[0]), "r"(b[1]));
}

// ---------------- CSR build --------------------------------------------------
__global__ void init_kernel() {
    int i = blockIdx.x * blockDim.x + threadIdx.x;
    if (i < NN) g_hist[i] = 0;
    if (i == 0) g_etmax = 0;
}

__global__ void etmax_kernel(const int* __restrict__ et, int E0) {
    int i = blockIdx.x * blockDim.x + threadIdx.x;
    int loc = -1;
    for (; i < E0; i += gridDim.x * blockDim.x) loc = max(loc, et[i]);
    if (loc >= 0) atomicMax(&g_etmax, loc);
}

__global__ void hist_kernel(const int* __restrict__ ei, int E0, int Etot) {
    int e = blockIdx.x * blockDim.x + threadIdx.x;
    if (e >= Etot) return;
    int d = (e < E0) ? ei[E0 + e] : (e - E0);
    atomicAdd(&g_hist[d], 1);
}

__global__ __launch_bounds__(1024)
void scan_kernel() {
    __shared__ int sm[1024];
    const int t = threadIdx.x;
    const int base = t * 16;
    int loc[16];
    int sum = 0;
#pragma unroll
    for (int i = 0; i < 16; i++) {
        int idx = base + i;
        int v = (idx < NN) ? g_hist[idx] : 0;
        loc[i] = sum;
        sum += v;
    }
    sm[t] = sum;
    __syncthreads();
    for (int off = 1; off < 1024; off <<= 1) {
        int v = (t >= off) ? sm[t - off] : 0;
        __syncthreads();
        sm[t] += v;
        __syncthreads();
    }
    int pre = (t > 0) ? sm[t - 1] : 0;
#pragma unroll
    for (int i = 0; i < 16; i++) {
        int idx = base + i;
        if (idx < NN) {
            g_rowptr[idx] = pre + loc[i];
            g_cursor[idx] = pre + loc[i];
        }
    }
    if (t == 1023) g_rowptr[NN] = sm[1023];
}

__global__ void scatter_kernel(const int* __restrict__ ei, const int* __restrict__ etyp,
                               const float* __restrict__ ea, int E0, int Etot) {
    int e = blockIdx.x * blockDim.x + threadIdx.x;
    if (e >= Etot) return;
    int s, d, r;  float at;
    if (e < E0) { s = ei[e]; d = ei[E0 + e]; r = etyp[e]; at = ea[e]; }
    else        { s = d = e - E0; r = (g_etmax + 1) & (RR - 1); at = 0.5f; }
    int p = atomicAdd(&g_cursor[d], 1);
    g_csr_sr[p]   = s | (r << 20);
    g_csr_attr[p] = at;
}

// ======================= WIDE GEMM: 128x256 block, 64x64 warp tiles ==========
// 8 warps = 2(m) x 4(n). BK=8, double-buffered. A: [k][m-interleaved] stride 136
// (LDS.64 fragment pairs); B: [k][n] stride 264 (== 8 mod 32, conflict-free).
__global__ __launch_bounds__(256, 1)
void gemm_wide_kernel(const float* __restrict__ A, const float* __restrict__ B0,
                      float* __restrict__ C0, int K, int rstrideB, int rstrideC) {
    __shared__ __align__(16) uint32_t As[2][8][136];
    __shared__ __align__(16) uint32_t Bs[2][8][264];

    const int r  = blockIdx.x >> 1;
    const int n0 = (blockIdx.x & 1) * 256;
    const int m0 = blockIdx.y * 128;
    const float* B = B0 + (size_t)r * rstrideB;
    float*       C = C0 + (size_t)r * rstrideC;

    const int tid  = threadIdx.x;
    const int lane = tid & 31, warp = tid >> 5;
    const int grp  = lane >> 2, tig = lane & 3;
    const int wm   = (warp & 1) * 64;
    const int wn   = (warp >> 1) * 64;

    // loaders
    const int am   = tid & 127;
    const int amp  = (am & 0x70) | ((am & 7) << 1) | ((am >> 3) & 1);
    const int akq  = tid >> 7;                 // 0..1 -> k quads 0-3 / 4-7
    const int bn4  = tid & 63;
    const int bk   = tid >> 6;                 // 0..3, plus +4 row

    const float* Ag  = A + (size_t)(m0 + am) * K + 4 * akq;
    const float* Bg0 = B + (size_t)bk * 512 + n0 + 4 * bn4;
    const float* Bg1 = B + (size_t)(bk + 4) * 512 + n0 + 4 * bn4;

    float c[4][8][4];
#pragma unroll
    for (int mt = 0; mt < 4; mt++)
#pragma unroll
        for (int nt = 0; nt < 8; nt++)
#pragma unroll
            for (int i = 0; i < 4; i++) c[mt][nt][i] = 0.f;

    // prologue: stage 0
    float4 av  = *(const float4*)Ag;
    float4 bv0 = *(const float4*)Bg0;
    float4 bv1 = *(const float4*)Bg1;
    As[0][4 * akq + 0][amp] = f2tf(av.x);  As[0][4 * akq + 1][amp] = f2tf(av.y);
    As[0][4 * akq + 2][amp] = f2tf(av.z);  As[0][4 * akq + 3][amp] = f2tf(av.w);
    *(uint4*)&Bs[0][bk][4 * bn4]     = make_uint4(f2tf(bv0.x), f2tf(bv0.y), f2tf(bv0.z), f2tf(bv0.w));
    *(uint4*)&Bs[0][bk + 4][4 * bn4] = make_uint4(f2tf(bv1.x), f2tf(bv1.y), f2tf(bv1.z), f2tf(bv1.w));
    __syncthreads();

    int buf = 0;
    const int NSTEP = K >> 3;
    for (int s = 0; s < NSTEP; s++) {
        const bool nxt = (s + 1) < NSTEP;
        if (nxt) {
            const int ko = (s + 1) << 3;
            av  = *(const float4*)(Ag + ko);
            bv0 = *(const float4*)(Bg0 + (size_t)ko * 512);
            bv1 = *(const float4*)(Bg1 + (size_t)ko * 512);
        }
        // fragments
        uint32_t af[4][4], bf[8][2];
#pragma unroll
        for (int mt = 0; mt < 4; mt++) {
            const int mcol = wm + mt * 16 + 2 * grp;
            const uint2 p0 = *(const uint2*)&As[buf][tig][mcol];
            const uint2 p1 = *(const uint2*)&As[buf][tig + 4][mcol];
            af[mt][0] = p0.x; af[mt][1] = p0.y;
            af[mt][2] = p1.x; af[mt][3] = p1.y;
        }
#pragma unroll
        for (int nt = 0; nt < 8; nt++) {
            const int nc = wn + nt * 8 + grp;
            bf[nt][0] = Bs[buf][tig][nc];
            bf[nt][1] = Bs[buf][tig + 4][nc];
        }
#pragma unroll
        for (int mt = 0; mt < 4; mt++)
#pragma unroll
            for (int nt = 0; nt < 8; nt++)
                mma_tf32(c[mt][nt], af[mt], bf[nt]);

        if (nxt) {
            const int nb = buf ^ 1;
            As[nb][4 * akq + 0][amp] = f2tf(av.x);  As[nb][4 * akq + 1][amp] = f2tf(av.y);
            As[nb][4 * akq + 2][amp] = f2tf(av.z);  As[nb][4 * akq + 3][amp] = f2tf(av.w);
            *(uint4*)&Bs[nb][bk][4 * bn4]     = make_uint4(f2tf(bv0.x), f2tf(bv0.y), f2tf(bv0.z), f2tf(bv0.w));
            *(uint4*)&Bs[nb][bk + 4][4 * bn4] = make_uint4(f2tf(bv1.x), f2tf(bv1.y), f2tf(bv1.z), f2tf(bv1.w));
            __syncthreads();
            buf = nb;
        }
    }

#pragma unroll
    for (int mt = 0; mt < 4; mt++) {
        const int row = m0 + wm + mt * 16 + grp;
#pragma unroll
        for (int nt = 0; nt < 8; nt++) {
            const int col = n0 + wn + nt * 8 + tig * 2;
            *(float2*)(C + (size_t)row * 512 + col)       = make_float2(c[mt][nt][0], c[mt][nt][1]);
            *(float2*)(C + (size_t)(row + 8) * 512 + col) = make_float2(c[mt][nt][2], c[mt][nt][3]);
        }
    }
}

// wrapper reading layer-2 input from device global g_h
__global__ __launch_bounds__(256, 1)
void gemm_wide_l2_kernel(const float* __restrict__ B0) {
    // identical body via direct call is not possible for __global__; duplicate driver:
    // (delegates by computing with A = g_h)
    // NOTE: implemented as a thin launch of the same code path:
    extern __shared__ int _dummy[]; (void)_dummy;
    // This wrapper is intentionally unused; layer-2 uses gemm_wide_kernel with A passed.
}

// ---------------- narrow GEMM (128x128) for q/k projection -------------------
__device__ __forceinline__ void gemm_tf32_body(
    const float* __restrict__ A, const float* __restrict__ B,
    float* __restrict__ C, int K, int m0, int n0, int ldb, int ldc)
{
    __shared__ __align__(16) uint32_t As[2][16][136];
    __shared__ __align__(16) uint32_t Bs[2][16][136];

    const int tid  = threadIdx.x;
    const int lane = tid & 31, warp = tid >> 5;
    const int grp  = lane >> 2, tig = lane & 3;
    const int wm   = (warp & 3) * 32;
    const int wn   = (warp >> 2) * 64;

    const int am   = tid & 127;
    const int amp  = (am & 0x70) | ((am & 7) << 1) | ((am >> 3) & 1);
    const int akq0 = tid >> 7;
    const int akq1 = akq0 + 2;
    const int bn4  = tid & 31;
    const int bk0  = tid >> 5;
    const int bk1  = bk0 + 8;

    const float* Ag0 = A + (size_t)(m0 + am) * K + 4 * akq0;
    const float* Ag1 = A + (size_t)(m0 + am) * K + 4 * akq1;
    const float* Bg0 = B + (size_t)bk0 * ldb + n0 + 4 * bn4;
    const float* Bg1 = B + (size_t)bk1 * ldb + n0 + 4 * bn4;

    float c[2][8][4];
#pragma unroll
    for (int mt = 0; mt < 2; mt++)
#pragma unroll
        for (int nt = 0; nt < 8; nt++)
#pragma unroll
            for (int i = 0; i < 4; i++) c[mt][nt][i] = 0.f;

    float4 a0v = *(const float4*)Ag0;
    float4 a1v = *(const float4*)Ag1;
    float4 b0v = *(const float4*)Bg0;
    float4 b1v = *(const float4*)Bg1;
    As[0][4 * akq0 + 0][amp] = f2tf(a0v.x); As[0][4 * akq0 + 1][amp] = f2tf(a0v.y);
    As[0][4 * akq0 + 2][amp] = f2tf(a0v.z); As[0][4 * akq0 + 3][amp] = f2tf(a0v.w);
    As[0][4 * akq1 + 0][amp] = f2tf(a1v.x); As[0][4 * akq1 + 1][amp] = f2tf(a1v.y);
    As[0][4 * akq1 + 2][amp] = f2tf(a1v.z); As[0][4 * akq1 + 3][amp] = f2tf(a1v.w);
    *(uint4*)&Bs[0][bk0][4 * bn4] = make_uint4(f2tf(b0v.x), f2tf(b0v.y), f2tf(b0v.z), f2tf(b0v.w));
    *(uint4*)&Bs[0][bk1][4 * bn4] = make_uint4(f2tf(b1v.x), f2tf(b1v.y), f2tf(b1v.z), f2tf(b1v.w));
    __syncthreads();

    int buf = 0;
    const int NSTEP = K >> 4;
    for (int s = 0; s < NSTEP; s++) {
        const bool nxt = (s + 1) < NSTEP;
        if (nxt) {
            const int ko = (s + 1) << 4;
            a0v = *(const float4*)(Ag0 + ko);
            a1v = *(const float4*)(Ag1 + ko);
            b0v = *(const float4*)(Bg0 + (size_t)ko * ldb);
            b1v = *(const float4*)(Bg1 + (size_t)ko * ldb);
        }
#pragma unroll
        for (int kb = 0; kb < 16; kb += 8) {
            uint32_t af[2][4], bf[8][2];
#pragma unroll
            for (int mt = 0; mt < 2; mt++) {
                const int mcol = wm + mt * 16 + 2 * grp;
                const uint2 p0 = *(const uint2*)&As[buf][kb + tig][mcol];
                const uint2 p1 = *(const uint2*)&As[buf][kb + tig + 4][mcol];
                af[mt][0] = p0.x; af[mt][1] = p0.y;
                af[mt][2] = p1.x; af[mt][3] = p1.y;
            }
#pragma unroll
            for (int nt = 0; nt < 8; nt++) {
                const int nc = wn + nt * 8 + grp;
                bf[nt][0] = Bs[buf][kb + tig][nc];
                bf[nt][1] = Bs[buf][kb + tig + 4][nc];
            }
#pragma unroll
            for (int mt = 0; mt < 2; mt++)
#pragma unroll
                for (int nt = 0; nt < 8; nt++)
                    mma_tf32(c[mt][nt], af[mt], bf[nt]);
        }
        if (nxt) {
            const int nb = buf ^ 1;
            As[nb][4 * akq0 + 0][amp] = f2tf(a0v.x); As[nb][4 * akq0 + 1][amp] = f2tf(a0v.y);
            As[nb][4 * akq0 + 2][amp] = f2tf(a0v.z); As[nb][4 * akq0 + 3][amp] = f2tf(a0v.w);
            As[nb][4 * akq1 + 0][amp] = f2tf(a1v.x); As[nb][4 * akq1 + 1][amp] = f2tf(a1v.y);
            As[nb][4 * akq1 + 2][amp] = f2tf(a1v.z); As[nb][4 * akq1 + 3][amp] = f2tf(a1v.w);
            *(uint4*)&Bs[nb][bk0][4 * bn4] = make_uint4(f2tf(b0v.x), f2tf(b0v.y), f2tf(b0v.z), f2tf(b0v.w));
            *(uint4*)&Bs[nb][bk1][4 * bn4] = make_uint4(f2tf(b1v.x), f2tf(b1v.y), f2tf(b1v.z), f2tf(b1v.w));
            __syncthreads();
            buf = nb;
        }
    }

#pragma unroll
    for (int mt = 0; mt < 2; mt++) {
        const int row = m0 + wm + mt * 16 + grp;
#pragma unroll
        for (int nt = 0; nt < 8; nt++) {
            const int col = n0 + wn + nt * 8 + tig * 2;
            *(float2*)(C + (size_t)row * ldc + col)       = make_float2(c[mt][nt][0], c[mt][nt][1]);
            *(float2*)(C + (size_t)(row + 8) * ldc + col) = make_float2(c[mt][nt][2], c[mt][nt][3]);
        }
    }
}

// q/k projection GEMM: [NN x K] @ [K x 128] -> g_qk [NN x 128]
__global__ __launch_bounds__(256, 2)
void qkgemm_l1_kernel(const float* __restrict__ A, int K) {
    gemm_tf32_body(A, g_wqk, g_qk, K, blockIdx.y * 128, 0, 128, 128);
}
__global__ __launch_bounds__(256, 2)
void qkgemm_l2_kernel(int K) {
    gemm_tf32_body(g_h, g_wqk, g_qk, K, blockIdx.y * 128, 0, 128, 128);
}

// ---------------- fold weights: g_wqk[j][r*16+h]=W[r]@q, +8: W[r]@k ----------
__global__ __launch_bounds__(256)
void packqk_kernel(const float* __restrict__ W, const float* __restrict__ q,
                   const float* __restrict__ k, int K) {
    const int gw = (blockIdx.x * blockDim.x + threadIdx.x) >> 5;
    if (gw >= RR * K) return;
    const int r = gw / K, j = gw - r * K;
    const int lane = threadIdx.x & 31;
    const float4* w4 = (const float4*)(W + ((size_t)r * K + j) * HID);
    const float4* q4 = (const float4*)q;
    const float4* k4 = (const float4*)k;
    float aq[NH], ak[NH];
#pragma unroll
    for (int h = 0; h < NH; h++) { aq[h] = 0.f; ak[h] = 0.f; }
#pragma unroll
    for (int i = 0; i < 4; i++) {
        const int c4 = lane + 32 * i;
        const float4 wv = w4[c4];
        const float wa[4] = {wv.x, wv.y, wv.z, wv.w};
#pragma unroll
        for (int f = 0; f < 4; f++) {
            const int c = 4 * c4 + f;
            const float4 qa = q4[c * 2], qb = q4[c * 2 + 1];
            const float4 ka = k4[c * 2], kb = k4[c * 2 + 1];
            const float w = wa[f];
            aq[0] += w * qa.x; aq[1] += w * qa.y; aq[2] += w * qa.z; aq[3] += w * qa.w;
            aq[4] += w * qb.x; aq[5] += w * qb.y; aq[6] += w * qb.z; aq[7] += w * qb.w;
            ak[0] += w * ka.x; ak[1] += w * ka.y; ak[2] += w * ka.z; ak[3] += w * ka.w;
            ak[4] += w * kb.x; ak[5] += w * kb.y; ak[6] += w * kb.z; ak[7] += w * kb.w;
        }
    }
#pragma unroll
    for (int h = 0; h < NH; h++) {
#pragma unroll
        for (int o = 16; o; o >>= 1) {
            aq[h] += __shfl_xor_sync(0xffffffffu, aq[h], o);
            ak[h] += __shfl_xor_sync(0xffffffffu, ak[h], o);
        }
    }
    if (lane == 0) {
        float* dst = g_wqk + (size_t)j * 128 + r * 16;
#pragma unroll
        for (int h = 0; h < NH; h++) {
            dst[h]      = aq[h];
            dst[8 + h]  = ak[h];
        }
    }
}

// ---------------- ce[h] = sum_j We[j] * e[j][h] (warp per head) --------------
__global__ void ce_kernel(const float* __restrict__ We, const float* __restrict__ e) {
    const int warp = threadIdx.x >> 5, lane = threadIdx.x & 31;
    float s = 0.f;
    for (int j = lane; j < HID; j += 32) s += We[j] * e[j * NH + warp];
#pragma unroll
    for (int o = 16; o; o >>= 1) s += __shfl_xor_sync(0xffffffffu, s, o);
    if (lane == 0) g_ce[warp] = s;
}

// ---------------- fused softmax + aggregation: warp per destination ----------
__global__ __launch_bounds__(256)
void fagg_kernel(const float* __restrict__ b, float* __restrict__ out, int concat) {
    const int d = (blockIdx.x * blockDim.x + threadIdx.x) >> 5;
    if (d >= NN) return;
    const int lane = threadIdx.x & 31;
    const int h = lane & 7;
    const int roff = g_rowptr[d];
    const int deg  = g_rowptr[d + 1] - roff;
    const float ceh = g_ce[h];
    const float* qrow = g_qk + (size_t)d * 128;

    // ---- phase A: per-head online softmax stats ----
    float m = -1e30f, s = 0.f;
    for (int base = 0; base < deg; base += 4) {
        const int e = base + (lane >> 3);
        if (e < deg) {
            const int   sr = g_csr_sr[roff + e];
            const float at = g_csr_attr[roff + e];
            const int src = sr & 0xFFFFF, r = sr >> 20;
            float l = qrow[r * 16 + h]
                    + g_qk[(size_t)src * 128 + r * 16 + 8 + h] + at * ceh;
            l = (l >= 0.f) ? l : 0.2f * l;
            const float mn = fmaxf(m, l);
            s = s * __expf(m - mn) + __expf(l - mn);
            m = mn;
        }
    }
#pragma unroll
    for (int off = 8; off < 32; off <<= 1) {
        const float om = __shfl_xor_sync(0xffffffffu, m, off);
        const float os = __shfl_xor_sync(0xffffffffu, s, off);
        const float mn = fmaxf(m, om);
        s = s * __expf(m - mn) + os * __expf(om - mn);
        m = mn;
    }
    const float sinv = 1.f / (s + 1e-16f);

    // ---- phase B: weighted aggregation ----
    float4 a0 = make_float4(0, 0, 0, 0), a1 = a0, a2 = a0, a3 = a0;
    const int hw0 = lane >> 4;
    for (int e = 0; e < deg; e++) {
        const int   sr = g_csr_sr[roff + e];
        const float at = g_csr_attr[roff + e];
        const int src = sr & 0xFFFFF, r = sr >> 20;
        float l = qrow[r * 16 + h]
                + g_qk[(size_t)src * 128 + r * 16 + 8 + h] + at * ceh;
        l = (l >= 0.f) ? l : 0.2f * l;
        const float w = __expf(l - m) * sinv;
        const float w0 = __shfl_sync(0xffffffffu, w, hw0);
        const float w1 = __shfl_sync(0xffffffffu, w, hw0 + 2);
        const float w2 = __shfl_sync(0xffffffffu, w, hw0 + 4);
        const float w3 = __shfl_sync(0xffffffffu, w, hw0 + 6);
        const float4* t4 = (const float4*)(g_t + ((size_t)r * NN + src) * HID);
        const float4 t0 = t4[lane], t1 = t4[lane + 32], t2 = t4[lane + 64], t3 = t4[lane + 96];
        a0.x += w0 * t0.x; a0.y += w0 * t0.y; a0.z += w0 * t0.z; a0.w += w0 * t0.w;
        a1.x += w1 * t1.x; a1.y += w1 * t1.y; a1.z += w1 * t1.z; a1.w += w1 * t1.w;
        a2.x += w2 * t2.x; a2.y += w2 * t2.y; a2.z += w2 * t2.z; a2.w += w2 * t2.w;
        a3.x += w3 * t3.x; a3.y += w3 * t3.y; a3.z += w3 * t3.z; a3.w += w3 * t3.w;
    }

    if (concat) {
        const float4* b4 = (const float4*)b;
        float4* o4 = (float4*)(g_h + (size_t)d * HID);
        float4 v;
        v = b4[lane];      o4[lane]      = make_float4(a0.x + v.x, a0.y + v.y, a0.z + v.z, a0.w + v.w);
        v = b4[lane + 32]; o4[lane + 32] = make_float4(a1.x + v.x, a1.y + v.y, a1.z + v.z, a1.w + v.w);
        v = b4[lane + 64]; o4[lane + 64] = make_float4(a2.x + v.x, a2.y + v.y, a2.z + v.z, a2.w + v.w);
        v = b4[lane + 96]; o4[lane + 96] = make_float4(a3.x + v.x, a3.y + v.y, a3.z + v.z, a3.w + v.w);
    } else {
        float4 s1 = make_float4(a0.x + a1.x + a2.x + a3.x,
                                a0.y + a1.y + a2.y + a3.y,
                                a0.z + a1.z + a2.z + a3.z,
                                a0.w + a1.w + a2.w + a3.w);
        s1.x += __shfl_xor_sync(0xffffffffu, s1.x, 16);
        s1.y += __shfl_xor_sync(0xffffffffu, s1.y, 16);
        s1.z += __shfl_xor_sync(0xffffffffu, s1.z, 16);
        s1.w += __shfl_xor_sync(0xffffffffu, s1.w, 16);
        if (lane < 16) {
            const float4 bv = ((const float4*)b)[lane];
            ((float4*)(out + (size_t)d * OC))[lane] =
                make_float4(s1.x * 0.125f + bv.x, s1.y * 0.125f + bv.y,
                            s1.z * 0.125f + bv.z, s1.w * 0.125f + bv.w);
        }
    }
}

// A-pointer shim for layer 2 (A lives in device global g_h)
__global__ void noop_kernel() {}

// ---------------- host driver ------------------------------------------------
extern "C" void kernel_launch(void* const* d_in, const int* in_sizes, int n_in,
                              void* d_out, int out_size) {
    const float* x   = (const float*)d_in[0];
    const int*   ei  = (const int*)  d_in[1];
    const int*   ety = (const int*)  d_in[2];
    const float* ea  = (const float*)d_in[3];
    const float* W1  = (const float*)d_in[4];
    const float* q1  = (const float*)d_in[5];
    const float* k1  = (const float*)d_in[6];
    const float* We1 = (const float*)d_in[7];
    const float* e1  = (const float*)d_in[8];
    const float* b1  = (const float*)d_in[9];
    const float* W2  = (const float*)d_in[10];
    const float* q2  = (const float*)d_in[11];
    const float* k2  = (const float*)d_in[12];
    const float* We2 = (const float*)d_in[13];
    const float* e2  = (const float*)d_in[14];
    const float* b2  = (const float*)d_in[15];

    const int E0   = in_sizes[2];
    const int Etot = E0 + NN;

    // device-global addresses for kernel arguments (host API allowed: not an alloc)
    float *p_t = nullptr, *p_h = nullptr;
    cudaGetSymbolAddress((void**)&p_t, g_t);
    cudaGetSymbolAddress((void**)&p_h, g_h);

    const dim3 gw(2 * RR, NN / 128);   // wide GEMM: (n_half | r<<1, m_tile)
    const dim3 gq(1, NN / 128);
    const int  eB   = (Etot + 255) / 256;
    const int  fagB = (NN * 32) / 256;

    init_kernel<<<(NN + 255) / 256, 256>>>();
    etmax_kernel<<<256, 256>>>(ety, E0);
    hist_kernel<<<eB, 256>>>(ei, E0, Etot);

    // ---------------- layer 1 (concat) ----------------
    gemm_wide_kernel<<<gw, 256>>>(x, W1, p_t, F1, F1 * HID, NN * HID);
    scan_kernel<<<1, 1024>>>();
    scatter_kernel<<<eB, 256>>>(ei, ety, ea, E0, Etot);
    packqk_kernel<<<RR * F1 / 8, 256>>>(W1, q1, k1, F1);
    ce_kernel<<<1, 256>>>(We1, e1);
    qkgemm_l1_kernel<<<gq, 256>>>(x, F1);
    fagg_kernel<<<fagB, 256>>>(b1, nullptr, 1);

    // ---------------- layer 2 (mean) ------------------
    gemm_wide_kernel<<<gw, 256>>>(p_h, W2, p_t, HID, HID * HID, NN * HID);
    packqk_kernel<<<RR * HID / 8, 256>>>(W2, q2, k2, HID);
    ce_kernel<<<1, 256>>>(We2, e2);
    qkgemm_l2_kernel<<<gq, 256>>>(HID);
    fagg_kernel<<<fagB, 256>>>(b2, (float*)d_out, 0);
}

// round 8
// speedup vs baseline: 4.1563x; 1.0255x over previous
#include <cuda_runtime.h>
#include <cstdint>

// Problem dimensions (fixed by the dataset)
#define NN   16000          // nodes
#define F1   256            // layer-1 input features
#define HID  512            // HEADS*OUT
#define NH   8              // heads
#define OC   64             // per-head out channels
#define RR   8              // relations
#define ECAP 300000         // capacity for edges + self loops

// ---------------- scratch (device globals; no allocation allowed) ----------
__device__ float    g_t[(size_t)RR * NN * HID];   // relation-transformed nodes [R,N,512]
__device__ float    g_h[(size_t)NN * HID];        // layer-1 output
__device__ float    g_qk[(size_t)NN * 128];       // [node][r*16 + (q:0-7 | k:8-15)]
__device__ float    g_wqk[(size_t)HID * 128];     // folded W@q / W@k weights
__device__ float    g_ce[NH];                     // (We @ e)[h]
__device__ uint32_t g_At[(size_t)HID * NN];       // tf32 bits, [K][M] m-interleaved
__device__ uint32_t g_Bt[(size_t)RR * HID * HID]; // tf32 bits, [r][k][n]
__device__ int      g_etmax;
__device__ int      g_hist[NN];
__device__ int      g_rowptr[NN + 1];
__device__ int      g_cursor[NN];
__device__ int      g_csr_sr[ECAP];               // src | (rel << 20)
__device__ float    g_csr_attr[ECAP];

// ---------------- helpers ---------------------------------------------------
__device__ __forceinline__ uint32_t f2tf(float f) {
    uint32_t u;
    asm("cvt.rna.tf32.f32 %0, %1;" : "=r"(u) : "f"(f));
    return u;
}
__device__ __forceinline__ void mma_tf32(float c[4], const uint32_t a[4], const uint32_t b[2]) {
    asm volatile("mma.sync.aligned.m16n8k8.row.col.f32.tf32.tf32.f32 "
                 "{%0,%1,%2,%3}, {%4,%5,%6,%7}, {%8,%9}, {%0,%1,%2,%3};"
                 : "+f"(c[0]), "+f"(c[1]), "+f"(c[2]), "+f"(c[3])
                 : "r"(a[0]), "r"(a[1]), "r"(a[2]), "r"(a[3]), "r"(b[0]), "r"(b[1]));
}
__device__ __forceinline__ uint32_t s2u(const void* p) {
    uint32_t a;
    asm("{.reg .u64 t; cvta.to.shared.u64 t, %1; cvt.u32.u64 %0, t;}" : "=r"(a) : "l"(p));
    return a;
}
__device__ __forceinline__ void cp16(uint32_t saddr, const void* g) {
    asm volatile("cp.async.cg.shared.global [%0], [%1], 16;" :: "r"(saddr), "l"(g));
}
#define CP_COMMIT() asm volatile("cp.async.commit_group;")
#define CP_WAIT1()  asm volatile("cp.async.wait_group 1;")

// ---------------- CSR build --------------------------------------------------
__global__ void init_kernel() {
    int i = blockIdx.x * blockDim.x + threadIdx.x;
    if (i < NN) g_hist[i] = 0;
    if (i == 0) g_etmax = 0;
}

__global__ void etmax_kernel(const int* __restrict__ et, int E0) {
    int i = blockIdx.x * blockDim.x + threadIdx.x;
    int loc = -1;
    for (; i < E0; i += gridDim.x * blockDim.x) loc = max(loc, et[i]);
    if (loc >= 0) atomicMax(&g_etmax, loc);
}

__global__ void hist_kernel(const int* __restrict__ ei, int E0, int Etot) {
    int e = blockIdx.x * blockDim.x + threadIdx.x;
    if (e >= Etot) return;
    int d = (e < E0) ? ei[E0 + e] : (e - E0);
    atomicAdd(&g_hist[d], 1);
}

__global__ __launch_bounds__(1024)
void scan_kernel() {
    __shared__ int sm[1024];
    const int t = threadIdx.x;
    const int base = t * 16;
    int loc[16];
    int sum = 0;
#pragma unroll
    for (int i = 0; i < 16; i++) {
        int idx = base + i;
        int v = (idx < NN) ? g_hist[idx] : 0;
        loc[i] = sum;
        sum += v;
    }
    sm[t] = sum;
    __syncthreads();
    for (int off = 1; off < 1024; off <<= 1) {
        int v = (t >= off) ? sm[t - off] : 0;
        __syncthreads();
        sm[t] += v;
        __syncthreads();
    }
    int pre = (t > 0) ? sm[t - 1] : 0;
#pragma unroll
    for (int i = 0; i < 16; i++) {
        int idx = base + i;
        if (idx < NN) {
            g_rowptr[idx] = pre + loc[i];
            g_cursor[idx] = pre + loc[i];
        }
    }
    if (t == 1023) g_rowptr[NN] = sm[1023];
}

__global__ void scatter_kernel(const int* __restrict__ ei, const int* __restrict__ etyp,
                               const float* __restrict__ ea, int E0, int Etot) {
    int e = blockIdx.x * blockDim.x + threadIdx.x;
    if (e >= Etot) return;
    int s, d, r;  float at;
    if (e < E0) { s = ei[e]; d = ei[E0 + e]; r = etyp[e]; at = ea[e]; }
    else        { s = d = e - E0; r = (g_etmax + 1) & (RR - 1); at = 0.5f; }
    int p = atomicAdd(&g_cursor[d], 1);
    g_csr_sr[p]   = s | (r << 20);
    g_csr_attr[p] = at;
}

// ---------------- operand conversion ----------------------------------------
// A: [M][K] fp32 -> g_At [K][M] tf32 bits, m-interleaved within 16-groups.
__global__ __launch_bounds__(256)
void convA_kernel(const float* __restrict__ A, int K) {
    __shared__ float sm[32][33];
    const int tx = threadIdx.x & 31, ty = threadIdx.x >> 5;   // 32 x 8
    const int k0 = blockIdx.x * 32, m0 = blockIdx.y * 32;
#pragma unroll
    for (int j = 0; j < 4; j++)
        sm[ty + 8 * j][tx] = A[(size_t)(m0 + ty + 8 * j) * K + k0 + tx];
    __syncthreads();
    const int lm   = m0 + tx;
    const int mperm = (lm & ~15) | (((lm & 7) << 1) | ((lm >> 3) & 1));
#pragma unroll
    for (int j = 0; j < 4; j++)
        g_At[(size_t)(k0 + ty + 8 * j) * NN + mperm] = f2tf(sm[tx][ty + 8 * j]);
}

// B: elementwise fp32 -> tf32 bits (layout unchanged)
__global__ __launch_bounds__(256)
void convB_kernel(const float* __restrict__ B, int n) {
    int i = blockIdx.x * blockDim.x + threadIdx.x;
    if (i < n) g_Bt[i] = f2tf(B[i]);
}

// ======================= cp.async GEMM: 128x256 block, 64x64 warp tiles ======
// 8 warps = 2(m) x 4(n). BK=8, 3 stages. As [k][m-int] stride 136; Bs [k][n]
// stride 264 (== 8 mod 32). Inner loop: LDGSTS only; tf32 pre-converted.
__global__ __launch_bounds__(256, 1)
void gemm_cp_kernel(float* __restrict__ C0, int K, int rstrideB, int rstrideC) {
    __shared__ __align__(16) uint32_t As[3][8][136];
    __shared__ __align__(16) uint32_t Bs[3][8][264];

    const int r  = blockIdx.x >> 1;
    const int n0 = (blockIdx.x & 1) * 256;
    const int m0 = blockIdx.y * 128;
    const uint32_t* Bt = g_Bt + (size_t)r * rstrideB;
    float*          C  = C0 + (size_t)r * rstrideC;

    const int tid  = threadIdx.x;
    const int lane = tid & 31, warp = tid >> 5;
    const int grp  = lane >> 2, tig = lane & 3;
    const int wm   = (warp & 1) * 64;
    const int wn   = (warp >> 1) * 64;

    // loader mapping
    const int arow  = tid >> 5, acol4 = (tid & 31) * 4;
    const int brow  = tid >> 6, bcol4 = (tid & 63) * 4;
    const uint32_t* Ag  = g_At + (size_t)arow * NN + m0 + acol4;
    const uint32_t* Bg0 = Bt + (size_t)brow * 512 + n0 + bcol4;
    const uint32_t* Bg1 = Bt + (size_t)(brow + 4) * 512 + n0 + bcol4;

    uint32_t sA[3], sB0[3], sB1[3];
#pragma unroll
    for (int st = 0; st < 3; st++) {
        sA[st]  = s2u(&As[st][arow][acol4]);
        sB0[st] = s2u(&Bs[st][brow][bcol4]);
        sB1[st] = s2u(&Bs[st][brow + 4][bcol4]);
    }

    float c[4][8][4];
#pragma unroll
    for (int mt = 0; mt < 4; mt++)
#pragma unroll
        for (int nt = 0; nt < 8; nt++)
#pragma unroll
            for (int i = 0; i < 4; i++) c[mt][nt][i] = 0.f;

    const int NSTEP = K >> 3;
    // prologue: stages 0,1
#pragma unroll
    for (int st = 0; st < 2; st++) {
        const int k0 = st * 8;
        cp16(sA[st],  Ag  + (size_t)k0 * NN);
        cp16(sB0[st], Bg0 + (size_t)k0 * 512);
        cp16(sB1[st], Bg1 + (size_t)k0 * 512);
        CP_COMMIT();
    }

    int buf = 0;
    for (int s = 0; s < NSTEP; s++) {
        CP_WAIT1();
        __syncthreads();
        if (s + 2 < NSTEP) {
            const int st = (s + 2) % 3;
            const int k0 = (s + 2) * 8;
            cp16(sA[st],  Ag  + (size_t)k0 * NN);
            cp16(sB0[st], Bg0 + (size_t)k0 * 512);
            cp16(sB1[st], Bg1 + (size_t)k0 * 512);
        }
        CP_COMMIT();          // commit every iter (possibly empty) keeps group count in sync

        uint32_t af[4][4], bf[8][2];
#pragma unroll
        for (int mt = 0; mt < 4; mt++) {
            const int mcol = wm + mt * 16 + 2 * grp;
            const uint2 p0 = *(const uint2*)&As[buf][tig][mcol];
            const uint2 p1 = *(const uint2*)&As[buf][tig + 4][mcol];
            af[mt][0] = p0.x; af[mt][1] = p0.y;
            af[mt][2] = p1.x; af[mt][3] = p1.y;
        }
#pragma unroll
        for (int nt = 0; nt < 8; nt++) {
            const int nc = wn + nt * 8 + grp;
            bf[nt][0] = Bs[buf][tig][nc];
            bf[nt][1] = Bs[buf][tig + 4][nc];
        }
#pragma unroll
        for (int mt = 0; mt < 4; mt++)
#pragma unroll
            for (int nt = 0; nt < 8; nt++)
                mma_tf32(c[mt][nt], af[mt], bf[nt]);

        buf = (buf + 1 == 3) ? 0 : buf + 1;
        __syncthreads();      // all warps done with buf before cp.async refills it next iter
    }

#pragma unroll
    for (int mt = 0; mt < 4; mt++) {
        const int row = m0 + wm + mt * 16 + grp;
#pragma unroll
        for (int nt = 0; nt < 8; nt++) {
            const int col = n0 + wn + nt * 8 + tig * 2;
            *(float2*)(C + (size_t)row * 512 + col)       = make_float2(c[mt][nt][0], c[mt][nt][1]);
            *(float2*)(C + (size_t)(row + 8) * 512 + col) = make_float2(c[mt][nt][2], c[mt][nt][3]);
        }
    }
}

// ---------------- narrow GEMM (128x128) for q/k projection -------------------
__device__ __forceinline__ void gemm_tf32_body(
    const float* __restrict__ A, const float* __restrict__ B,
    float* __restrict__ C, int K, int m0, int n0, int ldb, int ldc)
{
    __shared__ __align__(16) uint32_t As[2][16][136];
    __shared__ __align__(16) uint32_t Bs[2][16][136];

    const int tid  = threadIdx.x;
    const int lane = tid & 31, warp = tid >> 5;
    const int grp  = lane >> 2, tig = lane & 3;
    const int wm   = (warp & 3) * 32;
    const int wn   = (warp >> 2) * 64;

    const int am   = tid & 127;
    const int amp  = (am & 0x70) | ((am & 7) << 1) | ((am >> 3) & 1);
    const int akq0 = tid >> 7;
    const int akq1 = akq0 + 2;
    const int bn4  = tid & 31;
    const int bk0  = tid >> 5;
    const int bk1  = bk0 + 8;

    const float* Ag0 = A + (size_t)(m0 + am) * K + 4 * akq0;
    const float* Ag1 = A + (size_t)(m0 + am) * K + 4 * akq1;
    const float* Bg0 = B + (size_t)bk0 * ldb + n0 + 4 * bn4;
    const float* Bg1 = B + (size_t)bk1 * ldb + n0 + 4 * bn4;

    float c[2][8][4];
#pragma unroll
    for (int mt = 0; mt < 2; mt++)
#pragma unroll
        for (int nt = 0; nt < 8; nt++)
#pragma unroll
            for (int i = 0; i < 4; i++) c[mt][nt][i] = 0.f;

    float4 a0v = *(const float4*)Ag0;
    float4 a1v = *(const float4*)Ag1;
    float4 b0v = *(const float4*)Bg0;
    float4 b1v = *(const float4*)Bg1;
    As[0][4 * akq0 + 0][amp] = f2tf(a0v.x); As[0][4 * akq0 + 1][amp] = f2tf(a0v.y);
    As[0][4 * akq0 + 2][amp] = f2tf(a0v.z); As[0][4 * akq0 + 3][amp] = f2tf(a0v.w);
    As[0][4 * akq1 + 0][amp] = f2tf(a1v.x); As[0][4 * akq1 + 1][amp] = f2tf(a1v.y);
    As[0][4 * akq1 + 2][amp] = f2tf(a1v.z); As[0][4 * akq1 + 3][amp] = f2tf(a1v.w);
    *(uint4*)&Bs[0][bk0][4 * bn4] = make_uint4(f2tf(b0v.x), f2tf(b0v.y), f2tf(b0v.z), f2tf(b0v.w));
    *(uint4*)&Bs[0][bk1][4 * bn4] = make_uint4(f2tf(b1v.x), f2tf(b1v.y), f2tf(b1v.z), f2tf(b1v.w));
    __syncthreads();

    int buf = 0;
    const int NSTEP = K >> 4;
    for (int s = 0; s < NSTEP; s++) {
        const bool nxt = (s + 1) < NSTEP;
        if (nxt) {
            const int ko = (s + 1) << 4;
            a0v = *(const float4*)(Ag0 + ko);
            a1v = *(const float4*)(Ag1 + ko);
            b0v = *(const float4*)(Bg0 + (size_t)ko * ldb);
            b1v = *(const float4*)(Bg1 + (size_t)ko * ldb);
        }
#pragma unroll
        for (int kb = 0; kb < 16; kb += 8) {
            uint32_t af[2][4], bf[8][2];
#pragma unroll
            for (int mt = 0; mt < 2; mt++) {
                const int mcol = wm + mt * 16 + 2 * grp;
                const uint2 p0 = *(const uint2*)&As[buf][kb + tig][mcol];
                const uint2 p1 = *(const uint2*)&As[buf][kb + tig + 4][mcol];
                af[mt][0] = p0.x; af[mt][1] = p0.y;
                af[mt][2] = p1.x; af[mt][3] = p1.y;
            }
#pragma unroll
            for (int nt = 0; nt < 8; nt++) {
                const int nc = wn + nt * 8 + grp;
                bf[nt][0] = Bs[buf][kb + tig][nc];
                bf[nt][1] = Bs[buf][kb + tig + 4][nc];
            }
#pragma unroll
            for (int mt = 0; mt < 2; mt++)
#pragma unroll
                for (int nt = 0; nt < 8; nt++)
                    mma_tf32(c[mt][nt], af[mt], bf[nt]);
        }
        if (nxt) {
            const int nb = buf ^ 1;
            As[nb][4 * akq0 + 0][amp] = f2tf(a0v.x); As[nb][4 * akq0 + 1][amp] = f2tf(a0v.y);
            As[nb][4 * akq0 + 2][amp] = f2tf(a0v.z); As[nb][4 * akq0 + 3][amp] = f2tf(a0v.w);
            As[nb][4 * akq1 + 0][amp] = f2tf(a1v.x); As[nb][4 * akq1 + 1][amp] = f2tf(a1v.y);
            As[nb][4 * akq1 + 2][amp] = f2tf(a1v.z); As[nb][4 * akq1 + 3][amp] = f2tf(a1v.w);
            *(uint4*)&Bs[nb][bk0][4 * bn4] = make_uint4(f2tf(b0v.x), f2tf(b0v.y), f2tf(b0v.z), f2tf(b0v.w));
            *(uint4*)&Bs[nb][bk1][4 * bn4] = make_uint4(f2tf(b1v.x), f2tf(b1v.y), f2tf(b1v.z), f2tf(b1v.w));
            __syncthreads();
            buf = nb;
        }
    }

#pragma unroll
    for (int mt = 0; mt < 2; mt++) {
        const int row = m0 + wm + mt * 16 + grp;
#pragma unroll
        for (int nt = 0; nt < 8; nt++) {
            const int col = n0 + wn + nt * 8 + tig * 2;
            *(float2*)(C + (size_t)row * ldc + col)       = make_float2(c[mt][nt][0], c[mt][nt][1]);
            *(float2*)(C + (size_t)(row + 8) * ldc + col) = make_float2(c[mt][nt][2], c[mt][nt][3]);
        }
    }
}

// q/k projection GEMM: [NN x K] @ [K x 128] -> g_qk [NN x 128]
__global__ __launch_bounds__(256, 2)
void qkgemm_l1_kernel(const float* __restrict__ A, int K) {
    gemm_tf32_body(A, g_wqk, g_qk, K, blockIdx.y * 128, 0, 128, 128);
}
__global__ __launch_bounds__(256, 2)
void qkgemm_l2_kernel(int K) {
    gemm_tf32_body(g_h, g_wqk, g_qk, K, blockIdx.y * 128, 0, 128, 128);
}

// ---------------- fold weights: g_wqk[j][r*16+h]=W[r]@q, +8: W[r]@k ----------
__global__ __launch_bounds__(256)
void packqk_kernel(const float* __restrict__ W, const float* __restrict__ q,
                   const float* __restrict__ k, int K) {
    const int gw = (blockIdx.x * blockDim.x + threadIdx.x) >> 5;
    if (gw >= RR * K) return;
    const int r = gw / K, j = gw - r * K;
    const int lane = threadIdx.x & 31;
    const float4* w4 = (const float4*)(W + ((size_t)r * K + j) * HID);
    const float4* q4 = (const float4*)q;
    const float4* k4 = (const float4*)k;
    float aq[NH], ak[NH];
#pragma unroll
    for (int h = 0; h < NH; h++) { aq[h] = 0.f; ak[h] = 0.f; }
#pragma unroll
    for (int i = 0; i < 4; i++) {
        const int c4 = lane + 32 * i;
        const float4 wv = w4[c4];
        const float wa[4] = {wv.x, wv.y, wv.z, wv.w};
#pragma unroll
        for (int f = 0; f < 4; f++) {
            const int c = 4 * c4 + f;
            const float4 qa = q4[c * 2], qb = q4[c * 2 + 1];
            const float4 ka = k4[c * 2], kb = k4[c * 2 + 1];
            const float w = wa[f];
            aq[0] += w * qa.x; aq[1] += w * qa.y; aq[2] += w * qa.z; aq[3] += w * qa.w;
            aq[4] += w * qb.x; aq[5] += w * qb.y; aq[6] += w * qb.z; aq[7] += w * qb.w;
            ak[0] += w * ka.x; ak[1] += w * ka.y; ak[2] += w * ka.z; ak[3] += w * ka.w;
            ak[4] += w * kb.x; ak[5] += w * kb.y; ak[6] += w * kb.z; ak[7] += w * kb.w;
        }
    }
#pragma unroll
    for (int h = 0; h < NH; h++) {
#pragma unroll
        for (int o = 16; o; o >>= 1) {
            aq[h] += __shfl_xor_sync(0xffffffffu, aq[h], o);
            ak[h] += __shfl_xor_sync(0xffffffffu, ak[h], o);
        }
    }
    if (lane == 0) {
        float* dst = g_wqk + (size_t)j * 128 + r * 16;
#pragma unroll
        for (int h = 0; h < NH; h++) {
            dst[h]      = aq[h];
            dst[8 + h]  = ak[h];
        }
    }
}

// ---------------- ce[h] = sum_j We[j] * e[j][h] (warp per head) --------------
__global__ void ce_kernel(const float* __restrict__ We, const float* __restrict__ e) {
    const int warp = threadIdx.x >> 5, lane = threadIdx.x & 31;
    float s = 0.f;
    for (int j = lane; j < HID; j += 32) s += We[j] * e[j * NH + warp];
#pragma unroll
    for (int o = 16; o; o >>= 1) s += __shfl_xor_sync(0xffffffffu, s, o);
    if (lane == 0) g_ce[warp] = s;
}

// ---------------- fused softmax + aggregation: warp per destination ----------
__global__ __launch_bounds__(256)
void fagg_kernel(const float* __restrict__ b, float* __restrict__ out, int concat) {
    const int d = (blockIdx.x * blockDim.x + threadIdx.x) >> 5;
    if (d >= NN) return;
    const int lane = threadIdx.x & 31;
    const int h = lane & 7;
    const int roff = g_rowptr[d];
    const int deg  = g_rowptr[d + 1] - roff;
    const float ceh = g_ce[h];
    const float* qrow = g_qk + (size_t)d * 128;

    // ---- phase A: per-head online softmax stats ----
    float m = -1e30f, s = 0.f;
    for (int base = 0; base < deg; base += 4) {
        const int e = base + (lane >> 3);
        if (e < deg) {
            const int   sr = g_csr_sr[roff + e];
            const float at = g_csr_attr[roff + e];
            const int src = sr & 0xFFFFF, r = sr >> 20;
            float l = qrow[r * 16 + h]
                    + g_qk[(size_t)src * 128 + r * 16 + 8 + h] + at * ceh;
            l = (l >= 0.f) ? l : 0.2f * l;
            const float mn = fmaxf(m, l);
            s = s * __expf(m - mn) + __expf(l - mn);
            m = mn;
        }
    }
#pragma unroll
    for (int off = 8; off < 32; off <<= 1) {
        const float om = __shfl_xor_sync(0xffffffffu, m, off);
        const float os = __shfl_xor_sync(0xffffffffu, s, off);
        const float mn = fmaxf(m, om);
        s = s * __expf(m - mn) + os * __expf(om - mn);
        m = mn;
    }
    const float sinv = 1.f / (s + 1e-16f);

    // ---- phase B: weighted aggregation ----
    float4 a0 = make_float4(0, 0, 0, 0), a1 = a0, a2 = a0, a3 = a0;
    const int hw0 = lane >> 4;
    for (int e = 0; e < deg; e++) {
        const int   sr = g_csr_sr[roff + e];
        const float at = g_csr_attr[roff + e];
        const int src = sr & 0xFFFFF, r = sr >> 20;
        float l = qrow[r * 16 + h]
                + g_qk[(size_t)src * 128 + r * 16 + 8 + h] + at * ceh;
        l = (l >= 0.f) ? l : 0.2f * l;
        const float w = __expf(l - m) * sinv;
        const float w0 = __shfl_sync(0xffffffffu, w, hw0);
        const float w1 = __shfl_sync(0xffffffffu, w, hw0 + 2);
        const float w2 = __shfl_sync(0xffffffffu, w, hw0 + 4);
        const float w3 = __shfl_sync(0xffffffffu, w, hw0 + 6);
        const float4* t4 = (const float4*)(g_t + ((size_t)r * NN + src) * HID);
        const float4 t0 = t4[lane], t1 = t4[lane + 32], t2 = t4[lane + 64], t3 = t4[lane + 96];
        a0.x += w0 * t0.x; a0.y += w0 * t0.y; a0.z += w0 * t0.z; a0.w += w0 * t0.w;
        a1.x += w1 * t1.x; a1.y += w1 * t1.y; a1.z += w1 * t1.z; a1.w += w1 * t1.w;
        a2.x += w2 * t2.x; a2.y += w2 * t2.y; a2.z += w2 * t2.z; a2.w += w2 * t2.w;
        a3.x += w3 * t3.x; a3.y += w3 * t3.y; a3.z += w3 * t3.z; a3.w += w3 * t3.w;
    }

    if (concat) {
        const float4* b4 = (const float4*)b;
        float4* o4 = (float4*)(g_h + (size_t)d * HID);
        float4 v;
        v = b4[lane];      o4[lane]      = make_float4(a0.x + v.x, a0.y + v.y, a0.z + v.z, a0.w + v.w);
        v = b4[lane + 32]; o4[lane + 32] = make_float4(a1.x + v.x, a1.y + v.y, a1.z + v.z, a1.w + v.w);
        v = b4[lane + 64]; o4[lane + 64] = make_float4(a2.x + v.x, a2.y + v.y, a2.z + v.z, a2.w + v.w);
        v = b4[lane + 96]; o4[lane + 96] = make_float4(a3.x + v.x, a3.y + v.y, a3.z + v.z, a3.w + v.w);
    } else {
        float4 s1 = make_float4(a0.x + a1.x + a2.x + a3.x,
                                a0.y + a1.y + a2.y + a3.y,
                                a0.z + a1.z + a2.z + a3.z,
                                a0.w + a1.w + a2.w + a3.w);
        s1.x += __shfl_xor_sync(0xffffffffu, s1.x, 16);
        s1.y += __shfl_xor_sync(0xffffffffu, s1.y, 16);
        s1.z += __shfl_xor_sync(0xffffffffu, s1.z, 16);
        s1.w += __shfl_xor_sync(0xffffffffu, s1.w, 16);
        if (lane < 16) {
            const float4 bv = ((const float4*)b)[lane];
            ((float4*)(out + (size_t)d * OC))[lane] =
                make_float4(s1.x * 0.125f + bv.x, s1.y * 0.125f + bv.y,
                            s1.z * 0.125f + bv.z, s1.w * 0.125f + bv.w);
        }
    }
}

// ---------------- host driver ------------------------------------------------
extern "C" void kernel_launch(void* const* d_in, const int* in_sizes, int n_in,
                              void* d_out, int out_size) {
    const float* x   = (const float*)d_in[0];
    const int*   ei  = (const int*)  d_in[1];
    const int*   ety = (const int*)  d_in[2];
    const float* ea  = (const float*)d_in[3];
    const float* W1  = (const float*)d_in[4];
    const float* q1  = (const float*)d_in[5];
    const float* k1  = (const float*)d_in[6];
    const float* We1 = (const float*)d_in[7];
    const float* e1  = (const float*)d_in[8];
    const float* b1  = (const float*)d_in[9];
    const float* W2  = (const float*)d_in[10];
    const float* q2  = (const float*)d_in[11];
    const float* k2  = (const float*)d_in[12];
    const float* We2 = (const float*)d_in[13];
    const float* e2  = (const float*)d_in[14];
    const float* b2  = (const float*)d_in[15];

    const int E0   = in_sizes[2];
    const int Etot = E0 + NN;

    float *p_t = nullptr, *p_h = nullptr;
    cudaGetSymbolAddress((void**)&p_t, g_t);
    cudaGetSymbolAddress((void**)&p_h, g_h);

    const dim3 gw(2 * RR, NN / 128);       // cp GEMM: (n_half | r<<1, m_tile)
    const dim3 gq(1, NN / 128);
    const int  eB   = (Etot + 255) / 256;
    const int  fagB = (NN * 32) / 256;

    init_kernel<<<(NN + 255) / 256, 256>>>();
    etmax_kernel<<<256, 256>>>(ety, E0);
    hist_kernel<<<eB, 256>>>(ei, E0, Etot);

    // ---------------- layer 1 (concat) ----------------
    convA_kernel<<<dim3(F1 / 32, NN / 32), 256>>>(x, F1);
    convB_kernel<<<(RR * F1 * HID + 255) / 256, 256>>>(W1, RR * F1 * HID);
    gemm_cp_kernel<<<gw, 256>>>(p_t, F1, F1 * HID, NN * HID);
    scan_kernel<<<1, 1024>>>();
    scatter_kernel<<<eB, 256>>>(ei, ety, ea, E0, Etot);
    packqk_kernel<<<RR * F1 / 8, 256>>>(W1, q1, k1, F1);
    ce_kernel<<<1, 256>>>(We1, e1);
    qkgemm_l1_kernel<<<gq, 256>>>(x, F1);
    fagg_kernel<<<fagB, 256>>>(b1, nullptr, 1);

    // ---------------- layer 2 (mean) ------------------
    convA_kernel<<<dim3(HID / 32, NN / 32), 256>>>(p_h, HID);
    convB_kernel<<<(RR * HID * HID + 255) / 256, 256>>>(W2, RR * HID * HID);
    gemm_cp_kernel<<<gw, 256>>>(p_t, HID, HID * HID, NN * HID);
    packqk_kernel<<<RR * HID / 8, 256>>>(W2, q2, k2, HID);
    ce_kernel<<<1, 256>>>(We2, e2);
    qkgemm_l2_kernel<<<gq, 256>>>(HID);
    fagg_kernel<<<fagB, 256>>>(b2, (float*)d_out, 0);
}

// round 9
// speedup vs baseline: 4.7653x; 1.1465x over previous
#include <cuda_runtime.h>
#include <cstdint>

// Problem dimensions (fixed by the dataset)
#define NN   16000          // nodes
#define F1   256            // layer-1 input features
#define HID  512            // HEADS*OUT
#define NH   8              // heads
#define OC   64             // per-head out channels
#define RR   8              // relations
#define ECAP 300000         // capacity for edges + self loops

// ---------------- scratch (device globals; no allocation allowed) ----------
__device__ float    g_t[(size_t)RR * NN * HID];   // relation-transformed nodes [R,N,512]
__device__ float    g_h[(size_t)NN * HID];        // layer-1 output
__device__ float    g_qk[(size_t)NN * 128];       // [node][r*16 + (q:0-7 | k:8-15)]
__device__ float    g_wqk[(size_t)HID * 128];     // folded W@q / W@k weights
__device__ float    g_ce[NH];                     // (We @ e)[h]
__device__ uint32_t g_At[(size_t)HID * NN];       // tf32 bits, [K][M] m-interleaved
__device__ uint32_t g_Bt[(size_t)RR * HID * HID]; // tf32 bits, [r][k][n]
__device__ int      g_etmax;
__device__ int      g_hist[NN];
__device__ int      g_rowptr[NN + 1];
__device__ int      g_cursor[NN];
__device__ int      g_csr_sr[ECAP];               // src | (rel << 20)
__device__ float    g_csr_attr[ECAP];

// ---------------- helpers ---------------------------------------------------
__device__ __forceinline__ uint32_t f2tf(float f) {
    uint32_t u;
    asm("cvt.rna.tf32.f32 %0, %1;" : "=r"(u) : "f"(f));
    return u;
}
__device__ __forceinline__ void mma_tf32(float c[4], const uint32_t a[4], const uint32_t b[2]) {
    asm volatile("mma.sync.aligned.m16n8k8.row.col.f32.tf32.tf32.f32 "
                 "{%0,%1,%2,%3}, {%4,%5,%6,%7}, {%8,%9}, {%0,%1,%2,%3};"
                 : "+f"(c[0]), "+f"(c[1]), "+f"(c[2]), "+f"(c[3])
                 : "r"(a[0]), "r"(a[1]), "r"(a[2]), "r"(a[3]), "r"(b[0]), "r"(b[1]));
}
__device__ __forceinline__ uint32_t s2u(const void* p) {
    uint32_t a;
    asm("{.reg .u64 t; cvta.to.shared.u64 t, %1; cvt.u32.u64 %0, t;}" : "=r"(a) : "l"(p));
    return a;
}
__device__ __forceinline__ void cp16(uint32_t saddr, const void* g) {
    asm volatile("cp.async.cg.shared.global [%0], [%1], 16;" :: "r"(saddr), "l"(g));
}
#define CP_COMMIT() asm volatile("cp.async.commit_group;")
#define CP_WAIT1()  asm volatile("cp.async.wait_group 1;")

// ---------------- CSR build --------------------------------------------------
__global__ void init_kernel() {
    int i = blockIdx.x * blockDim.x + threadIdx.x;
    if (i < NN) g_hist[i] = 0;
    if (i == 0) g_etmax = 0;
}

__global__ void etmax_kernel(const int* __restrict__ et, int E0) {
    int i = blockIdx.x * blockDim.x + threadIdx.x;
    int loc = -1;
    for (; i < E0; i += gridDim.x * blockDim.x) loc = max(loc, et[i]);
    if (loc >= 0) atomicMax(&g_etmax, loc);
}

__global__ void hist_kernel(const int* __restrict__ ei, int E0, int Etot) {
    int e = blockIdx.x * blockDim.x + threadIdx.x;
    if (e >= Etot) return;
    int d = (e < E0) ? ei[E0 + e] : (e - E0);
    atomicAdd(&g_hist[d], 1);
}

__global__ __launch_bounds__(1024)
void scan_kernel() {
    __shared__ int sm[1024];
    const int t = threadIdx.x;
    const int base = t * 16;
    int loc[16];
    int sum = 0;
#pragma unroll
    for (int i = 0; i < 16; i++) {
        int idx = base + i;
        int v = (idx < NN) ? g_hist[idx] : 0;
        loc[i] = sum;
        sum += v;
    }
    sm[t] = sum;
    __syncthreads();
    for (int off = 1; off < 1024; off <<= 1) {
        int v = (t >= off) ? sm[t - off] : 0;
        __syncthreads();
        sm[t] += v;
        __syncthreads();
    }
    int pre = (t > 0) ? sm[t - 1] : 0;
#pragma unroll
    for (int i = 0; i < 16; i++) {
        int idx = base + i;
        if (idx < NN) {
            g_rowptr[idx] = pre + loc[i];
            g_cursor[idx] = pre + loc[i];
        }
    }
    if (t == 1023) g_rowptr[NN] = sm[1023];
}

__global__ void scatter_kernel(const int* __restrict__ ei, const int* __restrict__ etyp,
                               const float* __restrict__ ea, int E0, int Etot) {
    int e = blockIdx.x * blockDim.x + threadIdx.x;
    if (e >= Etot) return;
    int s, d, r;  float at;
    if (e < E0) { s = ei[e]; d = ei[E0 + e]; r = etyp[e]; at = ea[e]; }
    else        { s = d = e - E0; r = (g_etmax + 1) & (RR - 1); at = 0.5f; }
    int p = atomicAdd(&g_cursor[d], 1);
    g_csr_sr[p]   = s | (r << 20);
    g_csr_attr[p] = at;
}

// ---------------- operand conversion ----------------------------------------
// A: [M][K] fp32 -> g_At [K][M] tf32 bits, m-interleaved within 16-groups.
__global__ __launch_bounds__(256)
void convA_kernel(const float* __restrict__ A, int K) {
    __shared__ float sm[32][33];
    const int tx = threadIdx.x & 31, ty = threadIdx.x >> 5;   // 32 x 8
    const int k0 = blockIdx.x * 32, m0 = blockIdx.y * 32;
#pragma unroll
    for (int j = 0; j < 4; j++)
        sm[ty + 8 * j][tx] = A[(size_t)(m0 + ty + 8 * j) * K + k0 + tx];
    __syncthreads();
    const int lm   = m0 + tx;
    const int mperm = (lm & ~15) | (((lm & 7) << 1) | ((lm >> 3) & 1));
#pragma unroll
    for (int j = 0; j < 4; j++)
        g_At[(size_t)(k0 + ty + 8 * j) * NN + mperm] = f2tf(sm[tx][ty + 8 * j]);
}

// B: elementwise fp32 -> tf32 bits (layout unchanged)
__global__ __launch_bounds__(256)
void convB_kernel(const float* __restrict__ B, int n) {
    int i = blockIdx.x * blockDim.x + threadIdx.x;
    if (i < n) g_Bt[i] = f2tf(B[i]);
}

// ============ cp.async GEMM: 128x256 block, 64x64 warp tiles, BK=16 ==========
// 8 warps = 2(m) x 4(n). 3 stages x BK=16, ONE __syncthreads per iteration.
// As [k][m-int] stride 136; Bs [k][n] stride 264 (== 8 mod 32). tf32 pre-conv.
#define GSMEM_WORDS (3 * 16 * 136 + 3 * 16 * 264)
__global__ __launch_bounds__(256, 1)
void gemm_cp_kernel(float* __restrict__ C0, int K, int rstrideB, int rstrideC) {
    extern __shared__ __align__(16) uint32_t smem[];
    uint32_t (*As)[16][136] = (uint32_t (*)[16][136])smem;
    uint32_t (*Bs)[16][264] = (uint32_t (*)[16][264])(smem + 3 * 16 * 136);

    const int r  = blockIdx.x >> 1;
    const int n0 = (blockIdx.x & 1) * 256;
    const int m0 = blockIdx.y * 128;
    const uint32_t* Bt = g_Bt + (size_t)r * rstrideB;
    float*          C  = C0 + (size_t)r * rstrideC;

    const int tid  = threadIdx.x;
    const int lane = tid & 31, warp = tid >> 5;
    const int grp  = lane >> 2, tig = lane & 3;
    const int wm   = (warp & 1) * 64;
    const int wn   = (warp >> 1) * 64;

    // loader mapping: row = k within stage (0..15), col4 = 4-word column
    const int lrow = tid >> 4;          // 0..15
    const int col4 = (tid & 15) * 4;    // 0..60

    const uint32_t* Ag = g_At + (size_t)lrow * NN + m0 + col4;
    const uint32_t* Bg = Bt  + (size_t)lrow * 512 + n0 + col4;

    uint32_t sA[3], sB[3];
#pragma unroll
    for (int st = 0; st < 3; st++) {
        sA[st] = s2u(&As[st][lrow][col4]);
        sB[st] = s2u(&Bs[st][lrow][col4]);
    }

    float c[4][8][4];
#pragma unroll
    for (int mt = 0; mt < 4; mt++)
#pragma unroll
        for (int nt = 0; nt < 8; nt++)
#pragma unroll
            for (int i = 0; i < 4; i++) c[mt][nt][i] = 0.f;

    const int NSTEP = K >> 4;
    // prologue: stages 0,1
#pragma unroll
    for (int st = 0; st < 2; st++) {
        const size_t k0 = (size_t)st * 16;
        cp16(sA[st],       Ag + k0 * NN);
        cp16(sA[st] + 256, Ag + k0 * NN + 64);
        cp16(sB[st],        Bg + k0 * 512);
        cp16(sB[st] + 256,  Bg + k0 * 512 + 64);
        cp16(sB[st] + 512,  Bg + k0 * 512 + 128);
        cp16(sB[st] + 768,  Bg + k0 * 512 + 192);
        CP_COMMIT();
    }

    int buf = 0;
    for (int s = 0; s < NSTEP; s++) {
        CP_WAIT1();
        __syncthreads();        // stage s ready; all warps done with stage s-1
        if (s + 2 < NSTEP) {
            const int st = (s + 2) % 3;
            const size_t k0 = (size_t)(s + 2) * 16;
            cp16(sA[st],       Ag + k0 * NN);
            cp16(sA[st] + 256, Ag + k0 * NN + 64);
            cp16(sB[st],        Bg + k0 * 512);
            cp16(sB[st] + 256,  Bg + k0 * 512 + 64);
            cp16(sB[st] + 512,  Bg + k0 * 512 + 128);
            cp16(sB[st] + 768,  Bg + k0 * 512 + 192);
        }
        CP_COMMIT();            // commit every iter keeps group count in sync

#pragma unroll
        for (int kb = 0; kb < 16; kb += 8) {
            uint32_t af[4][4], bf[8][2];
#pragma unroll
            for (int mt = 0; mt < 4; mt++) {
                const int mcol = wm + mt * 16 + 2 * grp;
                const uint2 p0 = *(const uint2*)&As[buf][kb + tig][mcol];
                const uint2 p1 = *(const uint2*)&As[buf][kb + tig + 4][mcol];
                af[mt][0] = p0.x; af[mt][1] = p0.y;
                af[mt][2] = p1.x; af[mt][3] = p1.y;
            }
#pragma unroll
            for (int nt = 0; nt < 8; nt++) {
                const int nc = wn + nt * 8 + grp;
                bf[nt][0] = Bs[buf][kb + tig][nc];
                bf[nt][1] = Bs[buf][kb + tig + 4][nc];
            }
#pragma unroll
            for (int mt = 0; mt < 4; mt++)
#pragma unroll
                for (int nt = 0; nt < 8; nt++)
                    mma_tf32(c[mt][nt], af[mt], bf[nt]);
        }
        buf = (buf + 1 == 3) ? 0 : buf + 1;
    }

#pragma unroll
    for (int mt = 0; mt < 4; mt++) {
        const int row = m0 + wm + mt * 16 + grp;
#pragma unroll
        for (int nt = 0; nt < 8; nt++) {
            const int col = n0 + wn + nt * 8 + tig * 2;
            *(float2*)(C + (size_t)row * 512 + col)       = make_float2(c[mt][nt][0], c[mt][nt][1]);
            *(float2*)(C + (size_t)(row + 8) * 512 + col) = make_float2(c[mt][nt][2], c[mt][nt][3]);
        }
    }
}

// ---------------- narrow GEMM (128x128) for q/k projection -------------------
__device__ __forceinline__ void gemm_tf32_body(
    const float* __restrict__ A, const float* __restrict__ B,
    float* __restrict__ C, int K, int m0, int n0, int ldb, int ldc)
{
    __shared__ __align__(16) uint32_t As[2][16][136];
    __shared__ __align__(16) uint32_t Bs[2][16][136];

    const int tid  = threadIdx.x;
    const int lane = tid & 31, warp = tid >> 5;
    const int grp  = lane >> 2, tig = lane & 3;
    const int wm   = (warp & 3) * 32;
    const int wn   = (warp >> 2) * 64;

    const int am   = tid & 127;
    const int amp  = (am & 0x70) | ((am & 7) << 1) | ((am >> 3) & 1);
    const int akq0 = tid >> 7;
    const int akq1 = akq0 + 2;
    const int bn4  = tid & 31;
    const int bk0  = tid >> 5;
    const int bk1  = bk0 + 8;

    const float* Ag0 = A + (size_t)(m0 + am) * K + 4 * akq0;
    const float* Ag1 = A + (size_t)(m0 + am) * K + 4 * akq1;
    const float* Bg0 = B + (size_t)bk0 * ldb + n0 + 4 * bn4;
    const float* Bg1 = B + (size_t)bk1 * ldb + n0 + 4 * bn4;

    float c[2][8][4];
#pragma unroll
    for (int mt = 0; mt < 2; mt++)
#pragma unroll
        for (int nt = 0; nt < 8; nt++)
#pragma unroll
            for (int i = 0; i < 4; i++) c[mt][nt][i] = 0.f;

    float4 a0v = *(const float4*)Ag0;
    float4 a1v = *(const float4*)Ag1;
    float4 b0v = *(const float4*)Bg0;
    float4 b1v = *(const float4*)Bg1;
    As[0][4 * akq0 + 0][amp] = f2tf(a0v.x); As[0][4 * akq0 + 1][amp] = f2tf(a0v.y);
    As[0][4 * akq0 + 2][amp] = f2tf(a0v.z); As[0][4 * akq0 + 3][amp] = f2tf(a0v.w);
    As[0][4 * akq1 + 0][amp] = f2tf(a1v.x); As[0][4 * akq1 + 1][amp] = f2tf(a1v.y);
    As[0][4 * akq1 + 2][amp] = f2tf(a1v.z); As[0][4 * akq1 + 3][amp] = f2tf(a1v.w);
    *(uint4*)&Bs[0][bk0][4 * bn4] = make_uint4(f2tf(b0v.x), f2tf(b0v.y), f2tf(b0v.z), f2tf(b0v.w));
    *(uint4*)&Bs[0][bk1][4 * bn4] = make_uint4(f2tf(b1v.x), f2tf(b1v.y), f2tf(b1v.z), f2tf(b1v.w));
    __syncthreads();

    int buf = 0;
    const int NSTEP = K >> 4;
    for (int s = 0; s < NSTEP; s++) {
        const bool nxt = (s + 1) < NSTEP;
        if (nxt) {
            const int ko = (s + 1) << 4;
            a0v = *(const float4*)(Ag0 + ko);
            a1v = *(const float4*)(Ag1 + ko);
            b0v = *(const float4*)(Bg0 + (size_t)ko * ldb);
            b1v = *(const float4*)(Bg1 + (size_t)ko * ldb);
        }
#pragma unroll
        for (int kb = 0; kb < 16; kb += 8) {
            uint32_t af[2][4], bf[8][2];
#pragma unroll
            for (int mt = 0; mt < 2; mt++) {
                const int mcol = wm + mt * 16 + 2 * grp;
                const uint2 p0 = *(const uint2*)&As[buf][kb + tig][mcol];
                const uint2 p1 = *(const uint2*)&As[buf][kb + tig + 4][mcol];
                af[mt][0] = p0.x; af[mt][1] = p0.y;
                af[mt][2] = p1.x; af[mt][3] = p1.y;
            }
#pragma unroll
            for (int nt = 0; nt < 8; nt++) {
                const int nc = wn + nt * 8 + grp;
                bf[nt][0] = Bs[buf][kb + tig][nc];
                bf[nt][1] = Bs[buf][kb + tig + 4][nc];
            }
#pragma unroll
            for (int mt = 0; mt < 2; mt++)
#pragma unroll
                for (int nt = 0; nt < 8; nt++)
                    mma_tf32(c[mt][nt], af[mt], bf[nt]);
        }
        if (nxt) {
            const int nb = buf ^ 1;
            As[nb][4 * akq0 + 0][amp] = f2tf(a0v.x); As[nb][4 * akq0 + 1][amp] = f2tf(a0v.y);
            As[nb][4 * akq0 + 2][amp] = f2tf(a0v.z); As[nb][4 * akq0 + 3][amp] = f2tf(a0v.w);
            As[nb][4 * akq1 + 0][amp] = f2tf(a1v.x); As[nb][4 * akq1 + 1][amp] = f2tf(a1v.y);
            As[nb][4 * akq1 + 2][amp] = f2tf(a1v.z); As[nb][4 * akq1 + 3][amp] = f2tf(a1v.w);
            *(uint4*)&Bs[nb][bk0][4 * bn4] = make_uint4(f2tf(b0v.x), f2tf(b0v.y), f2tf(b0v.z), f2tf(b0v.w));
            *(uint4*)&Bs[nb][bk1][4 * bn4] = make_uint4(f2tf(b1v.x), f2tf(b1v.y), f2tf(b1v.z), f2tf(b1v.w));
            __syncthreads();
            buf = nb;
        }
    }

#pragma unroll
    for (int mt = 0; mt < 2; mt++) {
        const int row = m0 + wm + mt * 16 + grp;
#pragma unroll
        for (int nt = 0; nt < 8; nt++) {
            const int col = n0 + wn + nt * 8 + tig * 2;
            *(float2*)(C + (size_t)row * ldc + col)       = make_float2(c[mt][nt][0], c[mt][nt][1]);
            *(float2*)(C + (size_t)(row + 8) * ldc + col) = make_float2(c[mt][nt][2], c[mt][nt][3]);
        }
    }
}

// q/k projection GEMM: [NN x K] @ [K x 128] -> g_qk [NN x 128]
__global__ __launch_bounds__(256, 2)
void qkgemm_l1_kernel(const float* __restrict__ A, int K) {
    gemm_tf32_body(A, g_wqk, g_qk, K, blockIdx.y * 128, 0, 128, 128);
}
__global__ __launch_bounds__(256, 2)
void qkgemm_l2_kernel(int K) {
    gemm_tf32_body(g_h, g_wqk, g_qk, K, blockIdx.y * 128, 0, 128, 128);
}

// ---------------- fold weights: g_wqk[j][r*16+h]=W[r]@q, +8: W[r]@k ----------
__global__ __launch_bounds__(256)
void packqk_kernel(const float* __restrict__ W, const float* __restrict__ q,
                   const float* __restrict__ k, int K) {
    const int gw = (blockIdx.x * blockDim.x + threadIdx.x) >> 5;
    if (gw >= RR * K) return;
    const int r = gw / K, j = gw - r * K;
    const int lane = threadIdx.x & 31;
    const float4* w4 = (const float4*)(W + ((size_t)r * K + j) * HID);
    const float4* q4 = (const float4*)q;
    const float4* k4 = (const float4*)k;
    float aq[NH], ak[NH];
#pragma unroll
    for (int h = 0; h < NH; h++) { aq[h] = 0.f; ak[h] = 0.f; }
#pragma unroll
    for (int i = 0; i < 4; i++) {
        const int c4 = lane + 32 * i;
        const float4 wv = w4[c4];
        const float wa[4] = {wv.x, wv.y, wv.z, wv.w};
#pragma unroll
        for (int f = 0; f < 4; f++) {
            const int c = 4 * c4 + f;
            const float4 qa = q4[c * 2], qb = q4[c * 2 + 1];
            const float4 ka = k4[c * 2], kb = k4[c * 2 + 1];
            const float w = wa[f];
            aq[0] += w * qa.x; aq[1] += w * qa.y; aq[2] += w * qa.z; aq[3] += w * qa.w;
            aq[4] += w * qb.x; aq[5] += w * qb.y; aq[6] += w * qb.z; aq[7] += w * qb.w;
            ak[0] += w * ka.x; ak[1] += w * ka.y; ak[2] += w * ka.z; ak[3] += w * ka.w;
            ak[4] += w * kb.x; ak[5] += w * kb.y; ak[6] += w * kb.z; ak[7] += w * kb.w;
        }
    }
#pragma unroll
    for (int h = 0; h < NH; h++) {
#pragma unroll
        for (int o = 16; o; o >>= 1) {
            aq[h] += __shfl_xor_sync(0xffffffffu, aq[h], o);
            ak[h] += __shfl_xor_sync(0xffffffffu, ak[h], o);
        }
    }
    if (lane == 0) {
        float* dst = g_wqk + (size_t)j * 128 + r * 16;
#pragma unroll
        for (int h = 0; h < NH; h++) {
            dst[h]      = aq[h];
            dst[8 + h]  = ak[h];
        }
    }
}

// ---------------- ce[h] = sum_j We[j] * e[j][h] (warp per head) --------------
__global__ void ce_kernel(const float* __restrict__ We, const float* __restrict__ e) {
    const int warp = threadIdx.x >> 5, lane = threadIdx.x & 31;
    float s = 0.f;
    for (int j = lane; j < HID; j += 32) s += We[j] * e[j * NH + warp];
#pragma unroll
    for (int o = 16; o; o >>= 1) s += __shfl_xor_sync(0xffffffffu, s, o);
    if (lane == 0) g_ce[warp] = s;
}

// ---------------- fused softmax + aggregation: warp per destination ----------
__global__ __launch_bounds__(256)
void fagg_kernel(const float* __restrict__ b, float* __restrict__ out, int concat) {
    const int d = (blockIdx.x * blockDim.x + threadIdx.x) >> 5;
    if (d >= NN) return;
    const int lane = threadIdx.x & 31;
    const int h = lane & 7;
    const int roff = g_rowptr[d];
    const int deg  = g_rowptr[d + 1] - roff;
    const float ceh = g_ce[h];
    const float* qrow = g_qk + (size_t)d * 128;

    // ---- phase A: per-head online softmax stats ----
    float m = -1e30f, s = 0.f;
    for (int base = 0; base < deg; base += 4) {
        const int e = base + (lane >> 3);
        if (e < deg) {
            const int   sr = g_csr_sr[roff + e];
            const float at = g_csr_attr[roff + e];
            const int src = sr & 0xFFFFF, r = sr >> 20;
            float l = qrow[r * 16 + h]
                    + g_qk[(size_t)src * 128 + r * 16 + 8 + h] + at * ceh;
            l = (l >= 0.f) ? l : 0.2f * l;
            const float mn = fmaxf(m, l);
            s = s * __expf(m - mn) + __expf(l - mn);
            m = mn;
        }
    }
#pragma unroll
    for (int off = 8; off < 32; off <<= 1) {
        const float om = __shfl_xor_sync(0xffffffffu, m, off);
        const float os = __shfl_xor_sync(0xffffffffu, s, off);
        const float mn = fmaxf(m, om);
        s = s * __expf(m - mn) + os * __expf(om - mn);
        m = mn;
    }
    const float sinv = 1.f / (s + 1e-16f);

    // ---- phase B: weighted aggregation ----
    float4 a0 = make_float4(0, 0, 0, 0), a1 = a0, a2 = a0, a3 = a0;
    const int hw0 = lane >> 4;
    for (int e = 0; e < deg; e++) {
        const int   sr = g_csr_sr[roff + e];
        const float at = g_csr_attr[roff + e];
        const int src = sr & 0xFFFFF, r = sr >> 20;
        float l = qrow[r * 16 + h]
                + g_qk[(size_t)src * 128 + r * 16 + 8 + h] + at * ceh;
        l = (l >= 0.f) ? l : 0.2f * l;
        const float w = __expf(l - m) * sinv;
        const float w0 = __shfl_sync(0xffffffffu, w, hw0);
        const float w1 = __shfl_sync(0xffffffffu, w, hw0 + 2);
        const float w2 = __shfl_sync(0xffffffffu, w, hw0 + 4);
        const float w3 = __shfl_sync(0xffffffffu, w, hw0 + 6);
        const float4* t4 = (const float4*)(g_t + ((size_t)r * NN + src) * HID);
        const float4 t0 = t4[lane], t1 = t4[lane + 32], t2 = t4[lane + 64], t3 = t4[lane + 96];
        a0.x += w0 * t0.x; a0.y += w0 * t0.y; a0.z += w0 * t0.z; a0.w += w0 * t0.w;
        a1.x += w1 * t1.x; a1.y += w1 * t1.y; a1.z += w1 * t1.z; a1.w += w1 * t1.w;
        a2.x += w2 * t2.x; a2.y += w2 * t2.y; a2.z += w2 * t2.z; a2.w += w2 * t2.w;
        a3.x += w3 * t3.x; a3.y += w3 * t3.y; a3.z += w3 * t3.z; a3.w += w3 * t3.w;
    }

    if (concat) {
        const float4* b4 = (const float4*)b;
        float4* o4 = (float4*)(g_h + (size_t)d * HID);
        float4 v;
        v = b4[lane];      o4[lane]      = make_float4(a0.x + v.x, a0.y + v.y, a0.z + v.z, a0.w + v.w);
        v = b4[lane + 32]; o4[lane + 32] = make_float4(a1.x + v.x, a1.y + v.y, a1.z + v.z, a1.w + v.w);
        v = b4[lane + 64]; o4[lane + 64] = make_float4(a2.x + v.x, a2.y + v.y, a2.z + v.z, a2.w + v.w);
        v = b4[lane + 96]; o4[lane + 96] = make_float4(a3.x + v.x, a3.y + v.y, a3.z + v.z, a3.w + v.w);
    } else {
        float4 s1 = make_float4(a0.x + a1.x + a2.x + a3.x,
                                a0.y + a1.y + a2.y + a3.y,
                                a0.z + a1.z + a2.z + a3.z,
                                a0.w + a1.w + a2.w + a3.w);
        s1.x += __shfl_xor_sync(0xffffffffu, s1.x, 16);
        s1.y += __shfl_xor_sync(0xffffffffu, s1.y, 16);
        s1.z += __shfl_xor_sync(0xffffffffu, s1.z, 16);
        s1.w += __shfl_xor_sync(0xffffffffu, s1.w, 16);
        if (lane < 16) {
            const float4 bv = ((const float4*)b)[lane];
            ((float4*)(out + (size_t)d * OC))[lane] =
                make_float4(s1.x * 0.125f + bv.x, s1.y * 0.125f + bv.y,
                            s1.z * 0.125f + bv.z, s1.w * 0.125f + bv.w);
        }
    }
}

// ---------------- host driver ------------------------------------------------
extern "C" void kernel_launch(void* const* d_in, const int* in_sizes, int n_in,
                              void* d_out, int out_size) {
    const float* x   = (const float*)d_in[0];
    const int*   ei  = (const int*)  d_in[1];
    const int*   ety = (const int*)  d_in[2];
    const float* ea  = (const float*)d_in[3];
    const float* W1  = (const float*)d_in[4];
    const float* q1  = (const float*)d_in[5];
    const float* k1  = (const float*)d_in[6];
    const float* We1 = (const float*)d_in[7];
    const float* e1  = (const float*)d_in[8];
    const float* b1  = (const float*)d_in[9];
    const float* W2  = (const float*)d_in[10];
    const float* q2  = (const float*)d_in[11];
    const float* k2  = (const float*)d_in[12];
    const float* We2 = (const float*)d_in[13];
    const float* e2  = (const float*)d_in[14];
    const float* b2  = (const float*)d_in[15];

    const int E0   = in_sizes[2];
    const int Etot = E0 + NN;

    float *p_t = nullptr, *p_h = nullptr;
    cudaGetSymbolAddress((void**)&p_t, g_t);
    cudaGetSymbolAddress((void**)&p_h, g_h);

    const int GS = GSMEM_WORDS * 4;   // 76800 bytes dynamic smem
    cudaFuncSetAttribute(gemm_cp_kernel,
                         cudaFuncAttributeMaxDynamicSharedMemorySize, GS);

    const dim3 gw(2 * RR, NN / 128);       // cp GEMM: (n_half | r<<1, m_tile)
    const dim3 gq(1, NN / 128);
    const int  eB   = (Etot + 255) / 256;
    const int  fagB = (NN * 32) / 256;

    // ---------------- layer 1 (concat); gemm_cp at launch index 3 for ncu ----
    convA_kernel<<<dim3(F1 / 32, NN / 32), 256>>>(x, F1);
    convB_kernel<<<(RR * F1 * HID + 255) / 256, 256>>>(W1, RR * F1 * HID);
    init_kernel<<<(NN + 255) / 256, 256>>>();
    gemm_cp_kernel<<<gw, 256, GS>>>(p_t, F1, F1 * HID, NN * HID);
    etmax_kernel<<<256, 256>>>(ety, E0);
    hist_kernel<<<eB, 256>>>(ei, E0, Etot);
    scan_kernel<<<1, 1024>>>();
    scatter_kernel<<<eB, 256>>>(ei, ety, ea, E0, Etot);
    packqk_kernel<<<RR * F1 / 8, 256>>>(W1, q1, k1, F1);
    ce_kernel<<<1, 256>>>(We1, e1);
    qkgemm_l1_kernel<<<gq, 256>>>(x, F1);
    fagg_kernel<<<fagB, 256>>>(b1, nullptr, 1);

    // ---------------- layer 2 (mean) ------------------
    convA_kernel<<<dim3(HID / 32, NN / 32), 256>>>(p_h, HID);
    convB_kernel<<<(RR * HID * HID + 255) / 256, 256>>>(W2, RR * HID * HID);
    gemm_cp_kernel<<<gw, 256, GS>>>(p_t, HID, HID * HID, NN * HID);
    packqk_kernel<<<RR * HID / 8, 256>>>(W2, q2, k2, HID);
    ce_kernel<<<1, 256>>>(We2, e2);
    qkgemm_l2_kernel<<<gq, 256>>>(HID);
    fagg_kernel<<<fagB, 256>>>(b2, (float*)d_out, 0);
}

// round 10
// speedup vs baseline: 4.8357x; 1.0148x over previous
#include <cuda_runtime.h>
#include <cstdint>

// Problem dimensions (fixed by the dataset)
#define NN   16000          // nodes
#define F1   256            // layer-1 input features
#define HID  512            // HEADS*OUT
#define NH   8              // heads
#define OC   64             // per-head out channels
#define RR   8              // relations
#define ECAP 300000         // capacity for edges + self loops

// ---------------- scratch (device globals; no allocation allowed) ----------
__device__ float    g_t[(size_t)RR * NN * HID];   // relation-transformed nodes [R,N,512]
__device__ float    g_h[(size_t)NN * HID];        // layer-1 output
__device__ float    g_qk[(size_t)NN * 128];       // [node][r*16 + (q:0-7 | k:8-15)]
__device__ float    g_wqk[(size_t)HID * 128];     // folded W@q / W@k weights
__device__ float    g_ce[NH];                     // (We @ e)[h]
__device__ uint32_t g_At[(size_t)HID * NN];       // tf32 bits, [K][M] m-interleaved
__device__ uint32_t g_Bt[(size_t)RR * HID * HID]; // tf32 bits, [r][k][n]
__device__ int      g_etmax;
__device__ int      g_hist[NN];
__device__ int      g_rowptr[NN + 1];
__device__ int      g_cursor[NN];
__device__ int      g_csr_sr[ECAP];               // src | (rel << 20)
__device__ float    g_csr_attr[ECAP];

// ---------------- helpers ---------------------------------------------------
__device__ __forceinline__ uint32_t f2tf(float f) {
    uint32_t u;
    asm("cvt.rna.tf32.f32 %0, %1;" : "=r"(u) : "f"(f));
    return u;
}
__device__ __forceinline__ void mma_tf32(float c[4], const uint32_t a[4], const uint32_t b[2]) {
    asm volatile("mma.sync.aligned.m16n8k8.row.col.f32.tf32.tf32.f32 "
                 "{%0,%1,%2,%3}, {%4,%5,%6,%7}, {%8,%9}, {%0,%1,%2,%3};"
                 : "+f"(c[0]), "+f"(c[1]), "+f"(c[2]), "+f"(c[3])
                 : "r"(a[0]), "r"(a[1]), "r"(a[2]), "r"(a[3]), "r"(b[0]), "r"(b[1]));
}
__device__ __forceinline__ uint32_t s2u(const void* p) {
    uint32_t a;
    asm("{.reg .u64 t; cvta.to.shared.u64 t, %1; cvt.u32.u64 %0, t;}" : "=r"(a) : "l"(p));
    return a;
}
__device__ __forceinline__ void cp16(uint32_t saddr, const void* g) {
    asm volatile("cp.async.cg.shared.global [%0], [%1], 16;" :: "r"(saddr), "l"(g));
}
#define CP_COMMIT() asm volatile("cp.async.commit_group;")
#define CP_WAIT1()  asm volatile("cp.async.wait_group 1;")

// ---------------- CSR build --------------------------------------------------
__global__ void init_kernel() {
    int i = blockIdx.x * blockDim.x + threadIdx.x;
    if (i < NN) g_hist[i] = 0;
    if (i == 0) g_etmax = 0;
}

__global__ void etmax_kernel(const int* __restrict__ et, int E0) {
    int i = blockIdx.x * blockDim.x + threadIdx.x;
    int loc = -1;
    for (; i < E0; i += gridDim.x * blockDim.x) loc = max(loc, et[i]);
    if (loc >= 0) atomicMax(&g_etmax, loc);
}

__global__ void hist_kernel(const int* __restrict__ ei, int E0, int Etot) {
    int e = blockIdx.x * blockDim.x + threadIdx.x;
    if (e >= Etot) return;
    int d = (e < E0) ? ei[E0 + e] : (e - E0);
    atomicAdd(&g_hist[d], 1);
}

__global__ __launch_bounds__(1024)
void scan_kernel() {
    __shared__ int sm[1024];
    const int t = threadIdx.x;
    const int base = t * 16;
    int loc[16];
    int sum = 0;
#pragma unroll
    for (int i = 0; i < 16; i++) {
        int idx = base + i;
        int v = (idx < NN) ? g_hist[idx] : 0;
        loc[i] = sum;
        sum += v;
    }
    sm[t] = sum;
    __syncthreads();
    for (int off = 1; off < 1024; off <<= 1) {
        int v = (t >= off) ? sm[t - off] : 0;
        __syncthreads();
        sm[t] += v;
        __syncthreads();
    }
    int pre = (t > 0) ? sm[t - 1] : 0;
#pragma unroll
    for (int i = 0; i < 16; i++) {
        int idx = base + i;
        if (idx < NN) {
            g_rowptr[idx] = pre + loc[i];
            g_cursor[idx] = pre + loc[i];
        }
    }
    if (t == 1023) g_rowptr[NN] = sm[1023];
}

__global__ void scatter_kernel(const int* __restrict__ ei, const int* __restrict__ etyp,
                               const float* __restrict__ ea, int E0, int Etot) {
    int e = blockIdx.x * blockDim.x + threadIdx.x;
    if (e >= Etot) return;
    int s, d, r;  float at;
    if (e < E0) { s = ei[e]; d = ei[E0 + e]; r = etyp[e]; at = ea[e]; }
    else        { s = d = e - E0; r = (g_etmax + 1) & (RR - 1); at = 0.5f; }
    int p = atomicAdd(&g_cursor[d], 1);
    g_csr_sr[p]   = s | (r << 20);
    g_csr_attr[p] = at;
}

// ---------------- operand conversion ----------------------------------------
// A: [M][K] fp32 -> g_At [K][M] tf32 bits, m-interleaved within 16-groups.
__global__ __launch_bounds__(256)
void convA_kernel(const float* __restrict__ A, int K) {
    __shared__ float sm[32][33];
    const int tx = threadIdx.x & 31, ty = threadIdx.x >> 5;   // 32 x 8
    const int k0 = blockIdx.x * 32, m0 = blockIdx.y * 32;
#pragma unroll
    for (int j = 0; j < 4; j++)
        sm[ty + 8 * j][tx] = A[(size_t)(m0 + ty + 8 * j) * K + k0 + tx];
    __syncthreads();
    const int lm   = m0 + tx;
    const int mperm = (lm & ~15) | (((lm & 7) << 1) | ((lm >> 3) & 1));
#pragma unroll
    for (int j = 0; j < 4; j++)
        g_At[(size_t)(k0 + ty + 8 * j) * NN + mperm] = f2tf(sm[tx][ty + 8 * j]);
}

// B: elementwise fp32 -> tf32 bits (layout unchanged)
__global__ __launch_bounds__(256)
void convB_kernel(const float* __restrict__ B, int n) {
    int i = blockIdx.x * blockDim.x + threadIdx.x;
    if (i < n) g_Bt[i] = f2tf(B[i]);
}

// ============ cp.async GEMM: 128x256 block, 64x64 warp tiles, BK=32 ==========
// 8 warps = 2(m) x 4(n). 3 stages x BK=32, ONE __syncthreads per iteration.
// As [k][m-int] stride 136; Bs [k][n] stride 264 (== 8 mod 32). tf32 pre-conv.
#define GSMEM_WORDS (3 * 32 * 136 + 3 * 32 * 264)
__global__ __launch_bounds__(256, 1)
void gemm_cp_kernel(float* __restrict__ C0, int K, int rstrideB, int rstrideC) {
    extern __shared__ __align__(16) uint32_t smem[];
    uint32_t (*As)[32][136] = (uint32_t (*)[32][136])smem;
    uint32_t (*Bs)[32][264] = (uint32_t (*)[32][264])(smem + 3 * 32 * 136);

    const int r  = blockIdx.x >> 1;
    const int n0 = (blockIdx.x & 1) * 256;
    const int m0 = blockIdx.y * 128;
    const uint32_t* Bt = g_Bt + (size_t)r * rstrideB;
    float*          C  = C0 + (size_t)r * rstrideC;

    const int tid  = threadIdx.x;
    const int lane = tid & 31, warp = tid >> 5;
    const int grp  = lane >> 2, tig = lane & 3;
    const int wm   = (warp & 1) * 64;
    const int wn   = (warp >> 1) * 64;

    // loader mapping: row = k within stage (0..31), lcol = 4-word column base
    const int lrow = tid >> 3;          // 0..31
    const int lcol = (tid & 7) * 4;     // 0..28

    const uint32_t* Ag = g_At + (size_t)lrow * NN + m0 + lcol;
    const uint32_t* Bg = Bt  + (size_t)lrow * 512 + n0 + lcol;

    uint32_t sA[3], sB[3];
#pragma unroll
    for (int st = 0; st < 3; st++) {
        sA[st] = s2u(&As[st][lrow][lcol]);
        sB[st] = s2u(&Bs[st][lrow][lcol]);
    }

    float c[4][8][4];
#pragma unroll
    for (int mt = 0; mt < 4; mt++)
#pragma unroll
        for (int nt = 0; nt < 8; nt++)
#pragma unroll
            for (int i = 0; i < 4; i++) c[mt][nt][i] = 0.f;

    const int NSTEP = K >> 5;
    // prologue: stages 0,1
#pragma unroll
    for (int st = 0; st < 2; st++) {
        const size_t k0 = (size_t)st * 32;
#pragma unroll
        for (int j = 0; j < 4; j++)
            cp16(sA[st] + j * 128, Ag + k0 * NN + j * 32);
#pragma unroll
        for (int j = 0; j < 8; j++)
            cp16(sB[st] + j * 128, Bg + k0 * 512 + j * 32);
        CP_COMMIT();
    }

    int buf = 0;
    for (int s = 0; s < NSTEP; s++) {
        CP_WAIT1();
        __syncthreads();        // stage s ready; all warps done with stage s-1
        if (s + 2 < NSTEP) {
            const int st = (s + 2) % 3;
            const size_t k0 = (size_t)(s + 2) * 32;
#pragma unroll
            for (int j = 0; j < 4; j++)
                cp16(sA[st] + j * 128, Ag + k0 * NN + j * 32);
#pragma unroll
            for (int j = 0; j < 8; j++)
                cp16(sB[st] + j * 128, Bg + k0 * 512 + j * 32);
        }
        CP_COMMIT();            // commit every iter keeps group count in sync

#pragma unroll
        for (int kb = 0; kb < 32; kb += 8) {
            uint32_t af[4][4], bf[8][2];
#pragma unroll
            for (int mt = 0; mt < 4; mt++) {
                const int mcol = wm + mt * 16 + 2 * grp;
                const uint2 p0 = *(const uint2*)&As[buf][kb + tig][mcol];
                const uint2 p1 = *(const uint2*)&As[buf][kb + tig + 4][mcol];
                af[mt][0] = p0.x; af[mt][1] = p0.y;
                af[mt][2] = p1.x; af[mt][3] = p1.y;
            }
#pragma unroll
            for (int nt = 0; nt < 8; nt++) {
                const int nc = wn + nt * 8 + grp;
                bf[nt][0] = Bs[buf][kb + tig][nc];
                bf[nt][1] = Bs[buf][kb + tig + 4][nc];
            }
#pragma unroll
            for (int mt = 0; mt < 4; mt++)
#pragma unroll
                for (int nt = 0; nt < 8; nt++)
                    mma_tf32(c[mt][nt], af[mt], bf[nt]);
        }
        buf = (buf + 1 == 3) ? 0 : buf + 1;
    }

#pragma unroll
    for (int mt = 0; mt < 4; mt++) {
        const int row = m0 + wm + mt * 16 + grp;
#pragma unroll
        for (int nt = 0; nt < 8; nt++) {
            const int col = n0 + wn + nt * 8 + tig * 2;
            *(float2*)(C + (size_t)row * 512 + col)       = make_float2(c[mt][nt][0], c[mt][nt][1]);
            *(float2*)(C + (size_t)(row + 8) * 512 + col) = make_float2(c[mt][nt][2], c[mt][nt][3]);
        }
    }
}

// ---------------- narrow GEMM (128x128) for q/k projection -------------------
__device__ __forceinline__ void gemm_tf32_body(
    const float* __restrict__ A, const float* __restrict__ B,
    float* __restrict__ C, int K, int m0, int n0, int ldb, int ldc)
{
    __shared__ __align__(16) uint32_t As[2][16][136];
    __shared__ __align__(16) uint32_t Bs[2][16][136];

    const int tid  = threadIdx.x;
    const int lane = tid & 31, warp = tid >> 5;
    const int grp  = lane >> 2, tig = lane & 3;
    const int wm   = (warp & 3) * 32;
    const int wn   = (warp >> 2) * 64;

    const int am   = tid & 127;
    const int amp  = (am & 0x70) | ((am & 7) << 1) | ((am >> 3) & 1);
    const int akq0 = tid >> 7;
    const int akq1 = akq0 + 2;
    const int bn4  = tid & 31;
    const int bk0  = tid >> 5;
    const int bk1  = bk0 + 8;

    const float* Ag0 = A + (size_t)(m0 + am) * K + 4 * akq0;
    const float* Ag1 = A + (size_t)(m0 + am) * K + 4 * akq1;
    const float* Bg0 = B + (size_t)bk0 * ldb + n0 + 4 * bn4;
    const float* Bg1 = B + (size_t)bk1 * ldb + n0 + 4 * bn4;

    float c[2][8][4];
#pragma unroll
    for (int mt = 0; mt < 2; mt++)
#pragma unroll
        for (int nt = 0; nt < 8; nt++)
#pragma unroll
            for (int i = 0; i < 4; i++) c[mt][nt][i] = 0.f;

    float4 a0v = *(const float4*)Ag0;
    float4 a1v = *(const float4*)Ag1;
    float4 b0v = *(const float4*)Bg0;
    float4 b1v = *(const float4*)Bg1;
    As[0][4 * akq0 + 0][amp] = f2tf(a0v.x); As[0][4 * akq0 + 1][amp] = f2tf(a0v.y);
    As[0][4 * akq0 + 2][amp] = f2tf(a0v.z); As[0][4 * akq0 + 3][amp] = f2tf(a0v.w);
    As[0][4 * akq1 + 0][amp] = f2tf(a1v.x); As[0][4 * akq1 + 1][amp] = f2tf(a1v.y);
    As[0][4 * akq1 + 2][amp] = f2tf(a1v.z); As[0][4 * akq1 + 3][amp] = f2tf(a1v.w);
    *(uint4*)&Bs[0][bk0][4 * bn4] = make_uint4(f2tf(b0v.x), f2tf(b0v.y), f2tf(b0v.z), f2tf(b0v.w));
    *(uint4*)&Bs[0][bk1][4 * bn4] = make_uint4(f2tf(b1v.x), f2tf(b1v.y), f2tf(b1v.z), f2tf(b1v.w));
    __syncthreads();

    int buf = 0;
    const int NSTEP = K >> 4;
    for (int s = 0; s < NSTEP; s++) {
        const bool nxt = (s + 1) < NSTEP;
        if (nxt) {
            const int ko = (s + 1) << 4;
            a0v = *(const float4*)(Ag0 + ko);
            a1v = *(const float4*)(Ag1 + ko);
            b0v = *(const float4*)(Bg0 + (size_t)ko * ldb);
            b1v = *(const float4*)(Bg1 + (size_t)ko * ldb);
        }
#pragma unroll
        for (int kb = 0; kb < 16; kb += 8) {
            uint32_t af[2][4], bf[8][2];
#pragma unroll
            for (int mt = 0; mt < 2; mt++) {
                const int mcol = wm + mt * 16 + 2 * grp;
                const uint2 p0 = *(const uint2*)&As[buf][kb + tig][mcol];
                const uint2 p1 = *(const uint2*)&As[buf][kb + tig + 4][mcol];
                af[mt][0] = p0.x; af[mt][1] = p0.y;
                af[mt][2] = p1.x; af[mt][3] = p1.y;
            }
#pragma unroll
            for (int nt = 0; nt < 8; nt++) {
                const int nc = wn + nt * 8 + grp;
                bf[nt][0] = Bs[buf][kb + tig][nc];
                bf[nt][1] = Bs[buf][kb + tig + 4][nc];
            }
#pragma unroll
            for (int mt = 0; mt < 2; mt++)
#pragma unroll
                for (int nt = 0; nt < 8; nt++)
                    mma_tf32(c[mt][nt], af[mt], bf[nt]);
        }
        if (nxt) {
            const int nb = buf ^ 1;
            As[nb][4 * akq0 + 0][amp] = f2tf(a0v.x); As[nb][4 * akq0 + 1][amp] = f2tf(a0v.y);
            As[nb][4 * akq0 + 2][amp] = f2tf(a0v.z); As[nb][4 * akq0 + 3][amp] = f2tf(a0v.w);
            As[nb][4 * akq1 + 0][amp] = f2tf(a1v.x); As[nb][4 * akq1 + 1][amp] = f2tf(a1v.y);
            As[nb][4 * akq1 + 2][amp] = f2tf(a1v.z); As[nb][4 * akq1 + 3][amp] = f2tf(a1v.w);
            *(uint4*)&Bs[nb][bk0][4 * bn4] = make_uint4(f2tf(b0v.x), f2tf(b0v.y), f2tf(b0v.z), f2tf(b0v.w));
            *(uint4*)&Bs[nb][bk1][4 * bn4] = make_uint4(f2tf(b1v.x), f2tf(b1v.y), f2tf(b1v.z), f2tf(b1v.w));
            __syncthreads();
            buf = nb;
        }
    }

#pragma unroll
    for (int mt = 0; mt < 2; mt++) {
        const int row = m0 + wm + mt * 16 + grp;
#pragma unroll
        for (int nt = 0; nt < 8; nt++) {
            const int col = n0 + wn + nt * 8 + tig * 2;
            *(float2*)(C + (size_t)row * ldc + col)       = make_float2(c[mt][nt][0], c[mt][nt][1]);
            *(float2*)(C + (size_t)(row + 8) * ldc + col) = make_float2(c[mt][nt][2], c[mt][nt][3]);
        }
    }
}

// q/k projection GEMM: [NN x K] @ [K x 128] -> g_qk [NN x 128]
__global__ __launch_bounds__(256, 2)
void qkgemm_l1_kernel(const float* __restrict__ A, int K) {
    gemm_tf32_body(A, g_wqk, g_qk, K, blockIdx.y * 128, 0, 128, 128);
}
__global__ __launch_bounds__(256, 2)
void qkgemm_l2_kernel(int K) {
    gemm_tf32_body(g_h, g_wqk, g_qk, K, blockIdx.y * 128, 0, 128, 128);
}

// ---------------- fold weights: g_wqk[j][r*16+h]=W[r]@q, +8: W[r]@k ----------
__global__ __launch_bounds__(256)
void packqk_kernel(const float* __restrict__ W, const float* __restrict__ q,
                   const float* __restrict__ k, int K) {
    const int gw = (blockIdx.x * blockDim.x + threadIdx.x) >> 5;
    if (gw >= RR * K) return;
    const int r = gw / K, j = gw - r * K;
    const int lane = threadIdx.x & 31;
    const float4* w4 = (const float4*)(W + ((size_t)r * K + j) * HID);
    const float4* q4 = (const float4*)q;
    const float4* k4 = (const float4*)k;
    float aq[NH], ak[NH];
#pragma unroll
    for (int h = 0; h < NH; h++) { aq[h] = 0.f; ak[h] = 0.f; }
#pragma unroll
    for (int i = 0; i < 4; i++) {
        const int c4 = lane + 32 * i;
        const float4 wv = w4[c4];
        const float wa[4] = {wv.x, wv.y, wv.z, wv.w};
#pragma unroll
        for (int f = 0; f < 4; f++) {
            const int c = 4 * c4 + f;
            const float4 qa = q4[c * 2], qb = q4[c * 2 + 1];
            const float4 ka = k4[c * 2], kb = k4[c * 2 + 1];
            const float w = wa[f];
            aq[0] += w * qa.x; aq[1] += w * qa.y; aq[2] += w * qa.z; aq[3] += w * qa.w;
            aq[4] += w * qb.x; aq[5] += w * qb.y; aq[6] += w * qb.z; aq[7] += w * qb.w;
            ak[0] += w * ka.x; ak[1] += w * ka.y; ak[2] += w * ka.z; ak[3] += w * ka.w;
            ak[4] += w * kb.x; ak[5] += w * kb.y; ak[6] += w * kb.z; ak[7] += w * kb.w;
        }
    }
#pragma unroll
    for (int h = 0; h < NH; h++) {
#pragma unroll
        for (int o = 16; o; o >>= 1) {
            aq[h] += __shfl_xor_sync(0xffffffffu, aq[h], o);
            ak[h] += __shfl_xor_sync(0xffffffffu, ak[h], o);
        }
    }
    if (lane == 0) {
        float* dst = g_wqk + (size_t)j * 128 + r * 16;
#pragma unroll
        for (int h = 0; h < NH; h++) {
            dst[h]      = aq[h];
            dst[8 + h]  = ak[h];
        }
    }
}

// ---------------- ce[h] = sum_j We[j] * e[j][h] (warp per head) --------------
__global__ void ce_kernel(const float* __restrict__ We, const float* __restrict__ e) {
    const int warp = threadIdx.x >> 5, lane = threadIdx.x & 31;
    float s = 0.f;
    for (int j = lane; j < HID; j += 32) s += We[j] * e[j * NH + warp];
#pragma unroll
    for (int o = 16; o; o >>= 1) s += __shfl_xor_sync(0xffffffffu, s, o);
    if (lane == 0) g_ce[warp] = s;
}

// ---------------- fused softmax + aggregation: warp per destination ----------
__global__ __launch_bounds__(256)
void fagg_kernel(const float* __restrict__ b, float* __restrict__ out, int concat) {
    const int d = (blockIdx.x * blockDim.x + threadIdx.x) >> 5;
    if (d >= NN) return;
    const int lane = threadIdx.x & 31;
    const int h = lane & 7;
    const int roff = g_rowptr[d];
    const int deg  = g_rowptr[d + 1] - roff;
    const float ceh = g_ce[h];
    const float* qrow = g_qk + (size_t)d * 128;

    // ---- phase A: per-head online softmax stats ----
    float m = -1e30f, s = 0.f;
    for (int base = 0; base < deg; base += 4) {
        const int e = base + (lane >> 3);
        if (e < deg) {
            const int   sr = g_csr_sr[roff + e];
            const float at = g_csr_attr[roff + e];
            const int src = sr & 0xFFFFF, r = sr >> 20;
            float l = qrow[r * 16 + h]
                    + g_qk[(size_t)src * 128 + r * 16 + 8 + h] + at * ceh;
            l = (l >= 0.f) ? l : 0.2f * l;
            const float mn = fmaxf(m, l);
            s = s * __expf(m - mn) + __expf(l - mn);
            m = mn;
        }
    }
#pragma unroll
    for (int off = 8; off < 32; off <<= 1) {
        const float om = __shfl_xor_sync(0xffffffffu, m, off);
        const float os = __shfl_xor_sync(0xffffffffu, s, off);
        const float mn = fmaxf(m, om);
        s = s * __expf(m - mn) + os * __expf(om - mn);
        m = mn;
    }
    const float sinv = 1.f / (s + 1e-16f);

    // ---- phase B: weighted aggregation ----
    float4 a0 = make_float4(0, 0, 0, 0), a1 = a0, a2 = a0, a3 = a0;
    const int hw0 = lane >> 4;
    for (int e = 0; e < deg; e++) {
        const int   sr = g_csr_sr[roff + e];
        const float at = g_csr_attr[roff + e];
        const int src = sr & 0xFFFFF, r = sr >> 20;
        float l = qrow[r * 16 + h]
                + g_qk[(size_t)src * 128 + r * 16 + 8 + h] + at * ceh;
        l = (l >= 0.f) ? l : 0.2f * l;
        const float w = __expf(l - m) * sinv;
        const float w0 = __shfl_sync(0xffffffffu, w, hw0);
        const float w1 = __shfl_sync(0xffffffffu, w, hw0 + 2);
        const float w2 = __shfl_sync(0xffffffffu, w, hw0 + 4);
        const float w3 = __shfl_sync(0xffffffffu, w, hw0 + 6);
        const float4* t4 = (const float4*)(g_t + ((size_t)r * NN + src) * HID);
        const float4 t0 = t4[lane], t1 = t4[lane + 32], t2 = t4[lane + 64], t3 = t4[lane + 96];
        a0.x += w0 * t0.x; a0.y += w0 * t0.y; a0.z += w0 * t0.z; a0.w += w0 * t0.w;
        a1.x += w1 * t1.x; a1.y += w1 * t1.y; a1.z += w1 * t1.z; a1.w += w1 * t1.w;
        a2.x += w2 * t2.x; a2.y += w2 * t2.y; a2.z += w2 * t2.z; a2.w += w2 * t2.w;
        a3.x += w3 * t3.x; a3.y += w3 * t3.y; a3.z += w3 * t3.z; a3.w += w3 * t3.w;
    }

    if (concat) {
        const float4* b4 = (const float4*)b;
        float4* o4 = (float4*)(g_h + (size_t)d * HID);
        float4 v;
        v = b4[lane];      o4[lane]      = make_float4(a0.x + v.x, a0.y + v.y, a0.z + v.z, a0.w + v.w);
        v = b4[lane + 32]; o4[lane + 32] = make_float4(a1.x + v.x, a1.y + v.y, a1.z + v.z, a1.w + v.w);
        v = b4[lane + 64]; o4[lane + 64] = make_float4(a2.x + v.x, a2.y + v.y, a2.z + v.z, a2.w + v.w);
        v = b4[lane + 96]; o4[lane + 96] = make_float4(a3.x + v.x, a3.y + v.y, a3.z + v.z, a3.w + v.w);
    } else {
        float4 s1 = make_float4(a0.x + a1.x + a2.x + a3.x,
                                a0.y + a1.y + a2.y + a3.y,
                                a0.z + a1.z + a2.z + a3.z,
                                a0.w + a1.w + a2.w + a3.w);
        s1.x += __shfl_xor_sync(0xffffffffu, s1.x, 16);
        s1.y += __shfl_xor_sync(0xffffffffu, s1.y, 16);
        s1.z += __shfl_xor_sync(0xffffffffu, s1.z, 16);
        s1.w += __shfl_xor_sync(0xffffffffu, s1.w, 16);
        if (lane < 16) {
            const float4 bv = ((const float4*)b)[lane];
            ((float4*)(out + (size_t)d * OC))[lane] =
                make_float4(s1.x * 0.125f + bv.x, s1.y * 0.125f + bv.y,
                            s1.z * 0.125f + bv.z, s1.w * 0.125f + bv.w);
        }
    }
}

// ---------------- host driver ------------------------------------------------
extern "C" void kernel_launch(void* const* d_in, const int* in_sizes, int n_in,
                              void* d_out, int out_size) {
    const float* x   = (const float*)d_in[0];
    const int*   ei  = (const int*)  d_in[1];
    const int*   ety = (const int*)  d_in[2];
    const float* ea  = (const float*)d_in[3];
    const float* W1  = (const float*)d_in[4];
    const float* q1  = (const float*)d_in[5];
    const float* k1  = (const float*)d_in[6];
    const float* We1 = (const float*)d_in[7];
    const float* e1  = (const float*)d_in[8];
    const float* b1  = (const float*)d_in[9];
    const float* W2  = (const float*)d_in[10];
    const float* q2  = (const float*)d_in[11];
    const float* k2  = (const float*)d_in[12];
    const float* We2 = (const float*)d_in[13];
    const float* e2  = (const float*)d_in[14];
    const float* b2  = (const float*)d_in[15];

    const int E0   = in_sizes[2];
    const int Etot = E0 + NN;

    float *p_t = nullptr, *p_h = nullptr;
    cudaGetSymbolAddress((void**)&p_t, g_t);
    cudaGetSymbolAddress((void**)&p_h, g_h);

    const int GS = GSMEM_WORDS * 4;   // 153600 bytes dynamic smem
    cudaFuncSetAttribute(gemm_cp_kernel,
                         cudaFuncAttributeMaxDynamicSharedMemorySize, GS);

    const dim3 gw(2 * RR, NN / 128);       // cp GEMM: (n_half | r<<1, m_tile)
    const dim3 gq(1, NN / 128);
    const int  eB   = (Etot + 255) / 256;
    const int  fagB = (NN * 32) / 256;

    // ---------------- layer 1 (concat); gemm_cp at launch index 3 for ncu ----
    convA_kernel<<<dim3(F1 / 32, NN / 32), 256>>>(x, F1);
    convB_kernel<<<(RR * F1 * HID + 255) / 256, 256>>>(W1, RR * F1 * HID);
    init_kernel<<<(NN + 255) / 256, 256>>>();
    gemm_cp_kernel<<<gw, 256, GS>>>(p_t, F1, F1 * HID, NN * HID);
    etmax_kernel<<<256, 256>>>(ety, E0);
    hist_kernel<<<eB, 256>>>(ei, E0, Etot);
    scan_kernel<<<1, 1024>>>();
    scatter_kernel<<<eB, 256>>>(ei, ety, ea, E0, Etot);
    packqk_kernel<<<RR * F1 / 8, 256>>>(W1, q1, k1, F1);
    ce_kernel<<<1, 256>>>(We1, e1);
    qkgemm_l1_kernel<<<gq, 256>>>(x, F1);
    fagg_kernel<<<fagB, 256>>>(b1, nullptr, 1);

    // ---------------- layer 2 (mean) ------------------
    convA_kernel<<<dim3(HID / 32, NN / 32), 256>>>(p_h, HID);
    convB_kernel<<<(RR * HID * HID + 255) / 256, 256>>>(W2, RR * HID * HID);
    gemm_cp_kernel<<<gw, 256, GS>>>(p_t, HID, HID * HID, NN * HID);
    packqk_kernel<<<RR * HID / 8, 256>>>(W2, q2, k2, HID);
    ce_kernel<<<1, 256>>>(We2, e2);
    qkgemm_l2_kernel<<<gq, 256>>>(HID);
    fagg_kernel<<<fagB, 256>>>(b2, (float*)d_out, 0);
}

// round 11
// speedup vs baseline: 4.9752x; 1.0288x over previous
#include <cuda_runtime.h>
#include <cstdint>

// Problem dimensions (fixed by the dataset)
#define NN   16000          // nodes
#define F1   256            // layer-1 input features
#define HID  512            // HEADS*OUT
#define NH   8              // heads
#define OC   64             // per-head out channels
#define RR   8              // relations
#define ECAP 300000         // capacity for edges + self loops

// ---------------- scratch (device globals; no allocation allowed) ----------
__device__ float    g_t[(size_t)RR * NN * HID];   // relation-transformed nodes [R,N,512]
__device__ float    g_h[(size_t)NN * HID];        // layer-1 output
__device__ float    g_qk[(size_t)NN * 128];       // [node][r*16 + (q:0-7 | k:8-15)]
__device__ float    g_wqk[(size_t)HID * 128];     // folded W@q / W@k weights
__device__ float    g_ce[NH];                     // (We @ e)[h]
__device__ uint32_t g_At[(size_t)HID * NN];       // tf32 bits, [K][M] m-interleaved
__device__ uint32_t g_Bt[(size_t)RR * HID * HID]; // tf32 bits, [r][k][n]
__device__ int      g_etmax;
__device__ int      g_hist[NN];
__device__ int      g_rowptr[NN + 1];
__device__ int      g_cursor[NN];
__device__ int      g_csr_sr[ECAP];               // src | (rel << 20)
__device__ float    g_csr_attr[ECAP];

// ---------------- helpers ---------------------------------------------------
__device__ __forceinline__ uint32_t f2tf(float f) {
    uint32_t u;
    asm("cvt.rna.tf32.f32 %0, %1;" : "=r"(u) : "f"(f));
    return u;
}
__device__ __forceinline__ void mma_tf32(float c[4], const uint32_t a[4], const uint32_t b[2]) {
    asm volatile("mma.sync.aligned.m16n8k8.row.col.f32.tf32.tf32.f32 "
                 "{%0,%1,%2,%3}, {%4,%5,%6,%7}, {%8,%9}, {%0,%1,%2,%3};"
                 : "+f"(c[0]), "+f"(c[1]), "+f"(c[2]), "+f"(c[3])
                 : "r"(a[0]), "r"(a[1]), "r"(a[2]), "r"(a[3]), "r"(b[0]), "r"(b[1]));
}
__device__ __forceinline__ uint32_t s2u(const void* p) {
    uint32_t a;
    asm("{.reg .u64 t; cvta.to.shared.u64 t, %1; cvt.u32.u64 %0, t;}" : "=r"(a) : "l"(p));
    return a;
}
__device__ __forceinline__ void cp16(uint32_t saddr, const void* g) {
    asm volatile("cp.async.cg.shared.global [%0], [%1], 16;" :: "r"(saddr), "l"(g));
}
#define CP_COMMIT() asm volatile("cp.async.commit_group;")
#define CP_WAIT1()  asm volatile("cp.async.wait_group 1;")

// ---------------- CSR build --------------------------------------------------
__global__ void init_kernel() {
    int i = blockIdx.x * blockDim.x + threadIdx.x;
    if (i < NN) g_hist[i] = 0;
    if (i == 0) g_etmax = 0;
}

__global__ void etmax_kernel(const int* __restrict__ et, int E0) {
    int i = blockIdx.x * blockDim.x + threadIdx.x;
    int loc = -1;
    for (; i < E0; i += gridDim.x * blockDim.x) loc = max(loc, et[i]);
    if (loc >= 0) atomicMax(&g_etmax, loc);
}

__global__ void hist_kernel(const int* __restrict__ ei, int E0, int Etot) {
    int e = blockIdx.x * blockDim.x + threadIdx.x;
    if (e >= Etot) return;
    int d = (e < E0) ? ei[E0 + e] : (e - E0);
    atomicAdd(&g_hist[d], 1);
}

__global__ __launch_bounds__(1024)
void scan_kernel() {
    __shared__ int sm[1024];
    const int t = threadIdx.x;
    const int base = t * 16;
    int loc[16];
    int sum = 0;
#pragma unroll
    for (int i = 0; i < 16; i++) {
        int idx = base + i;
        int v = (idx < NN) ? g_hist[idx] : 0;
        loc[i] = sum;
        sum += v;
    }
    sm[t] = sum;
    __syncthreads();
    for (int off = 1; off < 1024; off <<= 1) {
        int v = (t >= off) ? sm[t - off] : 0;
        __syncthreads();
        sm[t] += v;
        __syncthreads();
    }
    int pre = (t > 0) ? sm[t - 1] : 0;
#pragma unroll
    for (int i = 0; i < 16; i++) {
        int idx = base + i;
        if (idx < NN) {
            g_rowptr[idx] = pre + loc[i];
            g_cursor[idx] = pre + loc[i];
        }
    }
    if (t == 1023) g_rowptr[NN] = sm[1023];
}

__global__ void scatter_kernel(const int* __restrict__ ei, const int* __restrict__ etyp,
                               const float* __restrict__ ea, int E0, int Etot) {
    int e = blockIdx.x * blockDim.x + threadIdx.x;
    if (e >= Etot) return;
    int s, d, r;  float at;
    if (e < E0) { s = ei[e]; d = ei[E0 + e]; r = etyp[e]; at = ea[e]; }
    else        { s = d = e - E0; r = (g_etmax + 1) & (RR - 1); at = 0.5f; }
    int p = atomicAdd(&g_cursor[d], 1);
    g_csr_sr[p]   = s | (r << 20);
    g_csr_attr[p] = at;
}

// ---------------- operand conversion ----------------------------------------
// A: [M][K] fp32 -> g_At [K][M] tf32 bits, m-interleaved within 16-groups.
__global__ __launch_bounds__(256)
void convA_kernel(const float* __restrict__ A, int K) {
    __shared__ float sm[32][33];
    const int tx = threadIdx.x & 31, ty = threadIdx.x >> 5;   // 32 x 8
    const int k0 = blockIdx.x * 32, m0 = blockIdx.y * 32;
#pragma unroll
    for (int j = 0; j < 4; j++)
        sm[ty + 8 * j][tx] = A[(size_t)(m0 + ty + 8 * j) * K + k0 + tx];
    __syncthreads();
    const int lm   = m0 + tx;
    const int mperm = (lm & ~15) | (((lm & 7) << 1) | ((lm >> 3) & 1));
#pragma unroll
    for (int j = 0; j < 4; j++)
        g_At[(size_t)(k0 + ty + 8 * j) * NN + mperm] = f2tf(sm[tx][ty + 8 * j]);
}

// B: elementwise fp32 -> tf32 bits (layout unchanged)
__global__ __launch_bounds__(256)
void convB_kernel(const float* __restrict__ B, int n) {
    int i = blockIdx.x * blockDim.x + threadIdx.x;
    if (i < n) g_Bt[i] = f2tf(B[i]);
}

// ===== cp.async GEMM: 128x128 block, 64x32 warp tiles, BK=32, 2 CTAs/SM =====
// 8 warps = 2(m) x 4(n). 3 stages x BK=32, ONE __syncthreads per iteration.
// As [k][m-int] stride 136; Bs [k][n] stride 136 (== 8 mod 32). tf32 pre-conv.
#define GSMEM_WORDS (3 * 32 * 136 * 2)
__global__ __launch_bounds__(256, 2)
void gemm_cp_kernel(float* __restrict__ C0, int K, int rstrideB, int rstrideC) {
    extern __shared__ __align__(16) uint32_t smem[];
    uint32_t (*As)[32][136] = (uint32_t (*)[32][136])smem;
    uint32_t (*Bs)[32][136] = (uint32_t (*)[32][136])(smem + 3 * 32 * 136);

    const int r  = blockIdx.x >> 2;
    const int n0 = (blockIdx.x & 3) * 128;
    const int m0 = blockIdx.y * 128;
    const uint32_t* Bt = g_Bt + (size_t)r * rstrideB;
    float*          C  = C0 + (size_t)r * rstrideC;

    const int tid  = threadIdx.x;
    const int lane = tid & 31, warp = tid >> 5;
    const int grp  = lane >> 2, tig = lane & 3;
    const int wm   = (warp & 1) * 64;
    const int wn   = (warp >> 1) * 32;

    // loader mapping: 256 threads cover 32x128 words via 4 passes of 8 rows
    const int arow = tid >> 5;          // 0..7
    const int acol = (tid & 31) * 4;    // 0..124

    const uint32_t* Ag = g_At + (size_t)arow * NN + m0 + acol;
    const uint32_t* Bg = Bt  + (size_t)arow * 512 + n0 + acol;

    uint32_t sA[3], sB[3];
#pragma unroll
    for (int st = 0; st < 3; st++) {
        sA[st] = s2u(&As[st][arow][acol]);
        sB[st] = s2u(&Bs[st][arow][acol]);
    }
    const int JSTRIDE = 8 * 136 * 4;    // 8 rows in bytes

    float c[4][4][4];
#pragma unroll
    for (int mt = 0; mt < 4; mt++)
#pragma unroll
        for (int nt = 0; nt < 4; nt++)
#pragma unroll
            for (int i = 0; i < 4; i++) c[mt][nt][i] = 0.f;

    const int NSTEP = K >> 5;
    // prologue: stages 0,1
#pragma unroll
    for (int st = 0; st < 2; st++) {
        const size_t k0 = (size_t)st * 32;
#pragma unroll
        for (int j = 0; j < 4; j++) {
            cp16(sA[st] + j * JSTRIDE, Ag + (k0 + 8 * j) * NN);
            cp16(sB[st] + j * JSTRIDE, Bg + (k0 + 8 * j) * 512);
        }
        CP_COMMIT();
    }

    int buf = 0;
    for (int s = 0; s < NSTEP; s++) {
        CP_WAIT1();
        __syncthreads();        // stage s ready; all warps done with stage s-1
        if (s + 2 < NSTEP) {
            const int st = (s + 2) % 3;
            const size_t k0 = (size_t)(s + 2) * 32;
#pragma unroll
            for (int j = 0; j < 4; j++) {
                cp16(sA[st] + j * JSTRIDE, Ag + (k0 + 8 * j) * NN);
                cp16(sB[st] + j * JSTRIDE, Bg + (k0 + 8 * j) * 512);
            }
        }
        CP_COMMIT();            // commit every iter keeps group count in sync

#pragma unroll
        for (int kb = 0; kb < 32; kb += 8) {
            uint32_t af[4][4], bf[4][2];
#pragma unroll
            for (int mt = 0; mt < 4; mt++) {
                const int mcol = wm + mt * 16 + 2 * grp;
                const uint2 p0 = *(const uint2*)&As[buf][kb + tig][mcol];
                const uint2 p1 = *(const uint2*)&As[buf][kb + tig + 4][mcol];
                af[mt][0] = p0.x; af[mt][1] = p0.y;
                af[mt][2] = p1.x; af[mt][3] = p1.y;
            }
#pragma unroll
            for (int nt = 0; nt < 4; nt++) {
                const int nc = wn + nt * 8 + grp;
                bf[nt][0] = Bs[buf][kb + tig][nc];
                bf[nt][1] = Bs[buf][kb + tig + 4][nc];
            }
#pragma unroll
            for (int mt = 0; mt < 4; mt++)
#pragma unroll
                for (int nt = 0; nt < 4; nt++)
                    mma_tf32(c[mt][nt], af[mt], bf[nt]);
        }
        buf = (buf + 1 == 3) ? 0 : buf + 1;
    }

#pragma unroll
    for (int mt = 0; mt < 4; mt++) {
        const int row = m0 + wm + mt * 16 + grp;
#pragma unroll
        for (int nt = 0; nt < 4; nt++) {
            const int col = n0 + wn + nt * 8 + tig * 2;
            *(float2*)(C + (size_t)row * 512 + col)       = make_float2(c[mt][nt][0], c[mt][nt][1]);
            *(float2*)(C + (size_t)(row + 8) * 512 + col) = make_float2(c[mt][nt][2], c[mt][nt][3]);
        }
    }
}

// ---------------- narrow GEMM (128x128) for q/k projection -------------------
__device__ __forceinline__ void gemm_tf32_body(
    const float* __restrict__ A, const float* __restrict__ B,
    float* __restrict__ C, int K, int m0, int n0, int ldb, int ldc)
{
    __shared__ __align__(16) uint32_t As[2][16][136];
    __shared__ __align__(16) uint32_t Bs[2][16][136];

    const int tid  = threadIdx.x;
    const int lane = tid & 31, warp = tid >> 5;
    const int grp  = lane >> 2, tig = lane & 3;
    const int wm   = (warp & 3) * 32;
    const int wn   = (warp >> 2) * 64;

    const int am   = tid & 127;
    const int amp  = (am & 0x70) | ((am & 7) << 1) | ((am >> 3) & 1);
    const int akq0 = tid >> 7;
    const int akq1 = akq0 + 2;
    const int bn4  = tid & 31;
    const int bk0  = tid >> 5;
    const int bk1  = bk0 + 8;

    const float* Ag0 = A + (size_t)(m0 + am) * K + 4 * akq0;
    const float* Ag1 = A + (size_t)(m0 + am) * K + 4 * akq1;
    const float* Bg0 = B + (size_t)bk0 * ldb + n0 + 4 * bn4;
    const float* Bg1 = B + (size_t)bk1 * ldb + n0 + 4 * bn4;

    float c[2][8][4];
#pragma unroll
    for (int mt = 0; mt < 2; mt++)
#pragma unroll
        for (int nt = 0; nt < 8; nt++)
#pragma unroll
            for (int i = 0; i < 4; i++) c[mt][nt][i] = 0.f;

    float4 a0v = *(const float4*)Ag0;
    float4 a1v = *(const float4*)Ag1;
    float4 b0v = *(const float4*)Bg0;
    float4 b1v = *(const float4*)Bg1;
    As[0][4 * akq0 + 0][amp] = f2tf(a0v.x); As[0][4 * akq0 + 1][amp] = f2tf(a0v.y);
    As[0][4 * akq0 + 2][amp] = f2tf(a0v.z); As[0][4 * akq0 + 3][amp] = f2tf(a0v.w);
    As[0][4 * akq1 + 0][amp] = f2tf(a1v.x); As[0][4 * akq1 + 1][amp] = f2tf(a1v.y);
    As[0][4 * akq1 + 2][amp] = f2tf(a1v.z); As[0][4 * akq1 + 3][amp] = f2tf(a1v.w);
    *(uint4*)&Bs[0][bk0][4 * bn4] = make_uint4(f2tf(b0v.x), f2tf(b0v.y), f2tf(b0v.z), f2tf(b0v.w));
    *(uint4*)&Bs[0][bk1][4 * bn4] = make_uint4(f2tf(b1v.x), f2tf(b1v.y), f2tf(b1v.z), f2tf(b1v.w));
    __syncthreads();

    int buf = 0;
    const int NSTEP = K >> 4;
    for (int s = 0; s < NSTEP; s++) {
        const bool nxt = (s + 1) < NSTEP;
        if (nxt) {
            const int ko = (s + 1) << 4;
            a0v = *(const float4*)(Ag0 + ko);
            a1v = *(const float4*)(Ag1 + ko);
            b0v = *(const float4*)(Bg0 + (size_t)ko * ldb);
            b1v = *(const float4*)(Bg1 + (size_t)ko * ldb);
        }
#pragma unroll
        for (int kb = 0; kb < 16; kb += 8) {
            uint32_t af[2][4], bf[8][2];
#pragma unroll
            for (int mt = 0; mt < 2; mt++) {
                const int mcol = wm + mt * 16 + 2 * grp;
                const uint2 p0 = *(const uint2*)&As[buf][kb + tig][mcol];
                const uint2 p1 = *(const uint2*)&As[buf][kb + tig + 4][mcol];
                af[mt][0] = p0.x; af[mt][1] = p0.y;
                af[mt][2] = p1.x; af[mt][3] = p1.y;
            }
#pragma unroll
            for (int nt = 0; nt < 8; nt++) {
                const int nc = wn + nt * 8 + grp;
                bf[nt][0] = Bs[buf][kb + tig][nc];
                bf[nt][1] = Bs[buf][kb + tig + 4][nc];
            }
#pragma unroll
            for (int mt = 0; mt < 2; mt++)
#pragma unroll
                for (int nt = 0; nt < 8; nt++)
                    mma_tf32(c[mt][nt], af[mt], bf[nt]);
        }
        if (nxt) {
            const int nb = buf ^ 1;
            As[nb][4 * akq0 + 0][amp] = f2tf(a0v.x); As[nb][4 * akq0 + 1][amp] = f2tf(a0v.y);
            As[nb][4 * akq0 + 2][amp] = f2tf(a0v.z); As[nb][4 * akq0 + 3][amp] = f2tf(a0v.w);
            As[nb][4 * akq1 + 0][amp] = f2tf(a1v.x); As[nb][4 * akq1 + 1][amp] = f2tf(a1v.y);
            As[nb][4 * akq1 + 2][amp] = f2tf(a1v.z); As[nb][4 * akq1 + 3][amp] = f2tf(a1v.w);
            *(uint4*)&Bs[nb][bk0][4 * bn4] = make_uint4(f2tf(b0v.x), f2tf(b0v.y), f2tf(b0v.z), f2tf(b0v.w));
            *(uint4*)&Bs[nb][bk1][4 * bn4] = make_uint4(f2tf(b1v.x), f2tf(b1v.y), f2tf(b1v.z), f2tf(b1v.w));
            __syncthreads();
            buf = nb;
        }
    }

#pragma unroll
    for (int mt = 0; mt < 2; mt++) {
        const int row = m0 + wm + mt * 16 + grp;
#pragma unroll
        for (int nt = 0; nt < 8; nt++) {
            const int col = n0 + wn + nt * 8 + tig * 2;
            *(float2*)(C + (size_t)row * ldc + col)       = make_float2(c[mt][nt][0], c[mt][nt][1]);
            *(float2*)(C + (size_t)(row + 8) * ldc + col) = make_float2(c[mt][nt][2], c[mt][nt][3]);
        }
    }
}

// q/k projection GEMM: [NN x K] @ [K x 128] -> g_qk [NN x 128]
__global__ __launch_bounds__(256, 2)
void qkgemm_l1_kernel(const float* __restrict__ A, int K) {
    gemm_tf32_body(A, g_wqk, g_qk, K, blockIdx.y * 128, 0, 128, 128);
}
__global__ __launch_bounds__(256, 2)
void qkgemm_l2_kernel(int K) {
    gemm_tf32_body(g_h, g_wqk, g_qk, K, blockIdx.y * 128, 0, 128, 128);
}

// ---------------- fold weights: g_wqk[j][r*16+h]=W[r]@q, +8: W[r]@k ----------
__global__ __launch_bounds__(256)
void packqk_kernel(const float* __restrict__ W, const float* __restrict__ q,
                   const float* __restrict__ k, int K) {
    const int gw = (blockIdx.x * blockDim.x + threadIdx.x) >> 5;
    if (gw >= RR * K) return;
    const int r = gw / K, j = gw - r * K;
    const int lane = threadIdx.x & 31;
    const float4* w4 = (const float4*)(W + ((size_t)r * K + j) * HID);
    const float4* q4 = (const float4*)q;
    const float4* k4 = (const float4*)k;
    float aq[NH], ak[NH];
#pragma unroll
    for (int h = 0; h < NH; h++) { aq[h] = 0.f; ak[h] = 0.f; }
#pragma unroll
    for (int i = 0; i < 4; i++) {
        const int c4 = lane + 32 * i;
        const float4 wv = w4[c4];
        const float wa[4] = {wv.x, wv.y, wv.z, wv.w};
#pragma unroll
        for (int f = 0; f < 4; f++) {
            const int c = 4 * c4 + f;
            const float4 qa = q4[c * 2], qb = q4[c * 2 + 1];
            const float4 ka = k4[c * 2], kb = k4[c * 2 + 1];
            const float w = wa[f];
            aq[0] += w * qa.x; aq[1] += w * qa.y; aq[2] += w * qa.z; aq[3] += w * qa.w;
            aq[4] += w * qb.x; aq[5] += w * qb.y; aq[6] += w * qb.z; aq[7] += w * qb.w;
            ak[0] += w * ka.x; ak[1] += w * ka.y; ak[2] += w * ka.z; ak[3] += w * ka.w;
            ak[4] += w * kb.x; ak[5] += w * kb.y; ak[6] += w * kb.z; ak[7] += w * kb.w;
        }
    }
#pragma unroll
    for (int h = 0; h < NH; h++) {
#pragma unroll
        for (int o = 16; o; o >>= 1) {
            aq[h] += __shfl_xor_sync(0xffffffffu, aq[h], o);
            ak[h] += __shfl_xor_sync(0xffffffffu, ak[h], o);
        }
    }
    if (lane == 0) {
        float* dst = g_wqk + (size_t)j * 128 + r * 16;
#pragma unroll
        for (int h = 0; h < NH; h++) {
            dst[h]      = aq[h];
            dst[8 + h]  = ak[h];
        }
    }
}

// ---------------- ce[h] = sum_j We[j] * e[j][h] (warp per head) --------------
__global__ void ce_kernel(const float* __restrict__ We, const float* __restrict__ e) {
    const int warp = threadIdx.x >> 5, lane = threadIdx.x & 31;
    float s = 0.f;
    for (int j = lane; j < HID; j += 32) s += We[j] * e[j * NH + warp];
#pragma unroll
    for (int o = 16; o; o >>= 1) s += __shfl_xor_sync(0xffffffffu, s, o);
    if (lane == 0) g_ce[warp] = s;
}

// ---------------- fused softmax + aggregation: warp per destination ----------
__global__ __launch_bounds__(256)
void fagg_kernel(const float* __restrict__ b, float* __restrict__ out, int concat) {
    const int d = (blockIdx.x * blockDim.x + threadIdx.x) >> 5;
    if (d >= NN) return;
    const int lane = threadIdx.x & 31;
    const int h = lane & 7;
    const int roff = g_rowptr[d];
    const int deg  = g_rowptr[d + 1] - roff;
    const float ceh = g_ce[h];
    const float* qrow = g_qk + (size_t)d * 128;

    // ---- phase A: per-head online softmax stats ----
    float m = -1e30f, s = 0.f;
    for (int base = 0; base < deg; base += 4) {
        const int e = base + (lane >> 3);
        if (e < deg) {
            const int   sr = g_csr_sr[roff + e];
            const float at = g_csr_attr[roff + e];
            const int src = sr & 0xFFFFF, r = sr >> 20;
            float l = qrow[r * 16 + h]
                    + g_qk[(size_t)src * 128 + r * 16 + 8 + h] + at * ceh;
            l = (l >= 0.f) ? l : 0.2f * l;
            const float mn = fmaxf(m, l);
            s = s * __expf(m - mn) + __expf(l - mn);
            m = mn;
        }
    }
#pragma unroll
    for (int off = 8; off < 32; off <<= 1) {
        const float om = __shfl_xor_sync(0xffffffffu, m, off);
        const float os = __shfl_xor_sync(0xffffffffu, s, off);
        const float mn = fmaxf(m, om);
        s = s * __expf(m - mn) + os * __expf(om - mn);
        m = mn;
    }
    const float sinv = 1.f / (s + 1e-16f);

    // ---- phase B: weighted aggregation ----
    float4 a0 = make_float4(0, 0, 0, 0), a1 = a0, a2 = a0, a3 = a0;
    const int hw0 = lane >> 4;
    for (int e = 0; e < deg; e++) {
        const int   sr = g_csr_sr[roff + e];
        const float at = g_csr_attr[roff + e];
        const int src = sr & 0xFFFFF, r = sr >> 20;
        float l = qrow[r * 16 + h]
                + g_qk[(size_t)src * 128 + r * 16 + 8 + h] + at * ceh;
        l = (l >= 0.f) ? l : 0.2f * l;
        const float w = __expf(l - m) * sinv;
        const float w0 = __shfl_sync(0xffffffffu, w, hw0);
        const float w1 = __shfl_sync(0xffffffffu, w, hw0 + 2);
        const float w2 = __shfl_sync(0xffffffffu, w, hw0 + 4);
        const float w3 = __shfl_sync(0xffffffffu, w, hw0 + 6);
        const float4* t4 = (const float4*)(g_t + ((size_t)r * NN + src) * HID);
        const float4 t0 = t4[lane], t1 = t4[lane + 32], t2 = t4[lane + 64], t3 = t4[lane + 96];
        a0.x += w0 * t0.x; a0.y += w0 * t0.y; a0.z += w0 * t0.z; a0.w += w0 * t0.w;
        a1.x += w1 * t1.x; a1.y += w1 * t1.y; a1.z += w1 * t1.z; a1.w += w1 * t1.w;
        a2.x += w2 * t2.x; a2.y += w2 * t2.y; a2.z += w2 * t2.z; a2.w += w2 * t2.w;
        a3.x += w3 * t3.x; a3.y += w3 * t3.y; a3.z += w3 * t3.z; a3.w += w3 * t3.w;
    }

    if (concat) {
        const float4* b4 = (const float4*)b;
        float4* o4 = (float4*)(g_h + (size_t)d * HID);
        float4 v;
        v = b4[lane];      o4[lane]      = make_float4(a0.x + v.x, a0.y + v.y, a0.z + v.z, a0.w + v.w);
        v = b4[lane + 32]; o4[lane + 32] = make_float4(a1.x + v.x, a1.y + v.y, a1.z + v.z, a1.w + v.w);
        v = b4[lane + 64]; o4[lane + 64] = make_float4(a2.x + v.x, a2.y + v.y, a2.z + v.z, a2.w + v.w);
        v = b4[lane + 96]; o4[lane + 96] = make_float4(a3.x + v.x, a3.y + v.y, a3.z + v.z, a3.w + v.w);
    } else {
        float4 s1 = make_float4(a0.x + a1.x + a2.x + a3.x,
                                a0.y + a1.y + a2.y + a3.y,
                                a0.z + a1.z + a2.z + a3.z,
                                a0.w + a1.w + a2.w + a3.w);
        s1.x += __shfl_xor_sync(0xffffffffu, s1.x, 16);
        s1.y += __shfl_xor_sync(0xffffffffu, s1.y, 16);
        s1.z += __shfl_xor_sync(0xffffffffu, s1.z, 16);
        s1.w += __shfl_xor_sync(0xffffffffu, s1.w, 16);
        if (lane < 16) {
            const float4 bv = ((const float4*)b)[lane];
            ((float4*)(out + (size_t)d * OC))[lane] =
                make_float4(s1.x * 0.125f + bv.x, s1.y * 0.125f + bv.y,
                            s1.z * 0.125f + bv.z, s1.w * 0.125f + bv.w);
        }
    }
}

// ---------------- host driver ------------------------------------------------
extern "C" void kernel_launch(void* const* d_in, const int* in_sizes, int n_in,
                              void* d_out, int out_size) {
    const float* x   = (const float*)d_in[0];
    const int*   ei  = (const int*)  d_in[1];
    const int*   ety = (const int*)  d_in[2];
    const float* ea  = (const float*)d_in[3];
    const float* W1  = (const float*)d_in[4];
    const float* q1  = (const float*)d_in[5];
    const float* k1  = (const float*)d_in[6];
    const float* We1 = (const float*)d_in[7];
    const float* e1  = (const float*)d_in[8];
    const float* b1  = (const float*)d_in[9];
    const float* W2  = (const float*)d_in[10];
    const float* q2  = (const float*)d_in[11];
    const float* k2  = (const float*)d_in[12];
    const float* We2 = (const float*)d_in[13];
    const float* e2  = (const float*)d_in[14];
    const float* b2  = (const float*)d_in[15];

    const int E0   = in_sizes[2];
    const int Etot = E0 + NN;

    float *p_t = nullptr, *p_h = nullptr;
    cudaGetSymbolAddress((void**)&p_t, g_t);
    cudaGetSymbolAddress((void**)&p_h, g_h);

    const int GS = GSMEM_WORDS * 4;   // 104448 bytes dynamic smem
    cudaFuncSetAttribute(gemm_cp_kernel,
                         cudaFuncAttributeMaxDynamicSharedMemorySize, GS);

    const dim3 gw(4 * RR, NN / 128);       // cp GEMM: (n_tile | r<<2, m_tile)
    const dim3 gq(1, NN / 128);
    const int  eB   = (Etot + 255) / 256;
    const int  fagB = (NN * 32) / 256;

    // ---------------- layer 1 (concat); gemm_cp at launch index 3 for ncu ----
    convA_kernel<<<dim3(F1 / 32, NN / 32), 256>>>(x, F1);
    convB_kernel<<<(RR * F1 * HID + 255) / 256, 256>>>(W1, RR * F1 * HID);
    init_kernel<<<(NN + 255) / 256, 256>>>();
    gemm_cp_kernel<<<gw, 256, GS>>>(p_t, F1, F1 * HID, NN * HID);
    etmax_kernel<<<256, 256>>>(ety, E0);
    hist_kernel<<<eB, 256>>>(ei, E0, Etot);
    scan_kernel<<<1, 1024>>>();
    scatter_kernel<<<eB, 256>>>(ei, ety, ea, E0, Etot);
    packqk_kernel<<<RR * F1 / 8, 256>>>(W1, q1, k1, F1);
    ce_kernel<<<1, 256>>>(We1, e1);
    qkgemm_l1_kernel<<<gq, 256>>>(x, F1);
    fagg_kernel<<<fagB, 256>>>(b1, nullptr, 1);

    // ---------------- layer 2 (mean) ------------------
    convA_kernel<<<dim3(HID / 32, NN / 32), 256>>>(p_h, HID);
    convB_kernel<<<(RR * HID * HID + 255) / 256, 256>>>(W2, RR * HID * HID);
    gemm_cp_kernel<<<gw, 256, GS>>>(p_t, HID, HID * HID, NN * HID);
    packqk_kernel<<<RR * HID / 8, 256>>>(W2, q2, k2, HID);
    ce_kernel<<<1, 256>>>(We2, e2);
    qkgemm_l2_kernel<<<gq, 256>>>(HID);
    fagg_kernel<<<fagB, 256>>>(b2, (float*)d_out, 0);
}

// round 14
// speedup vs baseline: 4.9764x; 1.0002x over previous
#include <cuda_runtime.h>
#include <cstdint>

// Problem dimensions (fixed by the dataset)
#define NN   16000          // nodes
#define F1   256            // layer-1 input features
#define HID  512            // HEADS*OUT
#define NH   8              // heads
#define OC   64             // per-head out channels
#define RR   8              // relations
#define ECAP 300000         // capacity for edges + self loops

// ---------------- scratch (device globals; no allocation allowed) ----------
__device__ float    g_t[(size_t)RR * NN * HID];   // relation-transformed nodes [R,N,512]
__device__ float    g_h[(size_t)NN * HID];        // layer-1 output
__device__ float    g_qk[(size_t)NN * 128];       // [node][r*16 + (q:0-7 | k:8-15)]
__device__ float    g_wqk[(size_t)HID * 128];     // folded W@q / W@k weights
__device__ float    g_ce[NH];                     // (We @ e)[h]
__device__ uint32_t g_At[(size_t)HID * NN];       // tf32 bits, [K][M] m-interleaved
__device__ uint32_t g_Bt[(size_t)RR * HID * HID]; // tf32 bits, [r][k][n]
__device__ int      g_etmax;
__device__ int      g_hist[NN];
__device__ int      g_rowptr[NN + 1];
__device__ int      g_cursor[NN];
__device__ int      g_csr_sr[ECAP];               // src | (rel << 20)
__device__ float    g_csr_attr[ECAP];

// ---------------- helpers ---------------------------------------------------
__device__ __forceinline__ uint32_t f2tf(float f) {
    uint32_t u;
    asm("cvt.rna.tf32.f32 %0, %1;" : "=r"(u) : "f"(f));
    return u;
}
__device__ __forceinline__ void mma_tf32(float c[4], const uint32_t a[4], const uint32_t b[2]) {
    asm volatile("mma.sync.aligned.m16n8k8.row.col.f32.tf32.tf32.f32 "
                 "{%0,%1,%2,%3}, {%4,%5,%6,%7}, {%8,%9}, {%0,%1,%2,%3};"
                 : "+f"(c[0]), "+f"(c[1]), "+f"(c[2]), "+f"(c[3])
                 : "r"(a[0]), "r"(a[1]), "r"(a[2]), "r"(a[3]), "r"(b[0]), "r"(b[1]));
}
__device__ __forceinline__ uint32_t s2u(const void* p) {
    uint32_t a;
    asm("{.reg .u64 t; cvta.to.shared.u64 t, %1; cvt.u32.u64 %0, t;}" : "=r"(a) : "l"(p));
    return a;
}
__device__ __forceinline__ void cp16(uint32_t saddr, const void* g) {
    asm volatile("cp.async.cg.shared.global [%0], [%1], 16;" :: "r"(saddr), "l"(g));
}
#define CP_COMMIT() asm volatile("cp.async.commit_group;")
#define CP_WAIT1()  asm volatile("cp.async.wait_group 1;")

// ---------------- CSR build --------------------------------------------------
__global__ void init_kernel() {
    int i = blockIdx.x * blockDim.x + threadIdx.x;
    if (i < NN) g_hist[i] = 0;
    if (i == 0) g_etmax = 0;
}

__global__ void etmax_kernel(const int* __restrict__ et, int E0) {
    int i = blockIdx.x * blockDim.x + threadIdx.x;
    int loc = -1;
    for (; i < E0; i += gridDim.x * blockDim.x) loc = max(loc, et[i]);
    if (loc >= 0) atomicMax(&g_etmax, loc);
}

__global__ void hist_kernel(const int* __restrict__ ei, int E0, int Etot) {
    int e = blockIdx.x * blockDim.x + threadIdx.x;
    if (e >= Etot) return;
    int d = (e < E0) ? ei[E0 + e] : (e - E0);
    atomicAdd(&g_hist[d], 1);
}

__global__ __launch_bounds__(1024)
void scan_kernel() {
    __shared__ int sm[1024];
    const int t = threadIdx.x;
    const int base = t * 16;
    int loc[16];
    int sum = 0;
#pragma unroll
    for (int i = 0; i < 16; i++) {
        int idx = base + i;
        int v = (idx < NN) ? g_hist[idx] : 0;
        loc[i] = sum;
        sum += v;
    }
    sm[t] = sum;
    __syncthreads();
    for (int off = 1; off < 1024; off <<= 1) {
        int v = (t >= off) ? sm[t - off] : 0;
        __syncthreads();
        sm[t] += v;
        __syncthreads();
    }
    int pre = (t > 0) ? sm[t - 1] : 0;
#pragma unroll
    for (int i = 0; i < 16; i++) {
        int idx = base + i;
        if (idx < NN) {
            g_rowptr[idx] = pre + loc[i];
            g_cursor[idx] = pre + loc[i];
        }
    }
    if (t == 1023) g_rowptr[NN] = sm[1023];
}

__global__ void scatter_kernel(const int* __restrict__ ei, const int* __restrict__ etyp,
                               const float* __restrict__ ea, int E0, int Etot) {
    int e = blockIdx.x * blockDim.x + threadIdx.x;
    if (e >= Etot) return;
    int s, d, r;  float at;
    if (e < E0) { s = ei[e]; d = ei[E0 + e]; r = etyp[e]; at = ea[e]; }
    else        { s = d = e - E0; r = (g_etmax + 1) & (RR - 1); at = 0.5f; }
    int p = atomicAdd(&g_cursor[d], 1);
    g_csr_sr[p]   = s | (r << 20);
    g_csr_attr[p] = at;
}

// ---------------- operand conversion ----------------------------------------
// A: [M][K] fp32 -> g_At [K][M] tf32 bits, m-interleaved within 16-groups.
__global__ __launch_bounds__(256)
void convA_kernel(const float* __restrict__ A, int K) {
    __shared__ float sm[32][33];
    const int tx = threadIdx.x & 31, ty = threadIdx.x >> 5;   // 32 x 8
    const int k0 = blockIdx.x * 32, m0 = blockIdx.y * 32;
#pragma unroll
    for (int j = 0; j < 4; j++)
        sm[ty + 8 * j][tx] = A[(size_t)(m0 + ty + 8 * j) * K + k0 + tx];
    __syncthreads();
    const int lm   = m0 + tx;
    const int mperm = (lm & ~15) | (((lm & 7) << 1) | ((lm >> 3) & 1));
#pragma unroll
    for (int j = 0; j < 4; j++)
        g_At[(size_t)(k0 + ty + 8 * j) * NN + mperm] = f2tf(sm[tx][ty + 8 * j]);
}

// B: elementwise fp32 -> tf32 bits (layout unchanged)
__global__ __launch_bounds__(256)
void convB_kernel(const float* __restrict__ B, int n) {
    int i = blockIdx.x * blockDim.x + threadIdx.x;
    if (i < n) g_Bt[i] = f2tf(B[i]);
}

// ===== cp.async GEMM: 128x128 block, 64x32 warp tiles, BK=32, 2 CTAs/SM =====
// 8 warps = 2(m) x 4(n). 3 stages x BK=32, ONE __syncthreads per iteration.
// As [k][m-int] stride 136; Bs [k][n] stride 136 (== 8 mod 32). tf32 pre-conv.
#define GSMEM_WORDS (3 * 32 * 136 * 2)
__global__ __launch_bounds__(256, 2)
void gemm_cp_kernel(float* __restrict__ C0, int K, int rstrideB, int rstrideC) {
    extern __shared__ __align__(16) uint32_t smem[];
    uint32_t (*As)[32][136] = (uint32_t (*)[32][136])smem;
    uint32_t (*Bs)[32][136] = (uint32_t (*)[32][136])(smem + 3 * 32 * 136);

    const int r  = blockIdx.x >> 2;
    const int n0 = (blockIdx.x & 3) * 128;
    const int m0 = blockIdx.y * 128;
    const uint32_t* Bt = g_Bt + (size_t)r * rstrideB;
    float*          C  = C0 + (size_t)r * rstrideC;

    const int tid  = threadIdx.x;
    const int lane = tid & 31, warp = tid >> 5;
    const int grp  = lane >> 2, tig = lane & 3;
    const int wm   = (warp & 1) * 64;
    const int wn   = (warp >> 1) * 32;

    // loader mapping: 256 threads cover 32x128 words via 4 passes of 8 rows
    const int arow = tid >> 5;          // 0..7
    const int acol = (tid & 31) * 4;    // 0..124

    const uint32_t* Ag = g_At + (size_t)arow * NN + m0 + acol;
    const uint32_t* Bg = Bt  + (size_t)arow * 512 + n0 + acol;

    uint32_t sA[3], sB[3];
#pragma unroll
    for (int st = 0; st < 3; st++) {
        sA[st] = s2u(&As[st][arow][acol]);
        sB[st] = s2u(&Bs[st][arow][acol]);
    }
    const int JSTRIDE = 8 * 136 * 4;    // 8 rows in bytes

    float c[4][4][4];
#pragma unroll
    for (int mt = 0; mt < 4; mt++)
#pragma unroll
        for (int nt = 0; nt < 4; nt++)
#pragma unroll
            for (int i = 0; i < 4; i++) c[mt][nt][i] = 0.f;

    const int NSTEP = K >> 5;
    // prologue: stages 0,1
#pragma unroll
    for (int st = 0; st < 2; st++) {
        const size_t k0 = (size_t)st * 32;
#pragma unroll
        for (int j = 0; j < 4; j++) {
            cp16(sA[st] + j * JSTRIDE, Ag + (k0 + 8 * j) * NN);
            cp16(sB[st] + j * JSTRIDE, Bg + (k0 + 8 * j) * 512);
        }
        CP_COMMIT();
    }

    int buf = 0;
    for (int s = 0; s < NSTEP; s++) {
        CP_WAIT1();
        __syncthreads();        // stage s ready; all warps done with stage s-1
        if (s + 2 < NSTEP) {
            const int st = (s + 2) % 3;
            const size_t k0 = (size_t)(s + 2) * 32;
#pragma unroll
            for (int j = 0; j < 4; j++) {
                cp16(sA[st] + j * JSTRIDE, Ag + (k0 + 8 * j) * NN);
                cp16(sB[st] + j * JSTRIDE, Bg + (k0 + 8 * j) * 512);
            }
        }
        CP_COMMIT();            // commit every iter keeps group count in sync

#pragma unroll
        for (int kb = 0; kb < 32; kb += 8) {
            uint32_t af[4][4], bf[4][2];
#pragma unroll
            for (int mt = 0; mt < 4; mt++) {
                const int mcol = wm + mt * 16 + 2 * grp;
                const uint2 p0 = *(const uint2*)&As[buf][kb + tig][mcol];
                const uint2 p1 = *(const uint2*)&As[buf][kb + tig + 4][mcol];
                af[mt][0] = p0.x; af[mt][1] = p0.y;
                af[mt][2] = p1.x; af[mt][3] = p1.y;
            }
#pragma unroll
            for (int nt = 0; nt < 4; nt++) {
                const int nc = wn + nt * 8 + grp;
                bf[nt][0] = Bs[buf][kb + tig][nc];
                bf[nt][1] = Bs[buf][kb + tig + 4][nc];
            }
#pragma unroll
            for (int mt = 0; mt < 4; mt++)
#pragma unroll
                for (int nt = 0; nt < 4; nt++)
                    mma_tf32(c[mt][nt], af[mt], bf[nt]);
        }
        buf = (buf + 1 == 3) ? 0 : buf + 1;
    }

#pragma unroll
    for (int mt = 0; mt < 4; mt++) {
        const int row = m0 + wm + mt * 16 + grp;
#pragma unroll
        for (int nt = 0; nt < 4; nt++) {
            const int col = n0 + wn + nt * 8 + tig * 2;
            *(float2*)(C + (size_t)row * 512 + col)       = make_float2(c[mt][nt][0], c[mt][nt][1]);
            *(float2*)(C + (size_t)(row + 8) * 512 + col) = make_float2(c[mt][nt][2], c[mt][nt][3]);
        }
    }
}

// ---------------- narrow GEMM (128x128) for q/k projection -------------------
__device__ __forceinline__ void gemm_tf32_body(
    const float* __restrict__ A, const float* __restrict__ B,
    float* __restrict__ C, int K, int m0, int n0, int ldb, int ldc)
{
    __shared__ __align__(16) uint32_t As[2][16][136];
    __shared__ __align__(16) uint32_t Bs[2][16][136];

    const int tid  = threadIdx.x;
    const int lane = tid & 31, warp = tid >> 5;
    const int grp  = lane >> 2, tig = lane & 3;
    const int wm   = (warp & 3) * 32;
    const int wn   = (warp >> 2) * 64;

    const int am   = tid & 127;
    const int amp  = (am & 0x70) | ((am & 7) << 1) | ((am >> 3) & 1);
    const int akq0 = tid >> 7;
    const int akq1 = akq0 + 2;
    const int bn4  = tid & 31;
    const int bk0  = tid >> 5;
    const int bk1  = bk0 + 8;

    const float* Ag0 = A + (size_t)(m0 + am) * K + 4 * akq0;
    const float* Ag1 = A + (size_t)(m0 + am) * K + 4 * akq1;
    const float* Bg0 = B + (size_t)bk0 * ldb + n0 + 4 * bn4;
    const float* Bg1 = B + (size_t)bk1 * ldb + n0 + 4 * bn4;

    float c[2][8][4];
#pragma unroll
    for (int mt = 0; mt < 2; mt++)
#pragma unroll
        for (int nt = 0; nt < 8; nt++)
#pragma unroll
            for (int i = 0; i < 4; i++) c[mt][nt][i] = 0.f;

    float4 a0v = *(const float4*)Ag0;
    float4 a1v = *(const float4*)Ag1;
    float4 b0v = *(const float4*)Bg0;
    float4 b1v = *(const float4*)Bg1;
    As[0][4 * akq0 + 0][amp] = f2tf(a0v.x); As[0][4 * akq0 + 1][amp] = f2tf(a0v.y);
    As[0][4 * akq0 + 2][amp] = f2tf(a0v.z); As[0][4 * akq0 + 3][amp] = f2tf(a0v.w);
    As[0][4 * akq1 + 0][amp] = f2tf(a1v.x); As[0][4 * akq1 + 1][amp] = f2tf(a1v.y);
    As[0][4 * akq1 + 2][amp] = f2tf(a1v.z); As[0][4 * akq1 + 3][amp] = f2tf(a1v.w);
    *(uint4*)&Bs[0][bk0][4 * bn4] = make_uint4(f2tf(b0v.x), f2tf(b0v.y), f2tf(b0v.z), f2tf(b0v.w));
    *(uint4*)&Bs[0][bk1][4 * bn4] = make_uint4(f2tf(b1v.x), f2tf(b1v.y), f2tf(b1v.z), f2tf(b1v.w));
    __syncthreads();

    int buf = 0;
    const int NSTEP = K >> 4;
    for (int s = 0; s < NSTEP; s++) {
        const bool nxt = (s + 1) < NSTEP;
        if (nxt) {
            const int ko = (s + 1) << 4;
            a0v = *(const float4*)(Ag0 + ko);
            a1v = *(const float4*)(Ag1 + ko);
            b0v = *(const float4*)(Bg0 + (size_t)ko * ldb);
            b1v = *(const float4*)(Bg1 + (size_t)ko * ldb);
        }
#pragma unroll
        for (int kb = 0; kb < 16; kb += 8) {
            uint32_t af[2][4], bf[8][2];
#pragma unroll
            for (int mt = 0; mt < 2; mt++) {
                const int mcol = wm + mt * 16 + 2 * grp;
                const uint2 p0 = *(const uint2*)&As[buf][kb + tig][mcol];
                const uint2 p1 = *(const uint2*)&As[buf][kb + tig + 4][mcol];
                af[mt][0] = p0.x; af[mt][1] = p0.y;
                af[mt][2] = p1.x; af[mt][3] = p1.y;
            }
#pragma unroll
            for (int nt = 0; nt < 8; nt++) {
                const int nc = wn + nt * 8 + grp;
                bf[nt][0] = Bs[buf][kb + tig][nc];
                bf[nt][1] = Bs[buf][kb + tig + 4][nc];
            }
#pragma unroll
            for (int mt = 0; mt < 2; mt++)
#pragma unroll
                for (int nt = 0; nt < 8; nt++)
                    mma_tf32(c[mt][nt], af[mt], bf[nt]);
        }
        if (nxt) {
            const int nb = buf ^ 1;
            As[nb][4 * akq0 + 0][amp] = f2tf(a0v.x); As[nb][4 * akq0 + 1][amp] = f2tf(a0v.y);
            As[nb][4 * akq0 + 2][amp] = f2tf(a0v.z); As[nb][4 * akq0 + 3][amp] = f2tf(a0v.w);
            As[nb][4 * akq1 + 0][amp] = f2tf(a1v.x); As[nb][4 * akq1 + 1][amp] = f2tf(a1v.y);
            As[nb][4 * akq1 + 2][amp] = f2tf(a1v.z); As[nb][4 * akq1 + 3][amp] = f2tf(a1v.w);
            *(uint4*)&Bs[nb][bk0][4 * bn4] = make_uint4(f2tf(b0v.x), f2tf(b0v.y), f2tf(b0v.z), f2tf(b0v.w));
            *(uint4*)&Bs[nb][bk1][4 * bn4] = make_uint4(f2tf(b1v.x), f2tf(b1v.y), f2tf(b1v.z), f2tf(b1v.w));
            __syncthreads();
            buf = nb;
        }
    }

#pragma unroll
    for (int mt = 0; mt < 2; mt++) {
        const int row = m0 + wm + mt * 16 + grp;
#pragma unroll
        for (int nt = 0; nt < 8; nt++) {
            const int col = n0 + wn + nt * 8 + tig * 2;
            *(float2*)(C + (size_t)row * ldc + col)       = make_float2(c[mt][nt][0], c[mt][nt][1]);
            *(float2*)(C + (size_t)(row + 8) * ldc + col) = make_float2(c[mt][nt][2], c[mt][nt][3]);
        }
    }
}

// q/k projection GEMM: [NN x K] @ [K x 128] -> g_qk [NN x 128]
__global__ __launch_bounds__(256, 2)
void qkgemm_l1_kernel(const float* __restrict__ A, int K) {
    gemm_tf32_body(A, g_wqk, g_qk, K, blockIdx.y * 128, 0, 128, 128);
}
__global__ __launch_bounds__(256, 2)
void qkgemm_l2_kernel(int K) {
    gemm_tf32_body(g_h, g_wqk, g_qk, K, blockIdx.y * 128, 0, 128, 128);
}

// ---------------- fold weights: g_wqk[j][r*16+h]=W[r]@q, +8: W[r]@k ----------
__global__ __launch_bounds__(256)
void packqk_kernel(const float* __restrict__ W, const float* __restrict__ q,
                   const float* __restrict__ k, int K) {
    const int gw = (blockIdx.x * blockDim.x + threadIdx.x) >> 5;
    if (gw >= RR * K) return;
    const int r = gw / K, j = gw - r * K;
    const int lane = threadIdx.x & 31;
    const float4* w4 = (const float4*)(W + ((size_t)r * K + j) * HID);
    const float4* q4 = (const float4*)q;
    const float4* k4 = (const float4*)k;
    float aq[NH], ak[NH];
#pragma unroll
    for (int h = 0; h < NH; h++) { aq[h] = 0.f; ak[h] = 0.f; }
#pragma unroll
    for (int i = 0; i < 4; i++) {
        const int c4 = lane + 32 * i;
        const float4 wv = w4[c4];
        const float wa[4] = {wv.x, wv.y, wv.z, wv.w};
#pragma unroll
        for (int f = 0; f < 4; f++) {
            const int c = 4 * c4 + f;
            const float4 qa = q4[c * 2], qb = q4[c * 2 + 1];
            const float4 ka = k4[c * 2], kb = k4[c * 2 + 1];
            const float w = wa[f];
            aq[0] += w * qa.x; aq[1] += w * qa.y; aq[2] += w * qa.z; aq[3] += w * qa.w;
            aq[4] += w * qb.x; aq[5] += w * qb.y; aq[6] += w * qb.z; aq[7] += w * qb.w;
            ak[0] += w * ka.x; ak[1] += w * ka.y; ak[2] += w * ka.z; ak[3] += w * ka.w;
            ak[4] += w * kb.x; ak[5] += w * kb.y; ak[6] += w * kb.z; ak[7] += w * kb.w;
        }
    }
#pragma unroll
    for (int h = 0; h < NH; h++) {
#pragma unroll
        for (int o = 16; o; o >>= 1) {
            aq[h] += __shfl_xor_sync(0xffffffffu, aq[h], o);
            ak[h] += __shfl_xor_sync(0xffffffffu, ak[h], o);
        }
    }
    if (lane == 0) {
        float* dst = g_wqk + (size_t)j * 128 + r * 16;
#pragma unroll
        for (int h = 0; h < NH; h++) {
            dst[h]      = aq[h];
            dst[8 + h]  = ak[h];
        }
    }
}

// ---------------- ce[h] = sum_j We[j] * e[j][h] (warp per head) --------------
__global__ void ce_kernel(const float* __restrict__ We, const float* __restrict__ e) {
    const int warp = threadIdx.x >> 5, lane = threadIdx.x & 31;
    float s = 0.f;
    for (int j = lane; j < HID; j += 32) s += We[j] * e[j * NH + warp];
#pragma unroll
    for (int o = 16; o; o >>= 1) s += __shfl_xor_sync(0xffffffffu, s, o);
    if (lane == 0) g_ce[warp] = s;
}

// ---------------- fused softmax + aggregation: warp per destination ----------
__global__ __launch_bounds__(256)
void fagg_kernel(const float* __restrict__ b, float* __restrict__ out, int concat) {
    const int d = (blockIdx.x * blockDim.x + threadIdx.x) >> 5;
    if (d >= NN) return;
    const int lane = threadIdx.x & 31;
    const int h = lane & 7;
    const int roff = g_rowptr[d];
    const int deg  = g_rowptr[d + 1] - roff;
    const float ceh = g_ce[h];
    const float* qrow = g_qk + (size_t)d * 128;

    // ---- phase A: per-head online softmax stats ----
    float m = -1e30f, s = 0.f;
    for (int base = 0; base < deg; base += 4) {
        const int e = base + (lane >> 3);
        if (e < deg) {
            const int   sr = g_csr_sr[roff + e];
            const float at = g_csr_attr[roff + e];
            const int src = sr & 0xFFFFF, r = sr >> 20;
            float l = qrow[r * 16 + h]
                    + g_qk[(size_t)src * 128 + r * 16 + 8 + h] + at * ceh;
            l = (l >= 0.f) ? l : 0.2f * l;
            const float mn = fmaxf(m, l);
            s = s * __expf(m - mn) + __expf(l - mn);
            m = mn;
        }
    }
#pragma unroll
    for (int off = 8; off < 32; off <<= 1) {
        const float om = __shfl_xor_sync(0xffffffffu, m, off);
        const float os = __shfl_xor_sync(0xffffffffu, s, off);
        const float mn = fmaxf(m, om);
        s = s * __expf(m - mn) + os * __expf(om - mn);
        m = mn;
    }
    const float sinv = 1.f / (s + 1e-16f);

    // ---- phase B: weighted aggregation ----
    float4 a0 = make_float4(0, 0, 0, 0), a1 = a0, a2 = a0, a3 = a0;
    const int hw0 = lane >> 4;
    for (int e = 0; e < deg; e++) {
        const int   sr = g_csr_sr[roff + e];
        const float at = g_csr_attr[roff + e];
        const int src = sr & 0xFFFFF, r = sr >> 20;
        float l = qrow[r * 16 + h]
                + g_qk[(size_t)src * 128 + r * 16 + 8 + h] + at * ceh;
        l = (l >= 0.f) ? l : 0.2f * l;
        const float w = __expf(l - m) * sinv;
        const float w0 = __shfl_sync(0xffffffffu, w, hw0);
        const float w1 = __shfl_sync(0xffffffffu, w, hw0 + 2);
        const float w2 = __shfl_sync(0xffffffffu, w, hw0 + 4);
        const float w3 = __shfl_sync(0xffffffffu, w, hw0 + 6);
        const float4* t4 = (const float4*)(g_t + ((size_t)r * NN + src) * HID);
        const float4 t0 = t4[lane], t1 = t4[lane + 32], t2 = t4[lane + 64], t3 = t4[lane + 96];
        a0.x += w0 * t0.x; a0.y += w0 * t0.y; a0.z += w0 * t0.z; a0.w += w0 * t0.w;
        a1.x += w1 * t1.x; a1.y += w1 * t1.y; a1.z += w1 * t1.z; a1.w += w1 * t1.w;
        a2.x += w2 * t2.x; a2.y += w2 * t2.y; a2.z += w2 * t2.z; a2.w += w2 * t2.w;
        a3.x += w3 * t3.x; a3.y += w3 * t3.y; a3.z += w3 * t3.z; a3.w += w3 * t3.w;
    }

    if (concat) {
        const float4* b4 = (const float4*)b;
        float4* o4 = (float4*)(g_h + (size_t)d * HID);
        float4 v;
        v = b4[lane];      o4[lane]      = make_float4(a0.x + v.x, a0.y + v.y, a0.z + v.z, a0.w + v.w);
        v = b4[lane + 32]; o4[lane + 32] = make_float4(a1.x + v.x, a1.y + v.y, a1.z + v.z, a1.w + v.w);
        v = b4[lane + 64]; o4[lane + 64] = make_float4(a2.x + v.x, a2.y + v.y, a2.z + v.z, a2.w + v.w);
        v = b4[lane + 96]; o4[lane + 96] = make_float4(a3.x + v.x, a3.y + v.y, a3.z + v.z, a3.w + v.w);
    } else {
        float4 s1 = make_float4(a0.x + a1.x + a2.x + a3.x,
                                a0.y + a1.y + a2.y + a3.y,
                                a0.z + a1.z + a2.z + a3.z,
                                a0.w + a1.w + a2.w + a3.w);
        s1.x += __shfl_xor_sync(0xffffffffu, s1.x, 16);
        s1.y += __shfl_xor_sync(0xffffffffu, s1.y, 16);
        s1.z += __shfl_xor_sync(0xffffffffu, s1.z, 16);
        s1.w += __shfl_xor_sync(0xffffffffu, s1.w, 16);
        if (lane < 16) {
            const float4 bv = ((const float4*)b)[lane];
            ((float4*)(out + (size_t)d * OC))[lane] =
                make_float4(s1.x * 0.125f + bv.x, s1.y * 0.125f + bv.y,
                            s1.z * 0.125f + bv.z, s1.w * 0.125f + bv.w);
        }
    }
}

// ---------------- host driver ------------------------------------------------
extern "C" void kernel_launch(void* const* d_in, const int* in_sizes, int n_in,
                              void* d_out, int out_size) {
    const float* x   = (const float*)d_in[0];
    const int*   ei  = (const int*)  d_in[1];
    const int*   ety = (const int*)  d_in[2];
    const float* ea  = (const float*)d_in[3];
    const float* W1  = (const float*)d_in[4];
    const float* q1  = (const float*)d_in[5];
    const float* k1  = (const float*)d_in[6];
    const float* We1 = (const float*)d_in[7];
    const float* e1  = (const float*)d_in[8];
    const float* b1  = (const float*)d_in[9];
    const float* W2  = (const float*)d_in[10];
    const float* q2  = (const float*)d_in[11];
    const float* k2  = (const float*)d_in[12];
    const float* We2 = (const float*)d_in[13];
    const float* e2  = (const float*)d_in[14];
    const float* b2  = (const float*)d_in[15];

    const int E0   = in_sizes[2];
    const int Etot = E0 + NN;

    float *p_t = nullptr, *p_h = nullptr;
    cudaGetSymbolAddress((void**)&p_t, g_t);
    cudaGetSymbolAddress((void**)&p_h, g_h);

    const int GS = GSMEM_WORDS * 4;   // 104448 bytes dynamic smem
    cudaFuncSetAttribute(gemm_cp_kernel,
                         cudaFuncAttributeMaxDynamicSharedMemorySize, GS);

    const dim3 gw(4 * RR, NN / 128);       // cp GEMM: (n_tile | r<<2, m_tile)
    const dim3 gq(1, NN / 128);
    const int  eB   = (Etot + 255) / 256;
    const int  fagB = (NN * 32) / 256;

    // ---------------- layer 1 (concat); gemm_cp at launch index 3 for ncu ----
    convA_kernel<<<dim3(F1 / 32, NN / 32), 256>>>(x, F1);
    convB_kernel<<<(RR * F1 * HID + 255) / 256, 256>>>(W1, RR * F1 * HID);
    init_kernel<<<(NN + 255) / 256, 256>>>();
    gemm_cp_kernel<<<gw, 256, GS>>>(p_t, F1, F1 * HID, NN * HID);
    etmax_kernel<<<256, 256>>>(ety, E0);
    hist_kernel<<<eB, 256>>>(ei, E0, Etot);
    scan_kernel<<<1, 1024>>>();
    scatter_kernel<<<eB, 256>>>(ei, ety, ea, E0, Etot);
    packqk_kernel<<<RR * F1 / 8, 256>>>(W1, q1, k1, F1);
    ce_kernel<<<1, 256>>>(We1, e1);
    qkgemm_l1_kernel<<<gq, 256>>>(x, F1);
    fagg_kernel<<<fagB, 256>>>(b1, nullptr, 1);

    // ---------------- layer 2 (mean) ------------------
    convA_kernel<<<dim3(HID / 32, NN / 32), 256>>>(p_h, HID);
    convB_kernel<<<(RR * HID * HID + 255) / 256, 256>>>(W2, RR * HID * HID);
    gemm_cp_kernel<<<gw, 256, GS>>>(p_t, HID, HID * HID, NN * HID);
    packqk_kernel<<<RR * HID / 8, 256>>>(W2, q2, k2, HID);
    ce_kernel<<<1, 256>>>(We2, e2);
    qkgemm_l2_kernel<<<gq, 256>>>(HID);
    fagg_kernel<<<fagB, 256>>>(b2, (float*)d_out, 0);
}